// round 7
// baseline (speedup 1.0000x reference)
#include <cuda_runtime.h>
#include <math.h>
#include <stdint.h>

#define B_ 2
#define T_ 2048
#define C_ 1024
#define H_ 16
#define HD_ 64
#define M_ 256
#define S_ (T_ + 2*M_)   /* 2560 */
#define KC_ 4

// ---------------- scratch (static device globals; no runtime alloc) -------
__device__ uint32_t g_xcat[B_*S_*C_];   // concat(x,fwd,rev) as tf32 bits
__device__ uint32_t g_wtf [4*C_*C_];    // Wq|Wk|Wv|Wo as tf32 bits
__device__ float    g_q   [B_*T_*C_];   // tf32-rounded
__device__ float    g_k   [B_*S_*C_];   // tf32-rounded
__device__ float    g_v   [B_*S_*C_];   // tf32-rounded
__device__ float    g_vt  [B_*C_*S_];   // V transposed per (b,c): [b][c][s]
__device__ float    g_gate[B_*T_*H_];
__device__ float    g_attn[B_*T_*C_];
__device__ uint32_t g_ztf [B_*T_*C_];   // conv output as tf32 bits

// ================= TF32 helpers ===========================================
__device__ __forceinline__ uint32_t f2tf32(float f) {
    uint32_t r;
    asm("cvt.rna.tf32.f32 %0, %1;" : "=r"(r) : "f"(f));
    return r;
}
__device__ __forceinline__ void mma_tf32(float* d, const uint32_t* a,
                                         const uint32_t* b) {
    asm volatile(
        "mma.sync.aligned.m16n8k8.row.col.f32.tf32.tf32.f32 "
        "{%0,%1,%2,%3}, {%4,%5,%6,%7}, {%8,%9}, {%0,%1,%2,%3};"
        : "+f"(d[0]), "+f"(d[1]), "+f"(d[2]), "+f"(d[3])
        : "r"(a[0]), "r"(a[1]), "r"(a[2]), "r"(a[3]),
          "r"(b[0]), "r"(b[1]));
}
__device__ __forceinline__ void ldsm_x4(uint32_t* r, uint32_t addr) {
    asm volatile("ldmatrix.sync.aligned.m8n8.x4.shared.b16 {%0,%1,%2,%3}, [%4];"
        : "=r"(r[0]), "=r"(r[1]), "=r"(r[2]), "=r"(r[3]) : "r"(addr));
}
__device__ __forceinline__ void cp16(uint32_t dst, const void* src) {
    asm volatile("cp.async.cg.shared.global [%0], [%1], 16;" :: "r"(dst), "l"(src));
}

// ---------------- pack: xcat = concat(x, fwd, rev) -> tf32 bits ----------
__global__ void pack_kernel(const float4* __restrict__ x,
                            const float4* __restrict__ fwd,
                            const float4* __restrict__ rev,
                            uint4* __restrict__ xc) {
    const int C4 = C_/4;
    int idx = blockIdx.x * 256 + threadIdx.x;
    if (idx >= B_*S_*C4) return;
    int c4 = idx % C4;
    int r  = (idx / C4) % S_;
    int b  = idx / (C4 * S_);
    float4 val;
    if (r < T_)            val = x  [(b*T_ + r)          * C4 + c4];
    else if (r < T_ + M_)  val = fwd[(b*M_ + (r - T_))   * C4 + c4];
    else                   val = rev[(b*M_ + (r - T_-M_))* C4 + c4];
    xc[idx] = make_uint4(f2tf32(val.x), f2tf32(val.y), f2tf32(val.z), f2tf32(val.w));
}

// ---------------- weight cvt ------------------------------------------------
__global__ void wcvt_kernel(const float4* __restrict__ w0, const float4* __restrict__ w1,
                            const float4* __restrict__ w2, const float4* __restrict__ w3,
                            uint4* __restrict__ dst) {
    const int n4 = C_*C_/4;
    int idx = blockIdx.x * 256 + threadIdx.x;
    if (idx >= 4*n4) return;
    int m = idx / n4, r = idx % n4;
    const float4* s = (m == 0) ? w0 : (m == 1) ? w1 : (m == 2) ? w2 : w3;
    float4 v = s[r];
    dst[idx] = make_uint4(f2tf32(v.x), f2tf32(v.y), f2tf32(v.z), f2tf32(v.w));
}

// ---------------- V transpose: vT[b][c][s] = v[b][s][c] --------------------
__global__ __launch_bounds__(256)
void vtrans_kernel(const float* __restrict__ v, float* __restrict__ vT) {
    __shared__ float tile[32][33];
    const int tx = threadIdx.x & 31, ty = threadIdx.x >> 5;  // 32 x 8
    const int s0 = blockIdx.x * 32, c0 = blockIdx.y * 32, b = blockIdx.z;
    #pragma unroll
    for (int i = 0; i < 4; i++)
        tile[ty + i*8][tx] = v[((size_t)(b*S_ + s0 + ty + i*8)) * C_ + c0 + tx];
    __syncthreads();
    #pragma unroll
    for (int i = 0; i < 4; i++)
        vT[((size_t)(b*C_ + c0 + ty + i*8)) * S_ + s0 + tx] = tile[tx][ty + i*8];
}

// ================= TF32 GEMM: cp.async 3-stage + ldmatrix ==================
#define GBM 128
#define GBN 128
#define GBK 32
#define GPAD 36
#define GSTG (GBM * GPAD)
#define GSTRIDE (2 * GSTG)
#define GEMM2_SMEM (3 * GSTRIDE * (int)sizeof(uint32_t))

__global__ __launch_bounds__(256)
void gemm_tc(const uint32_t* __restrict__ A, const uint32_t* __restrict__ Bm,
             float* __restrict__ Cm, float* __restrict__ qp,
             float* __restrict__ kp, float* __restrict__ vp,
             int Mr, int Nr, int Kr, int rnd, int mode) {
    if (mode == 1 && blockIdx.x < 8 && (blockIdx.y % 20) >= 16) return;

    extern __shared__ uint32_t smg[];
    const uint32_t sbase = (uint32_t)__cvta_generic_to_shared(smg);

    const int tid  = threadIdx.x;
    const int lane = tid & 31, warp = tid >> 5;
    const int g = lane >> 2, qc = lane & 3;
    const int wm0 = (warp >> 2) * 64;
    const int wn0 = (warp & 3) * 32;
    const int m0 = blockIdx.y * GBM, n0 = blockIdx.x * GBN;
    const int nk = Kr / GBK;

    const int a_off = ((lane & 7) + ((lane >> 3) & 1) * 8) * GPAD + (lane >> 4) * 4;
    const int b_off = (((lane >> 4) & 1) * 8 + (lane & 7)) * GPAD + ((lane >> 3) & 1) * 4;

    float acc[4][4][4] = {};

    #define PREFETCH(KT)                                                       \
    do {                                                                       \
        int kt_ = (KT);                                                        \
        if (kt_ < nk) {                                                        \
            int slot_ = kt_ % 3;                                               \
            uint32_t da = sbase + (slot_ * GSTRIDE) * 4;                       \
            uint32_t db = da + GSTG * 4;                                       \
            const uint32_t* Ag_ = A  + (size_t)m0 * Kr + kt_ * GBK;            \
            const uint32_t* Bg_ = Bm + (size_t)n0 * Kr + kt_ * GBK;            \
            _Pragma("unroll")                                                  \
            for (int j = 0; j < 4; j++) {                                      \
                int u = tid + j * 256;                                         \
                int row = u >> 3, c4 = (u & 7) * 4;                            \
                cp16(da + (row * GPAD + c4) * 4, Ag_ + (size_t)row * Kr + c4); \
                cp16(db + (row * GPAD + c4) * 4, Bg_ + (size_t)row * Kr + c4); \
            }                                                                  \
        }                                                                      \
        asm volatile("cp.async.commit_group;");                                \
    } while (0)

    PREFETCH(0);
    PREFETCH(1);

    for (int kt = 0; kt < nk; kt++) {
        asm volatile("cp.async.wait_group 1;");
        __syncthreads();
        PREFETCH(kt + 2);

        const int slot = kt % 3;
        const uint32_t aAddr = sbase + (slot * GSTRIDE) * 4 + (wm0 * GPAD + a_off) * 4;
        const uint32_t bAddr = sbase + (slot * GSTRIDE + GSTG) * 4 + (wn0 * GPAD + b_off) * 4;

        #pragma unroll
        for (int kp_ = 0; kp_ < 4; kp_++) {
            uint32_t bf[4][2];
            {
                uint32_t r[4];
                ldsm_x4(r, bAddr + kp_ * 32);
                bf[0][0] = r[0]; bf[0][1] = r[1]; bf[1][0] = r[2]; bf[1][1] = r[3];
            }
            {
                uint32_t r[4];
                ldsm_x4(r, bAddr + 16 * GPAD * 4 + kp_ * 32);
                bf[2][0] = r[0]; bf[2][1] = r[1]; bf[3][0] = r[2]; bf[3][1] = r[3];
            }
            uint32_t af[4][4];
            #pragma unroll
            for (int mt = 0; mt < 4; mt++)
                ldsm_x4(af[mt], aAddr + mt * 16 * GPAD * 4 + kp_ * 32);
            #pragma unroll
            for (int mt = 0; mt < 4; mt++)
                #pragma unroll
                for (int nt = 0; nt < 4; nt++)
                    mma_tf32(acc[mt][nt], af[mt], bf[nt]);
        }
    }
    #undef PREFETCH

    if (rnd) {
        #pragma unroll
        for (int mt = 0; mt < 4; mt++)
            #pragma unroll
            for (int nt = 0; nt < 4; nt++)
                #pragma unroll
                for (int e = 0; e < 4; e++)
                    acc[mt][nt][e] = __uint_as_float(f2tf32(acc[mt][nt][e]));
    }

    if (mode == 0) {
        #pragma unroll
        for (int mt = 0; mt < 4; mt++) {
            #pragma unroll
            for (int nt = 0; nt < 4; nt++) {
                int row = m0 + wm0 + mt*16 + g;
                int col = n0 + wn0 + nt*8 + qc*2;
                float2 lo = make_float2(acc[mt][nt][0], acc[mt][nt][1]);
                float2 hi = make_float2(acc[mt][nt][2], acc[mt][nt][3]);
                *(float2*)(Cm + (size_t)row     * Nr + col) = lo;
                *(float2*)(Cm + (size_t)(row+8) * Nr + col) = hi;
            }
        }
    } else {
        #pragma unroll
        for (int mt = 0; mt < 4; mt++) {
            #pragma unroll
            for (int nt = 0; nt < 4; nt++) {
                int row = m0 + wm0 + mt*16 + g;
                int col = n0 + wn0 + nt*8 + qc*2;
                int which = col >> 10, lc = col & 1023;
                int bb = row / S_, rr = row % S_;
                float2 lo = make_float2(acc[mt][nt][0], acc[mt][nt][1]);
                float2 hi = make_float2(acc[mt][nt][2], acc[mt][nt][3]);
                if (which == 0) {
                    if (rr < T_) {
                        float* dst = qp + ((size_t)(bb*T_ + rr)) * C_ + lc;
                        *(float2*)(dst)         = lo;
                        *(float2*)(dst + 8*C_)  = hi;
                    }
                } else {
                    float* dst = ((which == 1) ? kp : vp) + (size_t)row * C_ + lc;
                    *(float2*)(dst)         = lo;
                    *(float2*)(dst + 8*C_)  = hi;
                }
            }
        }
    }
}

// ---------------- gate -----------------------------------------------------
__global__ __launch_bounds__(256)
void gate_kernel(const float* __restrict__ q, const float* __restrict__ gw,
                 const float* __restrict__ gb, float* __restrict__ gate) {
    __shared__ float qrow[C_];
    const int bt = blockIdx.x;
    for (int c = threadIdx.x; c < C_; c += 256)
        qrow[c] = q[(size_t)bt * C_ + c];
    __syncthreads();
    const int warp = threadIdx.x >> 5, lane = threadIdx.x & 31;
    for (int h = warp; h < H_; h += 8) {
        float s = 0.f;
        for (int c = lane; c < C_; c += 32)
            s += qrow[c] * gw[h * C_ + c];
        #pragma unroll
        for (int o = 16; o; o >>= 1) s += __shfl_xor_sync(0xffffffffu, s, o);
        if (lane == 0)
            gate[(size_t)bt * H_ + h] = 1.f / (1.f + __expf(-(s + gb[h])));
    }
}

// ================= attention v4: 4-tile smem, 3 CTA/SM =====================
// Buffers: K0 | K1 | V0 | V1 (each 64x68 words). Q staged via V1 then lives
// in registers. P staged into current K buffer after S-phase (K dead by then).
#define AP 68
#define ATILE (64 * AP)
#define ATT4_SMEM (4 * ATILE * (int)sizeof(uint32_t))   // 69632 B -> 3 CTA/SM

__global__ __launch_bounds__(128, 3)
void attn_tc2(const float* __restrict__ q, const float* __restrict__ k,
              const float* __restrict__ vT, const float* __restrict__ gate,
              float* __restrict__ outp) {
    extern __shared__ uint32_t s3[];
    const uint32_t sbase = (uint32_t)__cvta_generic_to_shared(s3);

    const int tid  = threadIdx.x;
    const int lane = tid & 31, warp = tid >> 5;
    const int g = lane >> 2, qc = lane & 3;
    const int wr0 = warp * 16;
    const int b  = blockIdx.y >> 4;
    const int h  = blockIdx.y & 15;
    const int t0 = (gridDim.x - 1 - blockIdx.x) * 64;

    const int a_off = ((lane & 7) + ((lane >> 3) & 1) * 8) * AP + (lane >> 4) * 4;
    const int b_off = (((lane >> 4) & 1) * 8 + (lane & 7)) * AP + ((lane >> 3) & 1) * 4;

    const int nChunk = t0/64 + 1;
    const int nTiles = nChunk + (2*M_)/64;

    // buffer layout: K0 @0, K1 @1, V0 @2, V1 @3  (units of ATILE)
    #define KBUF(IT) (sbase + ((((IT) & 1)    ) * ATILE) * 4)
    #define VBUF(IT) (sbase + ((2 + ((IT) & 1)) * ATILE) * 4)

    // ---- stage Q via V1 buffer (V1 first written by FILL_KV(1)) ----
    {
        const float* src_ = q + ((size_t)(b*T_ + t0)) * C_ + h*HD_;
        #pragma unroll
        for (int j = 0; j < 8; j++) {
            int u = tid + j * 128;
            int row = u >> 4, cw = (u & 15) * 4;
            cp16(VBUF(1) + (row * AP + cw) * 4, src_ + (size_t)row * C_ + cw);
        }
        asm volatile("cp.async.commit_group;");
    }

    #define FILL_KV(IT)                                                       \
    do {                                                                      \
        int it_ = (IT);                                                       \
        if (it_ < nTiles) {                                                   \
            int s0_ = (it_ < nChunk) ? it_*64 : T_ + (it_ - nChunk)*64;       \
            uint32_t kb_ = KBUF(it_);                                         \
            uint32_t vb_ = VBUF(it_);                                         \
            const float* ks_ = k  + ((size_t)(b*S_ + s0_)) * C_ + h*HD_;      \
            const float* vs_ = vT + ((size_t)(b*C_ + h*HD_)) * S_ + s0_;      \
            _Pragma("unroll")                                                 \
            for (int j = 0; j < 8; j++) {                                     \
                int u = tid + j * 128;                                        \
                int row = u >> 4, cw = (u & 15) * 4;                          \
                cp16(kb_ + (row * AP + cw) * 4, ks_ + (size_t)row * C_ + cw); \
                cp16(vb_ + (row * AP + cw) * 4, vs_ + (size_t)row * S_ + cw); \
            }                                                                 \
        }                                                                     \
        asm volatile("cp.async.commit_group;");                               \
    } while (0)

    FILL_KV(0);
    asm volatile("cp.async.wait_group 1;");   // Q staged
    __syncthreads();

    // ---- Q fragments from V1 (scaled by 1/8; exact on tf32 bits) ----
    uint32_t qf[8][4];
    #pragma unroll
    for (int kk = 0; kk < 8; kk++) {
        ldsm_x4(qf[kk], VBUF(1) + (wr0 * AP + a_off + kk * 8) * 4);
        #pragma unroll
        for (int e = 0; e < 4; e++)
            qf[kk][e] = __float_as_uint(__uint_as_float(qf[kk][e]) * 0.125f);
    }
    __syncthreads();   // everyone done with V1 before FILL_KV(1)

    float oc[8][4] = {}, om[8][4] = {};
    float mA = -1e30f, mB = -1e30f, lA = 0.f, lB = 0.f;

    for (int it = 0; it < nTiles; it++) {
        const bool isMem  = (it >= nChunk);
        const int  s0     = isMem ? (T_ + (it - nChunk)*64) : it*64;
        const bool isDiag = (!isMem) && (s0 == t0);
        const uint32_t Kb = KBUF(it);
        const uint32_t Vb = VBUF(it);

        FILL_KV(it + 1);
        asm volatile("cp.async.wait_group 1;");
        __syncthreads();                       // K/V(it) visible to all

        // ---- S = Q K^T ----
        float sf[8][4] = {};
        #pragma unroll
        for (int kk = 0; kk < 8; kk++) {
            #pragma unroll
            for (int f2 = 0; f2 < 4; f2++) {
                uint32_t r[4];
                ldsm_x4(r, Kb + (f2 * 16 * AP + b_off + kk * 8) * 4);
                uint32_t b0[2] = {r[0], r[1]}, b1[2] = {r[2], r[3]};
                mma_tf32(sf[2*f2],     qf[kk], b0);
                mma_tf32(sf[2*f2 + 1], qf[kk], b1);
            }
        }
        __syncthreads();                       // all warps done reading K(it)

        // ---- mask + row max ----
        float tmA = -1e30f, tmB = -1e30f;
        #pragma unroll
        for (int f = 0; f < 8; f++) {
            if (isDiag) {
                int c0 = f*8 + 2*qc, c1 = c0 + 1;
                int rA = wr0 + g, rB = rA + 8;
                if (c0 > rA) sf[f][0] = -1e30f;
                if (c1 > rA) sf[f][1] = -1e30f;
                if (c0 > rB) sf[f][2] = -1e30f;
                if (c1 > rB) sf[f][3] = -1e30f;
            }
            tmA = fmaxf(tmA, fmaxf(sf[f][0], sf[f][1]));
            tmB = fmaxf(tmB, fmaxf(sf[f][2], sf[f][3]));
        }
        tmA = fmaxf(tmA, __shfl_xor_sync(~0u, tmA, 1));
        tmA = fmaxf(tmA, __shfl_xor_sync(~0u, tmA, 2));
        tmB = fmaxf(tmB, __shfl_xor_sync(~0u, tmB, 1));
        tmB = fmaxf(tmB, __shfl_xor_sync(~0u, tmB, 2));

        float mAn = fmaxf(mA, tmA), mBn = fmaxf(mB, tmB);
        float fA = __expf(mA - mAn), fB = __expf(mB - mBn);
        mA = mAn; mB = mBn;

        // ---- P = exp(S-m) -> K buffer (own warp rows), row sums ----
        uint32_t* Kp = s3 + ((it & 1) * ATILE);
        float sA = 0.f, sB = 0.f;
        #pragma unroll
        for (int f = 0; f < 8; f++) {
            float p0 = __expf(sf[f][0] - mA);
            float p1 = __expf(sf[f][1] - mA);
            float p2 = __expf(sf[f][2] - mB);
            float p3 = __expf(sf[f][3] - mB);
            sA += p0 + p1; sB += p2 + p3;
            uint2 lo = make_uint2(f2tf32(p0), f2tf32(p1));
            uint2 hi = make_uint2(f2tf32(p2), f2tf32(p3));
            *(uint2*)&Kp[(wr0 + g    )*AP + f*8 + 2*qc] = lo;
            *(uint2*)&Kp[(wr0 + g + 8)*AP + f*8 + 2*qc] = hi;
        }
        sA += __shfl_xor_sync(~0u, sA, 1); sA += __shfl_xor_sync(~0u, sA, 2);
        sB += __shfl_xor_sync(~0u, sB, 1); sB += __shfl_xor_sync(~0u, sB, 2);
        lA = lA * fA + sA;
        lB = lB * fB + sB;

        // ---- rescale accumulators ----
        #pragma unroll
        for (int f = 0; f < 8; f++) {
            oc[f][0] *= fA; oc[f][1] *= fA; oc[f][2] *= fB; oc[f][3] *= fB;
            om[f][0] *= fA; om[f][1] *= fA; om[f][2] *= fB; om[f][3] *= fB;
        }
        __syncwarp();

        // ---- P fragments (own warp rows of K buffer) ----
        uint32_t pf[8][4];
        #pragma unroll
        for (int kk = 0; kk < 8; kk++)
            ldsm_x4(pf[kk], Kb + (wr0 * AP + a_off + kk * 8) * 4);

        // ---- O += P V ----
        float (*accp)[4] = isMem ? om : oc;
        #pragma unroll
        for (int kk = 0; kk < 8; kk++) {
            #pragma unroll
            for (int f2 = 0; f2 < 4; f2++) {
                uint32_t r[4];
                ldsm_x4(r, Vb + (f2 * 16 * AP + b_off + kk * 8) * 4);
                uint32_t b0[2] = {r[0], r[1]}, b1[2] = {r[2], r[3]};
                mma_tf32(accp[2*f2],     pf[kk], b0);
                mma_tf32(accp[2*f2 + 1], pf[kk], b1);
            }
        }
        __syncthreads();   // P/V(it) free before FILL_KV(it+2) next iter
    }
    #undef FILL_KV
    #undef KBUF
    #undef VBUF

    int rA = t0 + wr0 + g, rB = rA + 8;
    float gA = gate[(size_t)(b*T_ + rA) * H_ + h];
    float gB = gate[(size_t)(b*T_ + rB) * H_ + h];
    float invA = 1.f / lA, invB = 1.f / lB;
    #pragma unroll
    for (int f = 0; f < 8; f++) {
        int col = h*HD_ + f*8 + 2*qc;
        float2 o0 = make_float2((oc[f][0] + gA*om[f][0]) * invA,
                                (oc[f][1] + gA*om[f][1]) * invA);
        float2 o1 = make_float2((oc[f][2] + gB*om[f][2]) * invB,
                                (oc[f][3] + gB*om[f][3]) * invB);
        *(float2*)&outp[(size_t)(b*T_ + rA) * C_ + col] = o0;
        *(float2*)&outp[(size_t)(b*T_ + rB) * C_ + col] = o1;
    }
}

// ---------------- canon conv -> tf32 bits ----------------------------------
__global__ __launch_bounds__(256)
void conv_kernel(const float* __restrict__ y, const float* __restrict__ cw,
                 const float* __restrict__ cb, uint32_t* __restrict__ z) {
    int idx = blockIdx.x * 256 + threadIdx.x;
    if (idx >= B_*T_*C_) return;
    int c = idx % C_;
    int t = (idx / C_) % T_;
    int b = idx / (C_ * T_);
    float s = y[idx] + cb[c];
    #pragma unroll
    for (int j = 0; j < KC_; j++) {
        int tt = t - (KC_ - 1) + j;
        if (tt >= 0)
            s += y[((size_t)(b*T_ + tt)) * C_ + c] * cw[c*KC_ + j];
    }
    z[idx] = f2tf32(s);
}

// ---------------- orchestration -------------------------------------------
extern "C" void kernel_launch(void* const* d_in, const int* in_sizes, int n_in,
                              void* d_out, int out_size) {
    const float* x   = (const float*)d_in[0];
    const float* fwd = (const float*)d_in[1];
    const float* rev = (const float*)d_in[2];
    const float* Wq  = (const float*)d_in[3];
    const float* Wk  = (const float*)d_in[4];
    const float* Wv  = (const float*)d_in[5];
    const float* Wo  = (const float*)d_in[6];
    const float* gw  = (const float*)d_in[7];
    const float* gb  = (const float*)d_in[8];
    const float* cw  = (const float*)d_in[9];
    const float* cb  = (const float*)d_in[10];
    float* out = (float*)d_out;

    uint32_t *xc, *wtf, *ztf;
    float *qb, *kb, *vb, *vt, *gt, *at;
    cudaGetSymbolAddress((void**)&xc,  g_xcat);
    cudaGetSymbolAddress((void**)&wtf, g_wtf);
    cudaGetSymbolAddress((void**)&ztf, g_ztf);
    cudaGetSymbolAddress((void**)&qb,  g_q);
    cudaGetSymbolAddress((void**)&kb,  g_k);
    cudaGetSymbolAddress((void**)&vb,  g_v);
    cudaGetSymbolAddress((void**)&vt,  g_vt);
    cudaGetSymbolAddress((void**)&gt,  g_gate);
    cudaGetSymbolAddress((void**)&at,  g_attn);

    cudaFuncSetAttribute(gemm_tc,
                         cudaFuncAttributeMaxDynamicSharedMemorySize, GEMM2_SMEM);
    cudaFuncSetAttribute(attn_tc2,
                         cudaFuncAttributeMaxDynamicSharedMemorySize, ATT4_SMEM);

    // 1. pre-convert inputs
    {
        int n4 = B_*S_*(C_/4);
        pack_kernel<<<(n4 + 255)/256, 256>>>((const float4*)x, (const float4*)fwd,
                                             (const float4*)rev, (uint4*)xc);
    }
    wcvt_kernel<<<(4*C_*C_/4 + 255)/256, 256>>>((const float4*)Wq, (const float4*)Wk,
                                                (const float4*)Wv, (const float4*)Wo,
                                                (uint4*)wtf);

    // 2. fused QKV projection
    gemm_tc<<<dim3(3*C_/128, (B_*S_)/128), 256, GEMM2_SMEM>>>(
        xc, wtf, nullptr, qb, kb, vb, B_*S_, 3*C_, C_, 1, 1);

    // 3. V transpose + gate
    vtrans_kernel<<<dim3(S_/32, C_/32, B_), 256>>>(vb, vt);
    gate_kernel<<<B_*T_, 256>>>(qb, gw, gb, gt);
    // 4. attention
    attn_tc2<<<dim3(T_/64, B_*H_), 128, ATT4_SMEM>>>(qb, kb, vt, gt, at);
    // 5. canon conv (writes tf32)
    conv_kernel<<<(B_*T_*C_ + 255)/256, 256>>>(at, cw, cb, ztf);
    // 6. output projection into d_out
    gemm_tc<<<dim3(C_/128, (B_*T_)/128), 256, GEMM2_SMEM>>>(
        ztf, wtf + 3*C_*C_, out, nullptr, nullptr, nullptr, B_*T_, C_, C_, 0, 0);
}

// round 8
// speedup vs baseline: 1.0936x; 1.0936x over previous
#include <cuda_runtime.h>
#include <math.h>
#include <stdint.h>

#define B_ 2
#define T_ 2048
#define C_ 1024
#define H_ 16
#define HD_ 64
#define M_ 256
#define S_ (T_ + 2*M_)   /* 2560 */
#define KC_ 4

// ---------------- scratch (static device globals; no runtime alloc) -------
__device__ uint32_t g_xcat[B_*S_*C_];   // concat(x,fwd,rev) as tf32 bits
__device__ uint32_t g_wtf [4*C_*C_];    // Wq|Wk|Wv|Wo as tf32 bits
__device__ float    g_q   [B_*T_*C_];   // tf32-rounded
__device__ float    g_k   [B_*S_*C_];   // tf32-rounded
__device__ float    g_vt  [B_*C_*S_];   // V^T, tf32-rounded: [b][c][s]
__device__ float    g_gate[B_*T_*H_];
__device__ float    g_attn[B_*T_*C_];
__device__ uint32_t g_ztf [B_*T_*C_];   // conv output as tf32 bits

// ================= TF32 helpers ===========================================
__device__ __forceinline__ uint32_t f2tf32(float f) {
    uint32_t r;
    asm("cvt.rna.tf32.f32 %0, %1;" : "=r"(r) : "f"(f));
    return r;
}
__device__ __forceinline__ void mma_tf32(float* d, const uint32_t* a,
                                         const uint32_t* b) {
    asm volatile(
        "mma.sync.aligned.m16n8k8.row.col.f32.tf32.tf32.f32 "
        "{%0,%1,%2,%3}, {%4,%5,%6,%7}, {%8,%9}, {%0,%1,%2,%3};"
        : "+f"(d[0]), "+f"(d[1]), "+f"(d[2]), "+f"(d[3])
        : "r"(a[0]), "r"(a[1]), "r"(a[2]), "r"(a[3]),
          "r"(b[0]), "r"(b[1]));
}
__device__ __forceinline__ void ldsm_x4(uint32_t* r, uint32_t addr) {
    asm volatile("ldmatrix.sync.aligned.m8n8.x4.shared.b16 {%0,%1,%2,%3}, [%4];"
        : "=r"(r[0]), "=r"(r[1]), "=r"(r[2]), "=r"(r[3]) : "r"(addr));
}
__device__ __forceinline__ void cp16(uint32_t dst, const void* src) {
    asm volatile("cp.async.cg.shared.global [%0], [%1], 16;" :: "r"(dst), "l"(src));
}

// ---------------- pack: xcat = concat(x, fwd, rev) -> tf32 bits ----------
__global__ void pack_kernel(const float4* __restrict__ x,
                            const float4* __restrict__ fwd,
                            const float4* __restrict__ rev,
                            uint4* __restrict__ xc) {
    const int C4 = C_/4;
    int idx = blockIdx.x * 256 + threadIdx.x;
    if (idx >= B_*S_*C4) return;
    int c4 = idx % C4;
    int r  = (idx / C4) % S_;
    int b  = idx / (C4 * S_);
    float4 val;
    if (r < T_)            val = x  [(b*T_ + r)          * C4 + c4];
    else if (r < T_ + M_)  val = fwd[(b*M_ + (r - T_))   * C4 + c4];
    else                   val = rev[(b*M_ + (r - T_-M_))* C4 + c4];
    xc[idx] = make_uint4(f2tf32(val.x), f2tf32(val.y), f2tf32(val.z), f2tf32(val.w));
}

// ---------------- weight cvt ------------------------------------------------
__global__ void wcvt_kernel(const float4* __restrict__ w0, const float4* __restrict__ w1,
                            const float4* __restrict__ w2, const float4* __restrict__ w3,
                            uint4* __restrict__ dst) {
    const int n4 = C_*C_/4;
    int idx = blockIdx.x * 256 + threadIdx.x;
    if (idx >= 4*n4) return;
    int m = idx / n4, r = idx % n4;
    const float4* s = (m == 0) ? w0 : (m == 1) ? w1 : (m == 2) ? w2 : w3;
    float4 v = s[r];
    dst[idx] = make_uint4(f2tf32(v.x), f2tf32(v.y), f2tf32(v.z), f2tf32(v.w));
}

// ================= TF32 GEMM: cp.async 3-stage + ldmatrix ==================
// mode 0: C[m,n] -> Cm (ld Nr), optional tf32 rounding (rnd)
// mode 1: fused QKV routing: n<1024 -> qp (rows r<T only), <2048 -> kp,
//         else vp written TRANSPOSED into vt[b][c][s] layout.
#define GBM 128
#define GBN 128
#define GBK 32
#define GPAD 36
#define GSTG (GBM * GPAD)
#define GSTRIDE (2 * GSTG)
#define GEMM2_SMEM (3 * GSTRIDE * (int)sizeof(uint32_t))

__global__ __launch_bounds__(256)
void gemm_tc(const uint32_t* __restrict__ A, const uint32_t* __restrict__ Bm,
             float* __restrict__ Cm, float* __restrict__ qp,
             float* __restrict__ kp, float* __restrict__ vp,
             int Mr, int Nr, int Kr, int rnd, int mode) {
    if (mode == 1 && blockIdx.x < 8 && (blockIdx.y % 20) >= 16) return;

    extern __shared__ uint32_t smg[];
    const uint32_t sbase = (uint32_t)__cvta_generic_to_shared(smg);

    const int tid  = threadIdx.x;
    const int lane = tid & 31, warp = tid >> 5;
    const int g = lane >> 2, qc = lane & 3;
    const int wm0 = (warp >> 2) * 64;
    const int wn0 = (warp & 3) * 32;
    const int m0 = blockIdx.y * GBM, n0 = blockIdx.x * GBN;
    const int nk = Kr / GBK;

    const int a_off = ((lane & 7) + ((lane >> 3) & 1) * 8) * GPAD + (lane >> 4) * 4;
    const int b_off = (((lane >> 4) & 1) * 8 + (lane & 7)) * GPAD + ((lane >> 3) & 1) * 4;

    float acc[4][4][4] = {};

    #define PREFETCH(KT)                                                       \
    do {                                                                       \
        int kt_ = (KT);                                                        \
        if (kt_ < nk) {                                                        \
            int slot_ = kt_ % 3;                                               \
            uint32_t da = sbase + (slot_ * GSTRIDE) * 4;                       \
            uint32_t db = da + GSTG * 4;                                       \
            const uint32_t* Ag_ = A  + (size_t)m0 * Kr + kt_ * GBK;            \
            const uint32_t* Bg_ = Bm + (size_t)n0 * Kr + kt_ * GBK;            \
            _Pragma("unroll")                                                  \
            for (int j = 0; j < 4; j++) {                                      \
                int u = tid + j * 256;                                         \
                int row = u >> 3, c4 = (u & 7) * 4;                            \
                cp16(da + (row * GPAD + c4) * 4, Ag_ + (size_t)row * Kr + c4); \
                cp16(db + (row * GPAD + c4) * 4, Bg_ + (size_t)row * Kr + c4); \
            }                                                                  \
        }                                                                      \
        asm volatile("cp.async.commit_group;");                                \
    } while (0)

    PREFETCH(0);
    PREFETCH(1);

    for (int kt = 0; kt < nk; kt++) {
        asm volatile("cp.async.wait_group 1;");
        __syncthreads();
        PREFETCH(kt + 2);

        const int slot = kt % 3;
        const uint32_t aAddr = sbase + (slot * GSTRIDE) * 4 + (wm0 * GPAD + a_off) * 4;
        const uint32_t bAddr = sbase + (slot * GSTRIDE + GSTG) * 4 + (wn0 * GPAD + b_off) * 4;

        #pragma unroll
        for (int kp_ = 0; kp_ < 4; kp_++) {
            uint32_t bf[4][2];
            {
                uint32_t r[4];
                ldsm_x4(r, bAddr + kp_ * 32);
                bf[0][0] = r[0]; bf[0][1] = r[1]; bf[1][0] = r[2]; bf[1][1] = r[3];
            }
            {
                uint32_t r[4];
                ldsm_x4(r, bAddr + 16 * GPAD * 4 + kp_ * 32);
                bf[2][0] = r[0]; bf[2][1] = r[1]; bf[3][0] = r[2]; bf[3][1] = r[3];
            }
            uint32_t af[4][4];
            #pragma unroll
            for (int mt = 0; mt < 4; mt++)
                ldsm_x4(af[mt], aAddr + mt * 16 * GPAD * 4 + kp_ * 32);
            #pragma unroll
            for (int mt = 0; mt < 4; mt++)
                #pragma unroll
                for (int nt = 0; nt < 4; nt++)
                    mma_tf32(acc[mt][nt], af[mt], bf[nt]);
        }
    }
    #undef PREFETCH

    if (rnd) {
        #pragma unroll
        for (int mt = 0; mt < 4; mt++)
            #pragma unroll
            for (int nt = 0; nt < 4; nt++)
                #pragma unroll
                for (int e = 0; e < 4; e++)
                    acc[mt][nt][e] = __uint_as_float(f2tf32(acc[mt][nt][e]));
    }

    if (mode == 0) {
        #pragma unroll
        for (int mt = 0; mt < 4; mt++) {
            #pragma unroll
            for (int nt = 0; nt < 4; nt++) {
                int row = m0 + wm0 + mt*16 + g;
                int col = n0 + wn0 + nt*8 + qc*2;
                float2 lo = make_float2(acc[mt][nt][0], acc[mt][nt][1]);
                float2 hi = make_float2(acc[mt][nt][2], acc[mt][nt][3]);
                *(float2*)(Cm + (size_t)row     * Nr + col) = lo;
                *(float2*)(Cm + (size_t)(row+8) * Nr + col) = hi;
            }
        }
    } else {
        #pragma unroll
        for (int mt = 0; mt < 4; mt++) {
            #pragma unroll
            for (int nt = 0; nt < 4; nt++) {
                int row = m0 + wm0 + mt*16 + g;          // 0..B*S-1
                int col = n0 + wn0 + nt*8 + qc*2;        // 0..3071
                int which = col >> 10, lc = col & 1023;
                int bb = row / S_, rr = row % S_;
                float2 lo = make_float2(acc[mt][nt][0], acc[mt][nt][1]);
                float2 hi = make_float2(acc[mt][nt][2], acc[mt][nt][3]);
                if (which == 0) {
                    if (rr < T_) {
                        float* dst = qp + ((size_t)(bb*T_ + rr)) * C_ + lc;
                        *(float2*)(dst)         = lo;
                        *(float2*)(dst + 8*C_)  = hi;
                    }
                } else if (which == 1) {
                    float* dst = kp + (size_t)row * C_ + lc;
                    *(float2*)(dst)         = lo;
                    *(float2*)(dst + 8*C_)  = hi;
                } else {
                    // transposed store into vt[b][c][s]
                    float* b0 = vp + ((size_t)(bb*C_ + lc)) * S_ + rr;
                    b0[0]       = lo.x;   // (lc,   rr)
                    b0[S_]      = lo.y;   // (lc+1, rr)
                    b0[8]       = hi.x;   // (lc,   rr+8)
                    b0[S_ + 8]  = hi.y;   // (lc+1, rr+8)
                }
            }
        }
    }
}

// ---------------- gate -----------------------------------------------------
__global__ __launch_bounds__(256)
void gate_kernel(const float* __restrict__ q, const float* __restrict__ gw,
                 const float* __restrict__ gb, float* __restrict__ gate) {
    __shared__ float qrow[C_];
    const int bt = blockIdx.x;
    for (int c = threadIdx.x; c < C_; c += 256)
        qrow[c] = q[(size_t)bt * C_ + c];
    __syncthreads();
    const int warp = threadIdx.x >> 5, lane = threadIdx.x & 31;
    for (int h = warp; h < H_; h += 8) {
        float s = 0.f;
        for (int c = lane; c < C_; c += 32)
            s += qrow[c] * gw[h * C_ + c];
        #pragma unroll
        for (int o = 16; o; o >>= 1) s += __shfl_xor_sync(0xffffffffu, s, o);
        if (lane == 0)
            gate[(size_t)bt * H_ + h] = 1.f / (1.f + __expf(-(s + gb[h])));
    }
}

// ================= attention (R6 version: 5-tile, 2 CTA/SM) ================
#define AP 68
#define ATILE (64 * AP)
#define ATT3_SMEM (5 * ATILE * (int)sizeof(uint32_t))

__global__ __launch_bounds__(128, 2)
void attn_tc2(const float* __restrict__ q, const float* __restrict__ k,
              const float* __restrict__ vT, const float* __restrict__ gate,
              float* __restrict__ outp) {
    extern __shared__ uint32_t s3[];
    const uint32_t sbase = (uint32_t)__cvta_generic_to_shared(s3);

    const int tid  = threadIdx.x;
    const int lane = tid & 31, warp = tid >> 5;
    const int g = lane >> 2, qc = lane & 3;
    const int wr0 = warp * 16;
    const int b  = blockIdx.y >> 4;
    const int h  = blockIdx.y & 15;
    const int t0 = (gridDim.x - 1 - blockIdx.x) * 64;

    const int a_off = ((lane & 7) + ((lane >> 3) & 1) * 8) * AP + (lane >> 4) * 4;
    const int b_off = (((lane >> 4) & 1) * 8 + (lane & 7)) * AP + ((lane >> 3) & 1) * 4;

    const int nChunk = t0/64 + 1;
    const int nTiles = nChunk + (2*M_)/64;

    #define FILL_Q()                                                           \
    do {                                                                       \
        const float* src_ = q + ((size_t)(b*T_ + t0)) * C_ + h*HD_;            \
        _Pragma("unroll")                                                      \
        for (int j = 0; j < 8; j++) {                                          \
            int u = tid + j * 128;                                             \
            int row = u >> 4, cw = (u & 15) * 4;                               \
            cp16(sbase + (row * AP + cw) * 4, src_ + (size_t)row * C_ + cw);   \
        }                                                                      \
        asm volatile("cp.async.commit_group;");                                \
    } while (0)

    #define FILL_KV(IT)                                                       \
    do {                                                                      \
        int it_ = (IT);                                                       \
        if (it_ < nTiles) {                                                   \
            int s0_ = (it_ < nChunk) ? it_*64 : T_ + (it_ - nChunk)*64;       \
            int buf_ = it_ & 1;                                               \
            uint32_t kb_ = sbase + ((1 + buf_) * ATILE) * 4;                  \
            uint32_t vb_ = sbase + ((3 + buf_) * ATILE) * 4;                  \
            const float* ks_ = k  + ((size_t)(b*S_ + s0_)) * C_ + h*HD_;      \
            const float* vs_ = vT + ((size_t)(b*C_ + h*HD_)) * S_ + s0_;      \
            _Pragma("unroll")                                                 \
            for (int j = 0; j < 8; j++) {                                     \
                int u = tid + j * 128;                                        \
                int row = u >> 4, cw = (u & 15) * 4;                          \
                cp16(kb_ + (row * AP + cw) * 4, ks_ + (size_t)row * C_ + cw); \
                cp16(vb_ + (row * AP + cw) * 4, vs_ + (size_t)row * S_ + cw); \
            }                                                                 \
        }                                                                     \
        asm volatile("cp.async.commit_group;");                               \
    } while (0)

    FILL_Q();
    FILL_KV(0);
    asm volatile("cp.async.wait_group 1;");
    __syncthreads();

    uint32_t qf[8][4];
    #pragma unroll
    for (int kk = 0; kk < 8; kk++) {
        ldsm_x4(qf[kk], sbase + (wr0 * AP + a_off + kk * 8) * 4);
        #pragma unroll
        for (int e = 0; e < 4; e++)
            qf[kk][e] = __float_as_uint(__uint_as_float(qf[kk][e]) * 0.125f);
    }

    float oc[8][4] = {}, om[8][4] = {};
    float mA = -1e30f, mB = -1e30f, lA = 0.f, lB = 0.f;

    for (int it = 0; it < nTiles; it++) {
        const bool isMem  = (it >= nChunk);
        const int  s0     = isMem ? (T_ + (it - nChunk)*64) : it*64;
        const bool isDiag = (!isMem) && (s0 == t0);
        const uint32_t Kb = sbase + ((1 + (it & 1)) * ATILE) * 4;
        const uint32_t Vb = sbase + ((3 + (it & 1)) * ATILE) * 4;

        FILL_KV(it + 1);
        asm volatile("cp.async.wait_group 1;");
        __syncthreads();

        float sf[8][4] = {};
        #pragma unroll
        for (int kk = 0; kk < 8; kk++) {
            #pragma unroll
            for (int f2 = 0; f2 < 4; f2++) {
                uint32_t r[4];
                ldsm_x4(r, Kb + (f2 * 16 * AP + b_off + kk * 8) * 4);
                uint32_t b0[2] = {r[0], r[1]}, b1[2] = {r[2], r[3]};
                mma_tf32(sf[2*f2],     qf[kk], b0);
                mma_tf32(sf[2*f2 + 1], qf[kk], b1);
            }
        }

        float tmA = -1e30f, tmB = -1e30f;
        #pragma unroll
        for (int f = 0; f < 8; f++) {
            if (isDiag) {
                int c0 = f*8 + 2*qc, c1 = c0 + 1;
                int rA = wr0 + g, rB = rA + 8;
                if (c0 > rA) sf[f][0] = -1e30f;
                if (c1 > rA) sf[f][1] = -1e30f;
                if (c0 > rB) sf[f][2] = -1e30f;
                if (c1 > rB) sf[f][3] = -1e30f;
            }
            tmA = fmaxf(tmA, fmaxf(sf[f][0], sf[f][1]));
            tmB = fmaxf(tmB, fmaxf(sf[f][2], sf[f][3]));
        }
        tmA = fmaxf(tmA, __shfl_xor_sync(~0u, tmA, 1));
        tmA = fmaxf(tmA, __shfl_xor_sync(~0u, tmA, 2));
        tmB = fmaxf(tmB, __shfl_xor_sync(~0u, tmB, 1));
        tmB = fmaxf(tmB, __shfl_xor_sync(~0u, tmB, 2));

        float mAn = fmaxf(mA, tmA), mBn = fmaxf(mB, tmB);
        float fA = __expf(mA - mAn), fB = __expf(mB - mBn);
        mA = mAn; mB = mBn;

        float sA = 0.f, sB = 0.f;
        #pragma unroll
        for (int f = 0; f < 8; f++) {
            float p0 = __expf(sf[f][0] - mA);
            float p1 = __expf(sf[f][1] - mA);
            float p2 = __expf(sf[f][2] - mB);
            float p3 = __expf(sf[f][3] - mB);
            sA += p0 + p1; sB += p2 + p3;
            uint2 lo = make_uint2(f2tf32(p0), f2tf32(p1));
            uint2 hi = make_uint2(f2tf32(p2), f2tf32(p3));
            *(uint2*)&s3[(wr0 + g    )*AP + f*8 + 2*qc] = lo;
            *(uint2*)&s3[(wr0 + g + 8)*AP + f*8 + 2*qc] = hi;
        }
        sA += __shfl_xor_sync(~0u, sA, 1); sA += __shfl_xor_sync(~0u, sA, 2);
        sB += __shfl_xor_sync(~0u, sB, 1); sB += __shfl_xor_sync(~0u, sB, 2);
        lA = lA * fA + sA;
        lB = lB * fB + sB;

        #pragma unroll
        for (int f = 0; f < 8; f++) {
            oc[f][0] *= fA; oc[f][1] *= fA; oc[f][2] *= fB; oc[f][3] *= fB;
            om[f][0] *= fA; om[f][1] *= fA; om[f][2] *= fB; om[f][3] *= fB;
        }
        __syncwarp();

        uint32_t pf[8][4];
        #pragma unroll
        for (int kk = 0; kk < 8; kk++)
            ldsm_x4(pf[kk], sbase + (wr0 * AP + a_off + kk * 8) * 4);

        float (*accp)[4] = isMem ? om : oc;
        #pragma unroll
        for (int kk = 0; kk < 8; kk++) {
            #pragma unroll
            for (int f2 = 0; f2 < 4; f2++) {
                uint32_t r[4];
                ldsm_x4(r, Vb + (f2 * 16 * AP + b_off + kk * 8) * 4);
                uint32_t b0[2] = {r[0], r[1]}, b1[2] = {r[2], r[3]};
                mma_tf32(accp[2*f2],     pf[kk], b0);
                mma_tf32(accp[2*f2 + 1], pf[kk], b1);
            }
        }
        __syncthreads();
    }
    #undef FILL_Q
    #undef FILL_KV

    int rA = t0 + wr0 + g, rB = rA + 8;
    float gA = gate[(size_t)(b*T_ + rA) * H_ + h];
    float gB = gate[(size_t)(b*T_ + rB) * H_ + h];
    float invA = 1.f / lA, invB = 1.f / lB;
    #pragma unroll
    for (int f = 0; f < 8; f++) {
        int col = h*HD_ + f*8 + 2*qc;
        float2 o0 = make_float2((oc[f][0] + gA*om[f][0]) * invA,
                                (oc[f][1] + gA*om[f][1]) * invA);
        float2 o1 = make_float2((oc[f][2] + gB*om[f][2]) * invB,
                                (oc[f][3] + gB*om[f][3]) * invB);
        *(float2*)&outp[(size_t)(b*T_ + rA) * C_ + col] = o0;
        *(float2*)&outp[(size_t)(b*T_ + rB) * C_ + col] = o1;
    }
}

// ---------------- canon conv -> tf32 bits ----------------------------------
__global__ __launch_bounds__(256)
void conv_kernel(const float* __restrict__ y, const float* __restrict__ cw,
                 const float* __restrict__ cb, uint32_t* __restrict__ z) {
    int idx = blockIdx.x * 256 + threadIdx.x;
    if (idx >= B_*T_*C_) return;
    int c = idx % C_;
    int t = (idx / C_) % T_;
    int b = idx / (C_ * T_);
    float s = y[idx] + cb[c];
    #pragma unroll
    for (int j = 0; j < KC_; j++) {
        int tt = t - (KC_ - 1) + j;
        if (tt >= 0)
            s += y[((size_t)(b*T_ + tt)) * C_ + c] * cw[c*KC_ + j];
    }
    z[idx] = f2tf32(s);
}

// ---------------- orchestration -------------------------------------------
extern "C" void kernel_launch(void* const* d_in, const int* in_sizes, int n_in,
                              void* d_out, int out_size) {
    const float* x   = (const float*)d_in[0];
    const float* fwd = (const float*)d_in[1];
    const float* rev = (const float*)d_in[2];
    const float* Wq  = (const float*)d_in[3];
    const float* Wk  = (const float*)d_in[4];
    const float* Wv  = (const float*)d_in[5];
    const float* Wo  = (const float*)d_in[6];
    const float* gw  = (const float*)d_in[7];
    const float* gb  = (const float*)d_in[8];
    const float* cw  = (const float*)d_in[9];
    const float* cb  = (const float*)d_in[10];
    float* out = (float*)d_out;

    uint32_t *xc, *wtf, *ztf;
    float *qb, *kb, *vt, *gt, *at;
    cudaGetSymbolAddress((void**)&xc,  g_xcat);
    cudaGetSymbolAddress((void**)&wtf, g_wtf);
    cudaGetSymbolAddress((void**)&ztf, g_ztf);
    cudaGetSymbolAddress((void**)&qb,  g_q);
    cudaGetSymbolAddress((void**)&kb,  g_k);
    cudaGetSymbolAddress((void**)&vt,  g_vt);
    cudaGetSymbolAddress((void**)&gt,  g_gate);
    cudaGetSymbolAddress((void**)&at,  g_attn);

    cudaFuncSetAttribute(gemm_tc,
                         cudaFuncAttributeMaxDynamicSharedMemorySize, GEMM2_SMEM);
    cudaFuncSetAttribute(attn_tc2,
                         cudaFuncAttributeMaxDynamicSharedMemorySize, ATT3_SMEM);

    // 1. pre-convert inputs
    {
        int n4 = B_*S_*(C_/4);
        pack_kernel<<<(n4 + 255)/256, 256>>>((const float4*)x, (const float4*)fwd,
                                             (const float4*)rev, (uint4*)xc);
    }
    wcvt_kernel<<<(4*C_*C_/4 + 255)/256, 256>>>((const float4*)Wq, (const float4*)Wk,
                                                (const float4*)Wv, (const float4*)Wo,
                                                (uint4*)wtf);

    // 2. fused QKV projection (v written transposed into g_vt)
    gemm_tc<<<dim3(3*C_/128, (B_*S_)/128), 256, GEMM2_SMEM>>>(
        xc, wtf, nullptr, qb, kb, vt, B_*S_, 3*C_, C_, 1, 1);

    // 3. gate
    gate_kernel<<<B_*T_, 256>>>(qb, gw, gb, gt);
    // 4. attention
    attn_tc2<<<dim3(T_/64, B_*H_), 128, ATT3_SMEM>>>(qb, kb, vt, gt, at);
    // 5. canon conv (writes tf32)
    conv_kernel<<<(B_*T_*C_ + 255)/256, 256>>>(at, cw, cb, ztf);
    // 6. output projection into d_out
    gemm_tc<<<dim3(C_/128, (B_*T_)/128), 256, GEMM2_SMEM>>>(
        ztf, wtf + 3*C_*C_, out, nullptr, nullptr, nullptr, B_*T_, C_, C_, 0, 0);
}

// round 9
// speedup vs baseline: 1.2594x; 1.1516x over previous
#include <cuda_runtime.h>
#include <math.h>
#include <stdint.h>

#define B_ 2
#define T_ 2048
#define C_ 1024
#define H_ 16
#define HD_ 64
#define M_ 256
#define S_ (T_ + 2*M_)   /* 2560 */
#define KC_ 4

// ---------------- scratch (static device globals; no runtime alloc) -------
__device__ uint32_t g_xcat[B_*S_*C_];   // concat(x,fwd,rev) as tf32 bits
__device__ uint32_t g_wtf [4*C_*C_];    // Wq|Wk|Wv|Wo as tf32 bits
__device__ float    g_q   [B_*T_*C_];   // tf32-rounded
__device__ float    g_k   [B_*S_*C_];   // tf32-rounded
__device__ float    g_vt  [B_*C_*S_];   // V^T, tf32-rounded: [b][c][s]
__device__ float    g_gate[B_*T_*H_];
__device__ float    g_attn[B_*T_*C_];
__device__ uint32_t g_ztf [B_*T_*C_];   // conv output as tf32 bits

// ================= TF32 helpers ===========================================
__device__ __forceinline__ uint32_t f2tf32(float f) {
    uint32_t r;
    asm("cvt.rna.tf32.f32 %0, %1;" : "=r"(r) : "f"(f));
    return r;
}
__device__ __forceinline__ void mma_tf32(float* d, const uint32_t* a,
                                         const uint32_t* b) {
    asm volatile(
        "mma.sync.aligned.m16n8k8.row.col.f32.tf32.tf32.f32 "
        "{%0,%1,%2,%3}, {%4,%5,%6,%7}, {%8,%9}, {%0,%1,%2,%3};"
        : "+f"(d[0]), "+f"(d[1]), "+f"(d[2]), "+f"(d[3])
        : "r"(a[0]), "r"(a[1]), "r"(a[2]), "r"(a[3]),
          "r"(b[0]), "r"(b[1]));
}
__device__ __forceinline__ void ldsm_x4(uint32_t* r, uint32_t addr) {
    asm volatile("ldmatrix.sync.aligned.m8n8.x4.shared.b16 {%0,%1,%2,%3}, [%4];"
        : "=r"(r[0]), "=r"(r[1]), "=r"(r[2]), "=r"(r[3]) : "r"(addr));
}
__device__ __forceinline__ void cp16(uint32_t dst, const void* src) {
    asm volatile("cp.async.cg.shared.global [%0], [%1], 16;" :: "r"(dst), "l"(src));
}

// ---------------- pack: xcat = concat(x, fwd, rev) -> tf32 bits ----------
__global__ void pack_kernel(const float4* __restrict__ x,
                            const float4* __restrict__ fwd,
                            const float4* __restrict__ rev,
                            uint4* __restrict__ xc) {
    const int C4 = C_/4;
    int idx = blockIdx.x * 256 + threadIdx.x;
    if (idx >= B_*S_*C4) return;
    int c4 = idx % C4;
    int r  = (idx / C4) % S_;
    int b  = idx / (C4 * S_);
    float4 val;
    if (r < T_)            val = x  [(b*T_ + r)          * C4 + c4];
    else if (r < T_ + M_)  val = fwd[(b*M_ + (r - T_))   * C4 + c4];
    else                   val = rev[(b*M_ + (r - T_-M_))* C4 + c4];
    xc[idx] = make_uint4(f2tf32(val.x), f2tf32(val.y), f2tf32(val.z), f2tf32(val.w));
}

// ---------------- weight cvt ------------------------------------------------
__global__ void wcvt_kernel(const float4* __restrict__ w0, const float4* __restrict__ w1,
                            const float4* __restrict__ w2, const float4* __restrict__ w3,
                            uint4* __restrict__ dst) {
    const int n4 = C_*C_/4;
    int idx = blockIdx.x * 256 + threadIdx.x;
    if (idx >= 4*n4) return;
    int m = idx / n4, r = idx % n4;
    const float4* s = (m == 0) ? w0 : (m == 1) ? w1 : (m == 2) ? w2 : w3;
    float4 v = s[r];
    dst[idx] = make_uint4(f2tf32(v.x), f2tf32(v.y), f2tf32(v.z), f2tf32(v.w));
}

// ================= TF32 GEMM: cp.async 3-stage + ldmatrix ==================
#define GBM 128
#define GBN 128
#define GBK 32
#define GPAD 36
#define GSTG (GBM * GPAD)
#define GSTRIDE (2 * GSTG)
#define GEMM2_SMEM (3 * GSTRIDE * (int)sizeof(uint32_t))

__global__ __launch_bounds__(256)
void gemm_tc(const uint32_t* __restrict__ A, const uint32_t* __restrict__ Bm,
             float* __restrict__ Cm, float* __restrict__ qp,
             float* __restrict__ kp, float* __restrict__ vp,
             int Mr, int Nr, int Kr, int rnd, int mode) {
    if (mode == 1 && blockIdx.x < 8 && (blockIdx.y % 20) >= 16) return;

    extern __shared__ uint32_t smg[];
    const uint32_t sbase = (uint32_t)__cvta_generic_to_shared(smg);

    const int tid  = threadIdx.x;
    const int lane = tid & 31, warp = tid >> 5;
    const int g = lane >> 2, qc = lane & 3;
    const int wm0 = (warp >> 2) * 64;
    const int wn0 = (warp & 3) * 32;
    const int m0 = blockIdx.y * GBM, n0 = blockIdx.x * GBN;
    const int nk = Kr / GBK;

    const int a_off = ((lane & 7) + ((lane >> 3) & 1) * 8) * GPAD + (lane >> 4) * 4;
    const int b_off = (((lane >> 4) & 1) * 8 + (lane & 7)) * GPAD + ((lane >> 3) & 1) * 4;

    float acc[4][4][4] = {};

    #define PREFETCH(KT)                                                       \
    do {                                                                       \
        int kt_ = (KT);                                                        \
        if (kt_ < nk) {                                                        \
            int slot_ = kt_ % 3;                                               \
            uint32_t da = sbase + (slot_ * GSTRIDE) * 4;                       \
            uint32_t db = da + GSTG * 4;                                       \
            const uint32_t* Ag_ = A  + (size_t)m0 * Kr + kt_ * GBK;            \
            const uint32_t* Bg_ = Bm + (size_t)n0 * Kr + kt_ * GBK;            \
            _Pragma("unroll")                                                  \
            for (int j = 0; j < 4; j++) {                                      \
                int u = tid + j * 256;                                         \
                int row = u >> 3, c4 = (u & 7) * 4;                            \
                cp16(da + (row * GPAD + c4) * 4, Ag_ + (size_t)row * Kr + c4); \
                cp16(db + (row * GPAD + c4) * 4, Bg_ + (size_t)row * Kr + c4); \
            }                                                                  \
        }                                                                      \
        asm volatile("cp.async.commit_group;");                                \
    } while (0)

    PREFETCH(0);
    PREFETCH(1);

    for (int kt = 0; kt < nk; kt++) {
        asm volatile("cp.async.wait_group 1;");
        __syncthreads();
        PREFETCH(kt + 2);

        const int slot = kt % 3;
        const uint32_t aAddr = sbase + (slot * GSTRIDE) * 4 + (wm0 * GPAD + a_off) * 4;
        const uint32_t bAddr = sbase + (slot * GSTRIDE + GSTG) * 4 + (wn0 * GPAD + b_off) * 4;

        #pragma unroll
        for (int kp_ = 0; kp_ < 4; kp_++) {
            uint32_t bf[4][2];
            {
                uint32_t r[4];
                ldsm_x4(r, bAddr + kp_ * 32);
                bf[0][0] = r[0]; bf[0][1] = r[1]; bf[1][0] = r[2]; bf[1][1] = r[3];
            }
            {
                uint32_t r[4];
                ldsm_x4(r, bAddr + 16 * GPAD * 4 + kp_ * 32);
                bf[2][0] = r[0]; bf[2][1] = r[1]; bf[3][0] = r[2]; bf[3][1] = r[3];
            }
            uint32_t af[4][4];
            #pragma unroll
            for (int mt = 0; mt < 4; mt++)
                ldsm_x4(af[mt], aAddr + mt * 16 * GPAD * 4 + kp_ * 32);
            #pragma unroll
            for (int mt = 0; mt < 4; mt++)
                #pragma unroll
                for (int nt = 0; nt < 4; nt++)
                    mma_tf32(acc[mt][nt], af[mt], bf[nt]);
        }
    }
    #undef PREFETCH

    if (rnd) {
        #pragma unroll
        for (int mt = 0; mt < 4; mt++)
            #pragma unroll
            for (int nt = 0; nt < 4; nt++)
                #pragma unroll
                for (int e = 0; e < 4; e++)
                    acc[mt][nt][e] = __uint_as_float(f2tf32(acc[mt][nt][e]));
    }

    if (mode == 0) {
        #pragma unroll
        for (int mt = 0; mt < 4; mt++) {
            #pragma unroll
            for (int nt = 0; nt < 4; nt++) {
                int row = m0 + wm0 + mt*16 + g;
                int col = n0 + wn0 + nt*8 + qc*2;
                float2 lo = make_float2(acc[mt][nt][0], acc[mt][nt][1]);
                float2 hi = make_float2(acc[mt][nt][2], acc[mt][nt][3]);
                *(float2*)(Cm + (size_t)row     * Nr + col) = lo;
                *(float2*)(Cm + (size_t)(row+8) * Nr + col) = hi;
            }
        }
    } else {
        #pragma unroll
        for (int mt = 0; mt < 4; mt++) {
            #pragma unroll
            for (int nt = 0; nt < 4; nt++) {
                int row = m0 + wm0 + mt*16 + g;
                int col = n0 + wn0 + nt*8 + qc*2;
                int which = col >> 10, lc = col & 1023;
                int bb = row / S_, rr = row % S_;
                float2 lo = make_float2(acc[mt][nt][0], acc[mt][nt][1]);
                float2 hi = make_float2(acc[mt][nt][2], acc[mt][nt][3]);
                if (which == 0) {
                    if (rr < T_) {
                        float* dst = qp + ((size_t)(bb*T_ + rr)) * C_ + lc;
                        *(float2*)(dst)         = lo;
                        *(float2*)(dst + 8*C_)  = hi;
                    }
                } else if (which == 1) {
                    float* dst = kp + (size_t)row * C_ + lc;
                    *(float2*)(dst)         = lo;
                    *(float2*)(dst + 8*C_)  = hi;
                } else {
                    float* b0 = vp + ((size_t)(bb*C_ + lc)) * S_ + rr;
                    b0[0]       = lo.x;
                    b0[S_]      = lo.y;
                    b0[8]       = hi.x;
                    b0[S_ + 8]  = hi.y;
                }
            }
        }
    }
}

// ---------------- gate -----------------------------------------------------
__global__ __launch_bounds__(256)
void gate_kernel(const float* __restrict__ q, const float* __restrict__ gw,
                 const float* __restrict__ gb, float* __restrict__ gate) {
    __shared__ float qrow[C_];
    const int bt = blockIdx.x;
    for (int c = threadIdx.x; c < C_; c += 256)
        qrow[c] = q[(size_t)bt * C_ + c];
    __syncthreads();
    const int warp = threadIdx.x >> 5, lane = threadIdx.x & 31;
    for (int h = warp; h < H_; h += 8) {
        float s = 0.f;
        for (int c = lane; c < C_; c += 32)
            s += qrow[c] * gw[h * C_ + c];
        #pragma unroll
        for (int o = 16; o; o >>= 1) s += __shfl_xor_sync(0xffffffffu, s, o);
        if (lane == 0)
            gate[(size_t)bt * H_ + h] = 1.f / (1.f + __expf(-(s + gb[h])));
    }
}

// ================= attention v5: mem-first gated acc, 4-tile, 3 CTA/SM =====
// Single accumulator: memory tiles processed FIRST, acc *= gate at the
// transition, chunk tiles accumulate ungated. l is the shared denominator.
// Buffers: K0 | K1 | V0 | V1 (64x68 words each). Q staged via V1, P into
// the current (dead) K buffer.
#define AP 68
#define ATILE (64 * AP)
#define ATT5_SMEM (4 * ATILE * (int)sizeof(uint32_t))   // 69632 B -> 3 CTA/SM

__global__ __launch_bounds__(128, 3)
void attn_tc2(const float* __restrict__ q, const float* __restrict__ k,
              const float* __restrict__ vT, const float* __restrict__ gate,
              float* __restrict__ outp) {
    extern __shared__ uint32_t s3[];
    const uint32_t sbase = (uint32_t)__cvta_generic_to_shared(s3);

    const int tid  = threadIdx.x;
    const int lane = tid & 31, warp = tid >> 5;
    const int g = lane >> 2, qc = lane & 3;
    const int wr0 = warp * 16;
    const int b  = blockIdx.y >> 4;
    const int h  = blockIdx.y & 15;
    const int t0 = (gridDim.x - 1 - blockIdx.x) * 64;

    const int a_off = ((lane & 7) + ((lane >> 3) & 1) * 8) * AP + (lane >> 4) * 4;
    const int b_off = (((lane >> 4) & 1) * 8 + (lane & 7)) * AP + ((lane >> 3) & 1) * 4;

    const int nMem   = (2*M_)/64;        // 8 memory tiles, processed first
    const int nChunk = t0/64 + 1;
    const int nTiles = nMem + nChunk;

    #define KBUF(IT) (sbase + ((((IT) & 1)    ) * ATILE) * 4)
    #define VBUF(IT) (sbase + ((2 + ((IT) & 1)) * ATILE) * 4)
    #define S0OF(IT) (((IT) < nMem) ? (T_ + (IT)*64) : ((IT) - nMem)*64)

    // ---- stage Q via V1 buffer ----
    {
        const float* src_ = q + ((size_t)(b*T_ + t0)) * C_ + h*HD_;
        #pragma unroll
        for (int j = 0; j < 8; j++) {
            int u = tid + j * 128;
            int row = u >> 4, cw = (u & 15) * 4;
            cp16(VBUF(1) + (row * AP + cw) * 4, src_ + (size_t)row * C_ + cw);
        }
        asm volatile("cp.async.commit_group;");
    }

    #define FILL_KV(IT)                                                       \
    do {                                                                      \
        int it_ = (IT);                                                       \
        if (it_ < nTiles) {                                                   \
            int s0_ = S0OF(it_);                                              \
            uint32_t kb_ = KBUF(it_);                                         \
            uint32_t vb_ = VBUF(it_);                                         \
            const float* ks_ = k  + ((size_t)(b*S_ + s0_)) * C_ + h*HD_;      \
            const float* vs_ = vT + ((size_t)(b*C_ + h*HD_)) * S_ + s0_;      \
            _Pragma("unroll")                                                 \
            for (int j = 0; j < 8; j++) {                                     \
                int u = tid + j * 128;                                        \
                int row = u >> 4, cw = (u & 15) * 4;                          \
                cp16(kb_ + (row * AP + cw) * 4, ks_ + (size_t)row * C_ + cw); \
                cp16(vb_ + (row * AP + cw) * 4, vs_ + (size_t)row * S_ + cw); \
            }                                                                 \
        }                                                                     \
        asm volatile("cp.async.commit_group;");                               \
    } while (0)

    FILL_KV(0);
    asm volatile("cp.async.wait_group 1;");   // Q staged (first group done)
    __syncthreads();

    // ---- Q fragments from V1 (scale folded; exact on tf32 bits) ----
    uint32_t qf[8][4];
    #pragma unroll
    for (int kk = 0; kk < 8; kk++) {
        ldsm_x4(qf[kk], VBUF(1) + (wr0 * AP + a_off + kk * 8) * 4);
        #pragma unroll
        for (int e = 0; e < 4; e++)
            qf[kk][e] = __float_as_uint(__uint_as_float(qf[kk][e]) * 0.125f);
    }
    __syncthreads();   // all warps done with V1 before FILL_KV(1)

    // per-row gates (two rows per thread)
    const int rA = t0 + wr0 + g, rB = rA + 8;
    const float gA = gate[(size_t)(b*T_ + rA) * H_ + h];
    const float gB = gate[(size_t)(b*T_ + rB) * H_ + h];

    float acc[8][4] = {};
    float mA = -1e30f, mB = -1e30f, lA = 0.f, lB = 0.f;

    for (int it = 0; it < nTiles; it++) {
        const int  s0     = S0OF(it);
        const bool isDiag = (it == nTiles - 1);   // only final chunk tile
        const uint32_t Kb = KBUF(it);
        const uint32_t Vb = VBUF(it);

        FILL_KV(it + 1);
        asm volatile("cp.async.wait_group 1;");
        __syncthreads();                       // K/V(it) visible

        // ---- S = Q K^T ----
        float sf[8][4] = {};
        #pragma unroll
        for (int kk = 0; kk < 8; kk++) {
            #pragma unroll
            for (int f2 = 0; f2 < 4; f2++) {
                uint32_t r[4];
                ldsm_x4(r, Kb + (f2 * 16 * AP + b_off + kk * 8) * 4);
                uint32_t b0[2] = {r[0], r[1]}, b1[2] = {r[2], r[3]};
                mma_tf32(sf[2*f2],     qf[kk], b0);
                mma_tf32(sf[2*f2 + 1], qf[kk], b1);
            }
        }
        __syncthreads();                       // all warps done reading K(it)

        // ---- mask (final tile) + row max ----
        float tmA = -1e30f, tmB = -1e30f;
        #pragma unroll
        for (int f = 0; f < 8; f++) {
            if (isDiag) {
                int c0 = s0 + f*8 + 2*qc, c1 = c0 + 1;
                if (c0 > rA) sf[f][0] = -1e30f;
                if (c1 > rA) sf[f][1] = -1e30f;
                if (c0 > rB) sf[f][2] = -1e30f;
                if (c1 > rB) sf[f][3] = -1e30f;
            }
            tmA = fmaxf(tmA, fmaxf(sf[f][0], sf[f][1]));
            tmB = fmaxf(tmB, fmaxf(sf[f][2], sf[f][3]));
        }
        tmA = fmaxf(tmA, __shfl_xor_sync(~0u, tmA, 1));
        tmA = fmaxf(tmA, __shfl_xor_sync(~0u, tmA, 2));
        tmB = fmaxf(tmB, __shfl_xor_sync(~0u, tmB, 1));
        tmB = fmaxf(tmB, __shfl_xor_sync(~0u, tmB, 2));

        float mAn = fmaxf(mA, tmA), mBn = fmaxf(mB, tmB);
        float fA = __expf(mA - mAn), fB = __expf(mB - mBn);
        mA = mAn; mB = mBn;

        // ---- P = exp(S-m) -> current K buffer rows, row sums ----
        uint32_t* Kp = s3 + ((it & 1) * ATILE);
        float sA = 0.f, sB = 0.f;
        #pragma unroll
        for (int f = 0; f < 8; f++) {
            float p0 = __expf(sf[f][0] - mA);
            float p1 = __expf(sf[f][1] - mA);
            float p2 = __expf(sf[f][2] - mB);
            float p3 = __expf(sf[f][3] - mB);
            sA += p0 + p1; sB += p2 + p3;
            uint2 lo = make_uint2(f2tf32(p0), f2tf32(p1));
            uint2 hi = make_uint2(f2tf32(p2), f2tf32(p3));
            *(uint2*)&Kp[(wr0 + g    )*AP + f*8 + 2*qc] = lo;
            *(uint2*)&Kp[(wr0 + g + 8)*AP + f*8 + 2*qc] = hi;
        }
        sA += __shfl_xor_sync(~0u, sA, 1); sA += __shfl_xor_sync(~0u, sA, 2);
        sB += __shfl_xor_sync(~0u, sB, 1); sB += __shfl_xor_sync(~0u, sB, 2);
        lA = lA * fA + sA;
        lB = lB * fB + sB;

        // ---- rescale accumulator ----
        #pragma unroll
        for (int f = 0; f < 8; f++) {
            acc[f][0] *= fA; acc[f][1] *= fA; acc[f][2] *= fB; acc[f][3] *= fB;
        }
        __syncwarp();

        // ---- P fragments (own warp rows of K buffer) ----
        uint32_t pf[8][4];
        #pragma unroll
        for (int kk = 0; kk < 8; kk++)
            ldsm_x4(pf[kk], Kb + (wr0 * AP + a_off + kk * 8) * 4);

        // ---- O += P V ----
        #pragma unroll
        for (int kk = 0; kk < 8; kk++) {
            #pragma unroll
            for (int f2 = 0; f2 < 4; f2++) {
                uint32_t r[4];
                ldsm_x4(r, Vb + (f2 * 16 * AP + b_off + kk * 8) * 4);
                uint32_t b0[2] = {r[0], r[1]}, b1[2] = {r[2], r[3]};
                mma_tf32(acc[2*f2],     pf[kk], b0);
                mma_tf32(acc[2*f2 + 1], pf[kk], b1);
            }
        }

        // ---- gate transition: after last memory tile ----
        if (it == nMem - 1) {
            #pragma unroll
            for (int f = 0; f < 8; f++) {
                acc[f][0] *= gA; acc[f][1] *= gA;
                acc[f][2] *= gB; acc[f][3] *= gB;
            }
        }
        __syncthreads();   // P/V(it) free before next FILL overwrites
    }
    #undef FILL_KV
    #undef KBUF
    #undef VBUF
    #undef S0OF

    // ---- epilogue: Y = acc / l ----
    float invA = 1.f / lA, invB = 1.f / lB;
    #pragma unroll
    for (int f = 0; f < 8; f++) {
        int col = h*HD_ + f*8 + 2*qc;
        float2 o0 = make_float2(acc[f][0] * invA, acc[f][1] * invA);
        float2 o1 = make_float2(acc[f][2] * invB, acc[f][3] * invB);
        *(float2*)&outp[(size_t)(b*T_ + rA) * C_ + col] = o0;
        *(float2*)&outp[(size_t)(b*T_ + rB) * C_ + col] = o1;
    }
}

// ---------------- canon conv -> tf32 bits ----------------------------------
__global__ __launch_bounds__(256)
void conv_kernel(const float* __restrict__ y, const float* __restrict__ cw,
                 const float* __restrict__ cb, uint32_t* __restrict__ z) {
    int idx = blockIdx.x * 256 + threadIdx.x;
    if (idx >= B_*T_*C_) return;
    int c = idx % C_;
    int t = (idx / C_) % T_;
    int b = idx / (C_ * T_);
    float s = y[idx] + cb[c];
    #pragma unroll
    for (int j = 0; j < KC_; j++) {
        int tt = t - (KC_ - 1) + j;
        if (tt >= 0)
            s += y[((size_t)(b*T_ + tt)) * C_ + c] * cw[c*KC_ + j];
    }
    z[idx] = f2tf32(s);
}

// ---------------- orchestration -------------------------------------------
extern "C" void kernel_launch(void* const* d_in, const int* in_sizes, int n_in,
                              void* d_out, int out_size) {
    const float* x   = (const float*)d_in[0];
    const float* fwd = (const float*)d_in[1];
    const float* rev = (const float*)d_in[2];
    const float* Wq  = (const float*)d_in[3];
    const float* Wk  = (const float*)d_in[4];
    const float* Wv  = (const float*)d_in[5];
    const float* Wo  = (const float*)d_in[6];
    const float* gw  = (const float*)d_in[7];
    const float* gb  = (const float*)d_in[8];
    const float* cw  = (const float*)d_in[9];
    const float* cb  = (const float*)d_in[10];
    float* out = (float*)d_out;

    uint32_t *xc, *wtf, *ztf;
    float *qb, *kb, *vt, *gt, *at;
    cudaGetSymbolAddress((void**)&xc,  g_xcat);
    cudaGetSymbolAddress((void**)&wtf, g_wtf);
    cudaGetSymbolAddress((void**)&ztf, g_ztf);
    cudaGetSymbolAddress((void**)&qb,  g_q);
    cudaGetSymbolAddress((void**)&kb,  g_k);
    cudaGetSymbolAddress((void**)&vt,  g_vt);
    cudaGetSymbolAddress((void**)&gt,  g_gate);
    cudaGetSymbolAddress((void**)&at,  g_attn);

    cudaFuncSetAttribute(gemm_tc,
                         cudaFuncAttributeMaxDynamicSharedMemorySize, GEMM2_SMEM);
    cudaFuncSetAttribute(attn_tc2,
                         cudaFuncAttributeMaxDynamicSharedMemorySize, ATT5_SMEM);

    // 1. pre-convert inputs
    {
        int n4 = B_*S_*(C_/4);
        pack_kernel<<<(n4 + 255)/256, 256>>>((const float4*)x, (const float4*)fwd,
                                             (const float4*)rev, (uint4*)xc);
    }
    wcvt_kernel<<<(4*C_*C_/4 + 255)/256, 256>>>((const float4*)Wq, (const float4*)Wk,
                                                (const float4*)Wv, (const float4*)Wo,
                                                (uint4*)wtf);

    // 2. fused QKV projection (v written transposed into g_vt)
    gemm_tc<<<dim3(3*C_/128, (B_*S_)/128), 256, GEMM2_SMEM>>>(
        xc, wtf, nullptr, qb, kb, vt, B_*S_, 3*C_, C_, 1, 1);

    // 3. gate
    gate_kernel<<<B_*T_, 256>>>(qb, gw, gb, gt);
    // 4. attention
    attn_tc2<<<dim3(T_/64, B_*H_), 128, ATT5_SMEM>>>(qb, kb, vt, gt, at);
    // 5. canon conv (writes tf32)
    conv_kernel<<<(B_*T_*C_ + 255)/256, 256>>>(at, cw, cb, ztf);
    // 6. output projection into d_out
    gemm_tc<<<dim3(C_/128, (B_*T_)/128), 256, GEMM2_SMEM>>>(
        ztf, wtf + 3*C_*C_, out, nullptr, nullptr, nullptr, B_*T_, C_, C_, 0, 0);
}

// round 10
// speedup vs baseline: 1.2686x; 1.0073x over previous
#include <cuda_runtime.h>
#include <math.h>
#include <stdint.h>

#define B_ 2
#define T_ 2048
#define C_ 1024
#define H_ 16
#define HD_ 64
#define M_ 256
#define S_ (T_ + 2*M_)   /* 2560 */
#define KC_ 4

// ---------------- scratch (static device globals; no runtime alloc) -------
__device__ uint32_t g_xcat[B_*S_*C_];   // concat(x,fwd,rev) as tf32 bits
__device__ uint32_t g_wtf [4*C_*C_];    // Wq|Wk|Wv|Wo as tf32 bits
__device__ float    g_q   [B_*T_*C_];   // tf32-rounded
__device__ float    g_k   [B_*S_*C_];   // tf32-rounded
__device__ float    g_vt  [B_*C_*S_];   // V^T, tf32-rounded: [b][c][s]
__device__ float    g_gate[B_*T_*H_];
__device__ float    g_attn[B_*T_*C_];
__device__ uint32_t g_ztf [B_*T_*C_];   // conv output as tf32 bits

// ================= TF32 helpers ===========================================
__device__ __forceinline__ uint32_t f2tf32(float f) {
    uint32_t r;
    asm("cvt.rna.tf32.f32 %0, %1;" : "=r"(r) : "f"(f));
    return r;
}
__device__ __forceinline__ void mma_tf32(float* d, const uint32_t* a,
                                         const uint32_t* b) {
    asm volatile(
        "mma.sync.aligned.m16n8k8.row.col.f32.tf32.tf32.f32 "
        "{%0,%1,%2,%3}, {%4,%5,%6,%7}, {%8,%9}, {%0,%1,%2,%3};"
        : "+f"(d[0]), "+f"(d[1]), "+f"(d[2]), "+f"(d[3])
        : "r"(a[0]), "r"(a[1]), "r"(a[2]), "r"(a[3]),
          "r"(b[0]), "r"(b[1]));
}
__device__ __forceinline__ void ldsm_x4(uint32_t* r, uint32_t addr) {
    asm volatile("ldmatrix.sync.aligned.m8n8.x4.shared.b16 {%0,%1,%2,%3}, [%4];"
        : "=r"(r[0]), "=r"(r[1]), "=r"(r[2]), "=r"(r[3]) : "r"(addr));
}
__device__ __forceinline__ void cp16(uint32_t dst, const void* src) {
    asm volatile("cp.async.cg.shared.global [%0], [%1], 16;" :: "r"(dst), "l"(src));
}

// ---------------- pack: xcat = concat(x, fwd, rev) -> tf32 bits ----------
__global__ void pack_kernel(const float4* __restrict__ x,
                            const float4* __restrict__ fwd,
                            const float4* __restrict__ rev,
                            uint4* __restrict__ xc) {
    const int C4 = C_/4;
    int idx = blockIdx.x * 256 + threadIdx.x;
    if (idx >= B_*S_*C4) return;
    int c4 = idx % C4;
    int r  = (idx / C4) % S_;
    int b  = idx / (C4 * S_);
    float4 val;
    if (r < T_)            val = x  [(b*T_ + r)          * C4 + c4];
    else if (r < T_ + M_)  val = fwd[(b*M_ + (r - T_))   * C4 + c4];
    else                   val = rev[(b*M_ + (r - T_-M_))* C4 + c4];
    xc[idx] = make_uint4(f2tf32(val.x), f2tf32(val.y), f2tf32(val.z), f2tf32(val.w));
}

// ---------------- weight cvt ------------------------------------------------
__global__ void wcvt_kernel(const float4* __restrict__ w0, const float4* __restrict__ w1,
                            const float4* __restrict__ w2, const float4* __restrict__ w3,
                            uint4* __restrict__ dst) {
    const int n4 = C_*C_/4;
    int idx = blockIdx.x * 256 + threadIdx.x;
    if (idx >= 4*n4) return;
    int m = idx / n4, r = idx % n4;
    const float4* s = (m == 0) ? w0 : (m == 1) ? w1 : (m == 2) ? w2 : w3;
    float4 v = s[r];
    dst[idx] = make_uint4(f2tf32(v.x), f2tf32(v.y), f2tf32(v.z), f2tf32(v.w));
}

// ================= TF32 GEMM: cp.async 3-stage + ldmatrix ==================
#define GBM 128
#define GBN 128
#define GBK 32
#define GPAD 36
#define GSTG (GBM * GPAD)
#define GSTRIDE (2 * GSTG)
#define GEMM2_SMEM (3 * GSTRIDE * (int)sizeof(uint32_t))

__global__ __launch_bounds__(256)
void gemm_tc(const uint32_t* __restrict__ A, const uint32_t* __restrict__ Bm,
             float* __restrict__ Cm, float* __restrict__ qp,
             float* __restrict__ kp, float* __restrict__ vp,
             int Mr, int Nr, int Kr, int rnd, int mode) {
    if (mode == 1 && blockIdx.x < 8 && (blockIdx.y % 20) >= 16) return;

    extern __shared__ uint32_t smg[];
    const uint32_t sbase = (uint32_t)__cvta_generic_to_shared(smg);

    const int tid  = threadIdx.x;
    const int lane = tid & 31, warp = tid >> 5;
    const int g = lane >> 2, qc = lane & 3;
    const int wm0 = (warp >> 2) * 64;
    const int wn0 = (warp & 3) * 32;
    const int m0 = blockIdx.y * GBM, n0 = blockIdx.x * GBN;
    const int nk = Kr / GBK;

    const int a_off = ((lane & 7) + ((lane >> 3) & 1) * 8) * GPAD + (lane >> 4) * 4;
    const int b_off = (((lane >> 4) & 1) * 8 + (lane & 7)) * GPAD + ((lane >> 3) & 1) * 4;

    float acc[4][4][4] = {};

    #define PREFETCH(KT)                                                       \
    do {                                                                       \
        int kt_ = (KT);                                                        \
        if (kt_ < nk) {                                                        \
            int slot_ = kt_ % 3;                                               \
            uint32_t da = sbase + (slot_ * GSTRIDE) * 4;                       \
            uint32_t db = da + GSTG * 4;                                       \
            const uint32_t* Ag_ = A  + (size_t)m0 * Kr + kt_ * GBK;            \
            const uint32_t* Bg_ = Bm + (size_t)n0 * Kr + kt_ * GBK;            \
            _Pragma("unroll")                                                  \
            for (int j = 0; j < 4; j++) {                                      \
                int u = tid + j * 256;                                         \
                int row = u >> 3, c4 = (u & 7) * 4;                            \
                cp16(da + (row * GPAD + c4) * 4, Ag_ + (size_t)row * Kr + c4); \
                cp16(db + (row * GPAD + c4) * 4, Bg_ + (size_t)row * Kr + c4); \
            }                                                                  \
        }                                                                      \
        asm volatile("cp.async.commit_group;");                                \
    } while (0)

    PREFETCH(0);
    PREFETCH(1);

    for (int kt = 0; kt < nk; kt++) {
        asm volatile("cp.async.wait_group 1;");
        __syncthreads();
        PREFETCH(kt + 2);

        const int slot = kt % 3;
        const uint32_t aAddr = sbase + (slot * GSTRIDE) * 4 + (wm0 * GPAD + a_off) * 4;
        const uint32_t bAddr = sbase + (slot * GSTRIDE + GSTG) * 4 + (wn0 * GPAD + b_off) * 4;

        #pragma unroll
        for (int kp_ = 0; kp_ < 4; kp_++) {
            uint32_t bf[4][2];
            {
                uint32_t r[4];
                ldsm_x4(r, bAddr + kp_ * 32);
                bf[0][0] = r[0]; bf[0][1] = r[1]; bf[1][0] = r[2]; bf[1][1] = r[3];
            }
            {
                uint32_t r[4];
                ldsm_x4(r, bAddr + 16 * GPAD * 4 + kp_ * 32);
                bf[2][0] = r[0]; bf[2][1] = r[1]; bf[3][0] = r[2]; bf[3][1] = r[3];
            }
            uint32_t af[4][4];
            #pragma unroll
            for (int mt = 0; mt < 4; mt++)
                ldsm_x4(af[mt], aAddr + mt * 16 * GPAD * 4 + kp_ * 32);
            #pragma unroll
            for (int mt = 0; mt < 4; mt++)
                #pragma unroll
                for (int nt = 0; nt < 4; nt++)
                    mma_tf32(acc[mt][nt], af[mt], bf[nt]);
        }
    }
    #undef PREFETCH

    if (rnd) {
        #pragma unroll
        for (int mt = 0; mt < 4; mt++)
            #pragma unroll
            for (int nt = 0; nt < 4; nt++)
                #pragma unroll
                for (int e = 0; e < 4; e++)
                    acc[mt][nt][e] = __uint_as_float(f2tf32(acc[mt][nt][e]));
    }

    if (mode == 0) {
        #pragma unroll
        for (int mt = 0; mt < 4; mt++) {
            #pragma unroll
            for (int nt = 0; nt < 4; nt++) {
                int row = m0 + wm0 + mt*16 + g;
                int col = n0 + wn0 + nt*8 + qc*2;
                float2 lo = make_float2(acc[mt][nt][0], acc[mt][nt][1]);
                float2 hi = make_float2(acc[mt][nt][2], acc[mt][nt][3]);
                *(float2*)(Cm + (size_t)row     * Nr + col) = lo;
                *(float2*)(Cm + (size_t)(row+8) * Nr + col) = hi;
            }
        }
    } else {
        #pragma unroll
        for (int mt = 0; mt < 4; mt++) {
            #pragma unroll
            for (int nt = 0; nt < 4; nt++) {
                int row = m0 + wm0 + mt*16 + g;
                int col = n0 + wn0 + nt*8 + qc*2;
                int which = col >> 10, lc = col & 1023;
                int bb = row / S_, rr = row % S_;
                float2 lo = make_float2(acc[mt][nt][0], acc[mt][nt][1]);
                float2 hi = make_float2(acc[mt][nt][2], acc[mt][nt][3]);
                if (which == 0) {
                    if (rr < T_) {
                        float* dst = qp + ((size_t)(bb*T_ + rr)) * C_ + lc;
                        *(float2*)(dst)         = lo;
                        *(float2*)(dst + 8*C_)  = hi;
                    }
                } else if (which == 1) {
                    float* dst = kp + (size_t)row * C_ + lc;
                    *(float2*)(dst)         = lo;
                    *(float2*)(dst + 8*C_)  = hi;
                } else {
                    float* b0 = vp + ((size_t)(bb*C_ + lc)) * S_ + rr;
                    b0[0]       = lo.x;
                    b0[S_]      = lo.y;
                    b0[8]       = hi.x;
                    b0[S_ + 8]  = hi.y;
                }
            }
        }
    }
}

// ---------------- gate v3: 16 rows/block, gw register-cached per warp ------
#define GR 16
#define GATE_SMEM (GR * 256 * (int)sizeof(float4))   // 64 KB

__global__ __launch_bounds__(256)
void gate_kernel(const float* __restrict__ q, const float* __restrict__ gw,
                 const float* __restrict__ gb, float* __restrict__ gate) {
    extern __shared__ float4 qs[];          // [GR][256]
    const int bt0 = blockIdx.x * GR;
    const int tid = threadIdx.x;
    const int warp = tid >> 5, lane = tid & 31;

    // stage 16 q rows (each row 256 float4)
    const float4* q4 = (const float4*)(q + (size_t)bt0 * C_);
    #pragma unroll
    for (int i = 0; i < GR; i++)
        qs[i * 256 + tid] = q4[i * 256 + tid];
    __syncthreads();

    const int h0 = warp * 2, h1 = h0 + 1;
    const float4* g0p = (const float4*)(gw + h0 * C_);
    const float4* g1p = (const float4*)(gw + h1 * C_);

    float s0[GR] = {}, s1[GR] = {};
    #pragma unroll
    for (int i = 0; i < 8; i++) {
        float4 g0 = g0p[lane + i*32];
        float4 g1 = g1p[lane + i*32];
        #pragma unroll
        for (int r = 0; r < GR; r++) {
            float4 qv = qs[r * 256 + lane + i*32];
            s0[r] += qv.x*g0.x + qv.y*g0.y + qv.z*g0.z + qv.w*g0.w;
            s1[r] += qv.x*g1.x + qv.y*g1.y + qv.z*g1.z + qv.w*g1.w;
        }
    }
    float b0 = gb[h0], b1 = gb[h1];
    #pragma unroll
    for (int r = 0; r < GR; r++) {
        float v0 = s0[r], v1 = s1[r];
        #pragma unroll
        for (int o = 16; o; o >>= 1) {
            v0 += __shfl_xor_sync(~0u, v0, o);
            v1 += __shfl_xor_sync(~0u, v1, o);
        }
        if (lane == 0) {
            gate[(size_t)(bt0 + r) * H_ + h0] = 1.f / (1.f + __expf(-(v0 + b0)));
            gate[(size_t)(bt0 + r) * H_ + h1] = 1.f / (1.f + __expf(-(v1 + b1)));
        }
    }
}

// ================= attention v5: mem-first gated acc, 4-tile, 3 CTA/SM =====
#define AP 68
#define ATILE (64 * AP)
#define ATT5_SMEM (4 * ATILE * (int)sizeof(uint32_t))   // 69632 B -> 3 CTA/SM

__global__ __launch_bounds__(128, 3)
void attn_tc2(const float* __restrict__ q, const float* __restrict__ k,
              const float* __restrict__ vT, const float* __restrict__ gate,
              float* __restrict__ outp) {
    extern __shared__ uint32_t s3[];
    const uint32_t sbase = (uint32_t)__cvta_generic_to_shared(s3);

    const int tid  = threadIdx.x;
    const int lane = tid & 31, warp = tid >> 5;
    const int g = lane >> 2, qc = lane & 3;
    const int wr0 = warp * 16;
    const int b  = blockIdx.y >> 4;
    const int h  = blockIdx.y & 15;
    const int t0 = (gridDim.x - 1 - blockIdx.x) * 64;

    const int a_off = ((lane & 7) + ((lane >> 3) & 1) * 8) * AP + (lane >> 4) * 4;
    const int b_off = (((lane >> 4) & 1) * 8 + (lane & 7)) * AP + ((lane >> 3) & 1) * 4;

    const int nMem   = (2*M_)/64;
    const int nChunk = t0/64 + 1;
    const int nTiles = nMem + nChunk;

    #define KBUF(IT) (sbase + ((((IT) & 1)    ) * ATILE) * 4)
    #define VBUF(IT) (sbase + ((2 + ((IT) & 1)) * ATILE) * 4)
    #define S0OF(IT) (((IT) < nMem) ? (T_ + (IT)*64) : ((IT) - nMem)*64)

    {
        const float* src_ = q + ((size_t)(b*T_ + t0)) * C_ + h*HD_;
        #pragma unroll
        for (int j = 0; j < 8; j++) {
            int u = tid + j * 128;
            int row = u >> 4, cw = (u & 15) * 4;
            cp16(VBUF(1) + (row * AP + cw) * 4, src_ + (size_t)row * C_ + cw);
        }
        asm volatile("cp.async.commit_group;");
    }

    #define FILL_KV(IT)                                                       \
    do {                                                                      \
        int it_ = (IT);                                                       \
        if (it_ < nTiles) {                                                   \
            int s0_ = S0OF(it_);                                              \
            uint32_t kb_ = KBUF(it_);                                         \
            uint32_t vb_ = VBUF(it_);                                         \
            const float* ks_ = k  + ((size_t)(b*S_ + s0_)) * C_ + h*HD_;      \
            const float* vs_ = vT + ((size_t)(b*C_ + h*HD_)) * S_ + s0_;      \
            _Pragma("unroll")                                                 \
            for (int j = 0; j < 8; j++) {                                     \
                int u = tid + j * 128;                                        \
                int row = u >> 4, cw = (u & 15) * 4;                          \
                cp16(kb_ + (row * AP + cw) * 4, ks_ + (size_t)row * C_ + cw); \
                cp16(vb_ + (row * AP + cw) * 4, vs_ + (size_t)row * S_ + cw); \
            }                                                                 \
        }                                                                     \
        asm volatile("cp.async.commit_group;");                               \
    } while (0)

    FILL_KV(0);
    asm volatile("cp.async.wait_group 1;");
    __syncthreads();

    uint32_t qf[8][4];
    #pragma unroll
    for (int kk = 0; kk < 8; kk++) {
        ldsm_x4(qf[kk], VBUF(1) + (wr0 * AP + a_off + kk * 8) * 4);
        #pragma unroll
        for (int e = 0; e < 4; e++)
            qf[kk][e] = __float_as_uint(__uint_as_float(qf[kk][e]) * 0.125f);
    }
    __syncthreads();

    const int rA = t0 + wr0 + g, rB = rA + 8;
    const float gA = gate[(size_t)(b*T_ + rA) * H_ + h];
    const float gB = gate[(size_t)(b*T_ + rB) * H_ + h];

    float acc[8][4] = {};
    float mA = -1e30f, mB = -1e30f, lA = 0.f, lB = 0.f;

    for (int it = 0; it < nTiles; it++) {
        const int  s0     = S0OF(it);
        const bool isDiag = (it == nTiles - 1);
        const uint32_t Kb = KBUF(it);
        const uint32_t Vb = VBUF(it);

        FILL_KV(it + 1);
        asm volatile("cp.async.wait_group 1;");
        __syncthreads();

        float sf[8][4] = {};
        #pragma unroll
        for (int kk = 0; kk < 8; kk++) {
            #pragma unroll
            for (int f2 = 0; f2 < 4; f2++) {
                uint32_t r[4];
                ldsm_x4(r, Kb + (f2 * 16 * AP + b_off + kk * 8) * 4);
                uint32_t b0[2] = {r[0], r[1]}, b1[2] = {r[2], r[3]};
                mma_tf32(sf[2*f2],     qf[kk], b0);
                mma_tf32(sf[2*f2 + 1], qf[kk], b1);
            }
        }
        __syncthreads();

        float tmA = -1e30f, tmB = -1e30f;
        #pragma unroll
        for (int f = 0; f < 8; f++) {
            if (isDiag) {
                int c0 = s0 + f*8 + 2*qc, c1 = c0 + 1;
                if (c0 > rA) sf[f][0] = -1e30f;
                if (c1 > rA) sf[f][1] = -1e30f;
                if (c0 > rB) sf[f][2] = -1e30f;
                if (c1 > rB) sf[f][3] = -1e30f;
            }
            tmA = fmaxf(tmA, fmaxf(sf[f][0], sf[f][1]));
            tmB = fmaxf(tmB, fmaxf(sf[f][2], sf[f][3]));
        }
        tmA = fmaxf(tmA, __shfl_xor_sync(~0u, tmA, 1));
        tmA = fmaxf(tmA, __shfl_xor_sync(~0u, tmA, 2));
        tmB = fmaxf(tmB, __shfl_xor_sync(~0u, tmB, 1));
        tmB = fmaxf(tmB, __shfl_xor_sync(~0u, tmB, 2));

        float mAn = fmaxf(mA, tmA), mBn = fmaxf(mB, tmB);
        float fA = __expf(mA - mAn), fB = __expf(mB - mBn);
        mA = mAn; mB = mBn;

        uint32_t* Kp = s3 + ((it & 1) * ATILE);
        float sA = 0.f, sB = 0.f;
        #pragma unroll
        for (int f = 0; f < 8; f++) {
            float p0 = __expf(sf[f][0] - mA);
            float p1 = __expf(sf[f][1] - mA);
            float p2 = __expf(sf[f][2] - mB);
            float p3 = __expf(sf[f][3] - mB);
            sA += p0 + p1; sB += p2 + p3;
            uint2 lo = make_uint2(f2tf32(p0), f2tf32(p1));
            uint2 hi = make_uint2(f2tf32(p2), f2tf32(p3));
            *(uint2*)&Kp[(wr0 + g    )*AP + f*8 + 2*qc] = lo;
            *(uint2*)&Kp[(wr0 + g + 8)*AP + f*8 + 2*qc] = hi;
        }
        sA += __shfl_xor_sync(~0u, sA, 1); sA += __shfl_xor_sync(~0u, sA, 2);
        sB += __shfl_xor_sync(~0u, sB, 1); sB += __shfl_xor_sync(~0u, sB, 2);
        lA = lA * fA + sA;
        lB = lB * fB + sB;

        #pragma unroll
        for (int f = 0; f < 8; f++) {
            acc[f][0] *= fA; acc[f][1] *= fA; acc[f][2] *= fB; acc[f][3] *= fB;
        }
        __syncwarp();

        uint32_t pf[8][4];
        #pragma unroll
        for (int kk = 0; kk < 8; kk++)
            ldsm_x4(pf[kk], Kb + (wr0 * AP + a_off + kk * 8) * 4);

        #pragma unroll
        for (int kk = 0; kk < 8; kk++) {
            #pragma unroll
            for (int f2 = 0; f2 < 4; f2++) {
                uint32_t r[4];
                ldsm_x4(r, Vb + (f2 * 16 * AP + b_off + kk * 8) * 4);
                uint32_t b0[2] = {r[0], r[1]}, b1[2] = {r[2], r[3]};
                mma_tf32(acc[2*f2],     pf[kk], b0);
                mma_tf32(acc[2*f2 + 1], pf[kk], b1);
            }
        }

        if (it == nMem - 1) {
            #pragma unroll
            for (int f = 0; f < 8; f++) {
                acc[f][0] *= gA; acc[f][1] *= gA;
                acc[f][2] *= gB; acc[f][3] *= gB;
            }
        }
        __syncthreads();
    }
    #undef FILL_KV
    #undef KBUF
    #undef VBUF
    #undef S0OF

    float invA = 1.f / lA, invB = 1.f / lB;
    #pragma unroll
    for (int f = 0; f < 8; f++) {
        int col = h*HD_ + f*8 + 2*qc;
        float2 o0 = make_float2(acc[f][0] * invA, acc[f][1] * invA);
        float2 o1 = make_float2(acc[f][2] * invB, acc[f][3] * invB);
        *(float2*)&outp[(size_t)(b*T_ + rA) * C_ + col] = o0;
        *(float2*)&outp[(size_t)(b*T_ + rB) * C_ + col] = o1;
    }
}

// ---------------- canon conv v2 (float4) -> tf32 bits -----------------------
__global__ __launch_bounds__(256)
void conv_kernel(const float4* __restrict__ y4, const float* __restrict__ cw,
                 const float4* __restrict__ cb4, uint4* __restrict__ z) {
    const int C4 = C_/4;
    int idx = blockIdx.x * 256 + threadIdx.x;     // over B*T*C4
    if (idx >= B_*T_*C4) return;
    int c4 = idx & (C4 - 1);
    int t  = (idx / C4) % T_;
    int b  = idx / (C4 * T_);

    // cw rows for channels c4*4 .. c4*4+3 (each float4 = weights j=0..3)
    const float4* cwr = (const float4*)cw;
    float4 w0 = cwr[c4*4 + 0];
    float4 w1 = cwr[c4*4 + 1];
    float4 w2 = cwr[c4*4 + 2];
    float4 w3 = cwr[c4*4 + 3];
    float wa[4][4] = {{w0.x,w0.y,w0.z,w0.w}, {w1.x,w1.y,w1.z,w1.w},
                      {w2.x,w2.y,w2.z,w2.w}, {w3.x,w3.y,w3.z,w3.w}};

    float4 acc = y4[idx];
    float4 cbv = cb4[c4];
    acc.x += cbv.x; acc.y += cbv.y; acc.z += cbv.z; acc.w += cbv.w;

    #pragma unroll
    for (int j = 0; j < KC_; j++) {
        int tt = t - (KC_ - 1) + j;
        if (tt >= 0) {
            float4 yv = y4[((size_t)(b*T_ + tt)) * C4 + c4];
            acc.x += yv.x * wa[0][j];
            acc.y += yv.y * wa[1][j];
            acc.z += yv.z * wa[2][j];
            acc.w += yv.w * wa[3][j];
        }
    }
    z[idx] = make_uint4(f2tf32(acc.x), f2tf32(acc.y), f2tf32(acc.z), f2tf32(acc.w));
}

// ---------------- orchestration -------------------------------------------
extern "C" void kernel_launch(void* const* d_in, const int* in_sizes, int n_in,
                              void* d_out, int out_size) {
    const float* x   = (const float*)d_in[0];
    const float* fwd = (const float*)d_in[1];
    const float* rev = (const float*)d_in[2];
    const float* Wq  = (const float*)d_in[3];
    const float* Wk  = (const float*)d_in[4];
    const float* Wv  = (const float*)d_in[5];
    const float* Wo  = (const float*)d_in[6];
    const float* gw  = (const float*)d_in[7];
    const float* gb  = (const float*)d_in[8];
    const float* cw  = (const float*)d_in[9];
    const float* cb  = (const float*)d_in[10];
    float* out = (float*)d_out;

    uint32_t *xc, *wtf, *ztf;
    float *qb, *kb, *vt, *gt, *at;
    cudaGetSymbolAddress((void**)&xc,  g_xcat);
    cudaGetSymbolAddress((void**)&wtf, g_wtf);
    cudaGetSymbolAddress((void**)&ztf, g_ztf);
    cudaGetSymbolAddress((void**)&qb,  g_q);
    cudaGetSymbolAddress((void**)&kb,  g_k);
    cudaGetSymbolAddress((void**)&vt,  g_vt);
    cudaGetSymbolAddress((void**)&gt,  g_gate);
    cudaGetSymbolAddress((void**)&at,  g_attn);

    cudaFuncSetAttribute(gemm_tc,
                         cudaFuncAttributeMaxDynamicSharedMemorySize, GEMM2_SMEM);
    cudaFuncSetAttribute(attn_tc2,
                         cudaFuncAttributeMaxDynamicSharedMemorySize, ATT5_SMEM);
    cudaFuncSetAttribute(gate_kernel,
                         cudaFuncAttributeMaxDynamicSharedMemorySize, GATE_SMEM);

    // 1. pre-convert inputs
    {
        int n4 = B_*S_*(C_/4);
        pack_kernel<<<(n4 + 255)/256, 256>>>((const float4*)x, (const float4*)fwd,
                                             (const float4*)rev, (uint4*)xc);
    }
    wcvt_kernel<<<(4*C_*C_/4 + 255)/256, 256>>>((const float4*)Wq, (const float4*)Wk,
                                                (const float4*)Wv, (const float4*)Wo,
                                                (uint4*)wtf);

    // 2. fused QKV projection (v written transposed into g_vt)
    gemm_tc<<<dim3(3*C_/128, (B_*S_)/128), 256, GEMM2_SMEM>>>(
        xc, wtf, nullptr, qb, kb, vt, B_*S_, 3*C_, C_, 1, 1);

    // 3. gate
    gate_kernel<<<(B_*T_)/GR, 256, GATE_SMEM>>>(qb, gw, gb, gt);
    // 4. attention
    attn_tc2<<<dim3(T_/64, B_*H_), 128, ATT5_SMEM>>>(qb, kb, vt, gt, at);
    // 5. canon conv (writes tf32)
    conv_kernel<<<(B_*T_*(C_/4) + 255)/256, 256>>>((const float4*)at, cw,
                                                   (const float4*)cb, (uint4*)ztf);
    // 6. output projection into d_out
    gemm_tc<<<dim3(C_/128, (B_*T_)/128), 256, GEMM2_SMEM>>>(
        ztf, wtf + 3*C_*C_, out, nullptr, nullptr, nullptr, B_*T_, C_, C_, 0, 0);
}

// round 12
// speedup vs baseline: 2.0649x; 1.6277x over previous
#include <cuda_runtime.h>
#include <cuda_fp16.h>
#include <math.h>
#include <stdint.h>

#define B_ 2
#define T_ 2048
#define C_ 1024
#define H_ 16
#define HD_ 64
#define M_ 256
#define S_ (T_ + 2*M_)   /* 2560 */
#define KC_ 4

// ---------------- scratch (static device globals; no runtime alloc) -------
__device__ __half g_xcat[B_*S_*C_];   // concat(x,fwd,rev) fp16
__device__ __half g_wtf [4*C_*C_];    // Wq|Wk|Wv|Wo fp16
__device__ __half g_q16 [B_*T_*C_];   // q fp16
__device__ __half g_k16 [B_*S_*C_];   // k fp16
__device__ __half g_vt16[B_*C_*S_];   // V^T fp16: [b][c][s]
__device__ float  g_gate[B_*T_*H_];
__device__ float  g_attn[B_*T_*C_];
__device__ __half g_z16 [B_*T_*C_];   // conv output fp16

// ================= helpers =================================================
__device__ __forceinline__ uint32_t h2u(__half2 h) {
    return *reinterpret_cast<uint32_t*>(&h);
}
__device__ __forceinline__ void mma_f16(float* d, const uint32_t* a,
                                        const uint32_t* b) {
    asm volatile(
        "mma.sync.aligned.m16n8k16.row.col.f32.f16.f16.f32 "
        "{%0,%1,%2,%3}, {%4,%5,%6,%7}, {%8,%9}, {%0,%1,%2,%3};"
        : "+f"(d[0]), "+f"(d[1]), "+f"(d[2]), "+f"(d[3])
        : "r"(a[0]), "r"(a[1]), "r"(a[2]), "r"(a[3]),
          "r"(b[0]), "r"(b[1]));
}
__device__ __forceinline__ void ldsm_x4(uint32_t* r, uint32_t addr) {
    asm volatile("ldmatrix.sync.aligned.m8n8.x4.shared.b16 {%0,%1,%2,%3}, [%4];"
        : "=r"(r[0]), "=r"(r[1]), "=r"(r[2]), "=r"(r[3]) : "r"(addr));
}
__device__ __forceinline__ void cp16(uint32_t dst, const void* src) {
    asm volatile("cp.async.cg.shared.global [%0], [%1], 16;" :: "r"(dst), "l"(src));
}

// ---------------- pack: xcat = concat(x, fwd, rev) -> fp16 ----------------
__global__ void pack_kernel(const float4* __restrict__ x,
                            const float4* __restrict__ fwd,
                            const float4* __restrict__ rev,
                            uint2* __restrict__ xc) {
    const int C4 = C_/4;
    int idx = blockIdx.x * 256 + threadIdx.x;
    if (idx >= B_*S_*C4) return;
    int c4 = idx % C4;
    int r  = (idx / C4) % S_;
    int b  = idx / (C4 * S_);
    float4 val;
    if (r < T_)            val = x  [(b*T_ + r)          * C4 + c4];
    else if (r < T_ + M_)  val = fwd[(b*M_ + (r - T_))   * C4 + c4];
    else                   val = rev[(b*M_ + (r - T_-M_))* C4 + c4];
    xc[idx] = make_uint2(h2u(__floats2half2_rn(val.x, val.y)),
                         h2u(__floats2half2_rn(val.z, val.w)));
}

// ---------------- weight cvt -> fp16 ----------------------------------------
__global__ void wcvt_kernel(const float4* __restrict__ w0, const float4* __restrict__ w1,
                            const float4* __restrict__ w2, const float4* __restrict__ w3,
                            uint2* __restrict__ dst) {
    const int n4 = C_*C_/4;
    int idx = blockIdx.x * 256 + threadIdx.x;
    if (idx >= 4*n4) return;
    int m = idx / n4, r = idx % n4;
    const float4* s = (m == 0) ? w0 : (m == 1) ? w1 : (m == 2) ? w2 : w3;
    float4 v = s[r];
    dst[idx] = make_uint2(h2u(__floats2half2_rn(v.x, v.y)),
                          h2u(__floats2half2_rn(v.z, v.w)));
}

// ================= FP16 GEMM: cp.async 3-stage + ldmatrix ==================
// C[m,n] = sum_k A[m,k]*B[n,k]; A,B fp16, acc fp32.
// BM=BN=128, BK=32 halves, 256 threads (8 warps 2x4, 64x32 each).
// Row stride 80 B (64 B data + 16 pad) -> ldmatrix conflict-free.
#define GBK 32
#define GROWB 80
#define GOPB (128 * GROWB)               // bytes per operand per stage
#define GSTAGEB (2 * GOPB)
#define GEMM_SMEM (3 * GSTAGEB)          // 61440 B

__global__ __launch_bounds__(256)
void gemm_f16(const __half* __restrict__ A, const __half* __restrict__ Bm,
              float* __restrict__ Cm, __half* __restrict__ qp,
              __half* __restrict__ kp, __half* __restrict__ vp,
              int Nr, int Kr, int mode) {
    if (mode == 1 && blockIdx.x < 8 && (blockIdx.y % 20) >= 16) return;

    extern __shared__ uint32_t smg[];
    const uint32_t sbase = (uint32_t)__cvta_generic_to_shared(smg);

    const int tid  = threadIdx.x;
    const int lane = tid & 31, warp = tid >> 5;
    const int g = lane >> 2, qc = lane & 3;
    const int wm0 = (warp >> 2) * 64;
    const int wn0 = (warp & 3) * 32;
    const int m0 = blockIdx.y * 128, n0 = blockIdx.x * 128;
    const int nk = Kr / GBK;

    const int a_off = (lane & 15) * GROWB + (lane >> 4) * 16;
    const int b_off = (((lane >> 4) & 1) * 8 + (lane & 7)) * GROWB
                      + ((lane >> 3) & 1) * 16;

    float acc[4][4][4] = {};

    #define PREFETCH(KT)                                                       \
    do {                                                                       \
        int kt_ = (KT);                                                        \
        if (kt_ < nk) {                                                        \
            uint32_t da = sbase + (kt_ % 3) * GSTAGEB;                         \
            uint32_t db = da + GOPB;                                           \
            const __half* Ag_ = A  + (size_t)m0 * Kr + kt_ * GBK;              \
            const __half* Bg_ = Bm + (size_t)n0 * Kr + kt_ * GBK;              \
            _Pragma("unroll")                                                  \
            for (int j = 0; j < 2; j++) {                                      \
                int u = tid + j * 256;                                         \
                int row = u >> 2, q16 = u & 3;                                 \
                cp16(da + row * GROWB + q16 * 16, Ag_ + (size_t)row * Kr + q16 * 8); \
                cp16(db + row * GROWB + q16 * 16, Bg_ + (size_t)row * Kr + q16 * 8); \
            }                                                                  \
        }                                                                      \
        asm volatile("cp.async.commit_group;");                                \
    } while (0)

    PREFETCH(0);
    PREFETCH(1);

    for (int kt = 0; kt < nk; kt++) {
        asm volatile("cp.async.wait_group 1;");
        __syncthreads();
        PREFETCH(kt + 2);

        const uint32_t aAddr = sbase + (kt % 3) * GSTAGEB + wm0 * GROWB + a_off;
        const uint32_t bAddr = sbase + (kt % 3) * GSTAGEB + GOPB + wn0 * GROWB + b_off;

        #pragma unroll
        for (int kp_ = 0; kp_ < 2; kp_++) {
            uint32_t bf[4][2];
            {
                uint32_t r[4];
                ldsm_x4(r, bAddr + kp_ * 32);
                bf[0][0] = r[0]; bf[0][1] = r[1]; bf[1][0] = r[2]; bf[1][1] = r[3];
            }
            {
                uint32_t r[4];
                ldsm_x4(r, bAddr + 16 * GROWB + kp_ * 32);
                bf[2][0] = r[0]; bf[2][1] = r[1]; bf[3][0] = r[2]; bf[3][1] = r[3];
            }
            uint32_t af[4][4];
            #pragma unroll
            for (int mt = 0; mt < 4; mt++)
                ldsm_x4(af[mt], aAddr + mt * 16 * GROWB + kp_ * 32);
            #pragma unroll
            for (int mt = 0; mt < 4; mt++)
                #pragma unroll
                for (int nt = 0; nt < 4; nt++)
                    mma_f16(acc[mt][nt], af[mt], bf[nt]);
        }
    }
    #undef PREFETCH

    if (mode == 0) {
        #pragma unroll
        for (int mt = 0; mt < 4; mt++) {
            #pragma unroll
            for (int nt = 0; nt < 4; nt++) {
                int row = m0 + wm0 + mt*16 + g;
                int col = n0 + wn0 + nt*8 + qc*2;
                float2 lo = make_float2(acc[mt][nt][0], acc[mt][nt][1]);
                float2 hi = make_float2(acc[mt][nt][2], acc[mt][nt][3]);
                *(float2*)(Cm + (size_t)row     * Nr + col) = lo;
                *(float2*)(Cm + (size_t)(row+8) * Nr + col) = hi;
            }
        }
    } else {
        #pragma unroll
        for (int mt = 0; mt < 4; mt++) {
            #pragma unroll
            for (int nt = 0; nt < 4; nt++) {
                int row = m0 + wm0 + mt*16 + g;          // 0..B*S-1
                int col = n0 + wn0 + nt*8 + qc*2;        // 0..3071
                int which = col >> 10, lc = col & 1023;
                int bb = row / S_, rr = row % S_;
                __half2 lo = __floats2half2_rn(acc[mt][nt][0], acc[mt][nt][1]);
                __half2 hi = __floats2half2_rn(acc[mt][nt][2], acc[mt][nt][3]);
                if (which == 0) {
                    if (rr < T_) {
                        __half* dst = qp + ((size_t)(bb*T_ + rr)) * C_ + lc;
                        *(__half2*)(dst)        = lo;
                        *(__half2*)(dst + 8*C_) = hi;
                    }
                } else if (which == 1) {
                    __half* dst = kp + (size_t)row * C_ + lc;
                    *(__half2*)(dst)        = lo;
                    *(__half2*)(dst + 8*C_) = hi;
                } else {
                    __half* b0 = vp + ((size_t)(bb*C_ + lc)) * S_ + rr;
                    b0[0]      = __low2half(lo);
                    b0[S_]     = __high2half(lo);
                    b0[8]      = __low2half(hi);
                    b0[S_ + 8] = __high2half(hi);
                }
            }
        }
    }
}

// ---------------- gate: reads fp16 q --------------------------------------
#define GR 16
#define GATE_SMEM (GR * 256 * (int)sizeof(uint2))   // 32 KB

__global__ __launch_bounds__(256)
void gate_kernel(const __half* __restrict__ q, const float* __restrict__ gw,
                 const float* __restrict__ gb, float* __restrict__ gate) {
    extern __shared__ uint2 qs2[];          // [GR][256] uint2 = 4 halves
    const int bt0 = blockIdx.x * GR;
    const int tid = threadIdx.x;
    const int warp = tid >> 5, lane = tid & 31;

    const uint2* qsrc = (const uint2*)(q + (size_t)bt0 * C_);
    #pragma unroll
    for (int i = 0; i < GR; i++)
        qs2[i * 256 + tid] = qsrc[i * 256 + tid];
    __syncthreads();

    const int h0 = warp * 2, h1 = h0 + 1;
    const float4* g0p = (const float4*)(gw + h0 * C_);
    const float4* g1p = (const float4*)(gw + h1 * C_);

    float s0[GR] = {}, s1[GR] = {};
    #pragma unroll
    for (int i = 0; i < 8; i++) {
        float4 g0 = g0p[lane + i*32];
        float4 g1 = g1p[lane + i*32];
        #pragma unroll
        for (int r = 0; r < GR; r++) {
            uint2 qv = qs2[r * 256 + lane + i*32];
            float2 f01 = __half22float2(*reinterpret_cast<__half2*>(&qv.x));
            float2 f23 = __half22float2(*reinterpret_cast<__half2*>(&qv.y));
            s0[r] += f01.x*g0.x + f01.y*g0.y + f23.x*g0.z + f23.y*g0.w;
            s1[r] += f01.x*g1.x + f01.y*g1.y + f23.x*g1.z + f23.y*g1.w;
        }
    }
    float b0 = gb[h0], b1 = gb[h1];
    #pragma unroll
    for (int r = 0; r < GR; r++) {
        float v0 = s0[r], v1 = s1[r];
        #pragma unroll
        for (int o = 16; o; o >>= 1) {
            v0 += __shfl_xor_sync(~0u, v0, o);
            v1 += __shfl_xor_sync(~0u, v1, o);
        }
        if (lane == 0) {
            gate[(size_t)(bt0 + r) * H_ + h0] = 1.f / (1.f + __expf(-(v0 + b0)));
            gate[(size_t)(bt0 + r) * H_ + h1] = 1.f / (1.f + __expf(-(v1 + b1)));
        }
    }
}

// ================= fp16 attention: mem-first gated acc =====================
// Tiles 64 rows x 64 halves, row stride 144 B. Buffers: K0|K1|V0|V1|Q.
// P staged into dead K buffer. 3 CTA/SM.
#define AROWB 144
#define ATILE_B (64 * AROWB)             // 9216 B
#define ATT_SMEM (5 * ATILE_B)           // 46080 B

__global__ __launch_bounds__(128, 3)
void attn_f16(const __half* __restrict__ q, const __half* __restrict__ k,
              const __half* __restrict__ vT, const float* __restrict__ gate,
              float* __restrict__ outp) {
    extern __shared__ uint32_t s3[];
    const uint32_t sbase = (uint32_t)__cvta_generic_to_shared(s3);

    const int tid  = threadIdx.x;
    const int lane = tid & 31, warp = tid >> 5;
    const int g = lane >> 2, qc = lane & 3;
    const int wr0 = warp * 16;
    const int b  = blockIdx.y >> 4;
    const int h  = blockIdx.y & 15;
    const int t0 = (gridDim.x - 1 - blockIdx.x) * 64;

    const int a_off = (lane & 15) * AROWB + (lane >> 4) * 16;
    const int b_off = (((lane >> 4) & 1) * 8 + (lane & 7)) * AROWB
                      + ((lane >> 3) & 1) * 16;

    const int nMem   = (2*M_)/64;
    const int nChunk = t0/64 + 1;
    const int nTiles = nMem + nChunk;

    #define KBUF(IT) (sbase + (((IT) & 1)     ) * ATILE_B)
    #define VBUF(IT) (sbase + (2 + ((IT) & 1) ) * ATILE_B)
    #define QBUF     (sbase + 4 * ATILE_B)
    #define S0OF(IT) (((IT) < nMem) ? (T_ + (IT)*64) : ((IT) - nMem)*64)

    // ---- stage Q (own buffer) ----
    {
        const __half* src_ = q + ((size_t)(b*T_ + t0)) * C_ + h*HD_;
        #pragma unroll
        for (int j = 0; j < 4; j++) {
            int u = tid + j * 128;
            int row = u >> 3, cw = u & 7;
            cp16(QBUF + row * AROWB + cw * 16, src_ + (size_t)row * C_ + cw * 8);
        }
        asm volatile("cp.async.commit_group;");
    }

    #define FILL_KV(IT)                                                       \
    do {                                                                      \
        int it_ = (IT);                                                       \
        if (it_ < nTiles) {                                                   \
            int s0_ = S0OF(it_);                                              \
            uint32_t kb_ = KBUF(it_);                                         \
            uint32_t vb_ = VBUF(it_);                                         \
            const __half* ks_ = k  + ((size_t)(b*S_ + s0_)) * C_ + h*HD_;     \
            const __half* vs_ = vT + ((size_t)(b*C_ + h*HD_)) * S_ + s0_;     \
            _Pragma("unroll")                                                 \
            for (int j = 0; j < 4; j++) {                                     \
                int u = tid + j * 128;                                        \
                int row = u >> 3, cw = u & 7;                                 \
                cp16(kb_ + row * AROWB + cw * 16, ks_ + (size_t)row * C_ + cw * 8); \
                cp16(vb_ + row * AROWB + cw * 16, vs_ + (size_t)row * S_ + cw * 8); \
            }                                                                 \
        }                                                                     \
        asm volatile("cp.async.commit_group;");                               \
    } while (0)

    FILL_KV(0);
    asm volatile("cp.async.wait_group 1;");   // Q staged
    __syncthreads();

    // ---- Q fragments (4 k16 chunks), scale 1/8 folded ----
    uint32_t qf[4][4];
    const __half2 sc8 = __half2half2(__float2half(0.125f));
    #pragma unroll
    for (int kk = 0; kk < 4; kk++) {
        ldsm_x4(qf[kk], QBUF + wr0 * AROWB + a_off + kk * 32);
        #pragma unroll
        for (int e = 0; e < 4; e++) {
            __half2 hm = __hmul2(*reinterpret_cast<__half2*>(&qf[kk][e]), sc8);
            qf[kk][e] = h2u(hm);
        }
    }

    const int rA = t0 + wr0 + g, rB = rA + 8;
    const float gA = gate[(size_t)(b*T_ + rA) * H_ + h];
    const float gB = gate[(size_t)(b*T_ + rB) * H_ + h];

    float acc[8][4] = {};
    float mA = -1e30f, mB = -1e30f, lA = 0.f, lB = 0.f;

    for (int it = 0; it < nTiles; it++) {
        const int  s0     = S0OF(it);
        const bool isDiag = (it == nTiles - 1);
        const uint32_t Kb = KBUF(it);
        const uint32_t Vb = VBUF(it);

        FILL_KV(it + 1);
        asm volatile("cp.async.wait_group 1;");
        __syncthreads();                       // K/V(it) visible

        // ---- S = Q K^T ----
        float sf[8][4] = {};
        #pragma unroll
        for (int kk = 0; kk < 4; kk++) {
            #pragma unroll
            for (int f2 = 0; f2 < 4; f2++) {
                uint32_t r[4];
                ldsm_x4(r, Kb + f2 * 16 * AROWB + b_off + kk * 32);
                uint32_t b0[2] = {r[0], r[1]}, b1[2] = {r[2], r[3]};
                mma_f16(sf[2*f2],     qf[kk], b0);
                mma_f16(sf[2*f2 + 1], qf[kk], b1);
            }
        }
        __syncthreads();                       // done reading K(it)

        // ---- mask + row max ----
        float tmA = -1e30f, tmB = -1e30f;
        #pragma unroll
        for (int f = 0; f < 8; f++) {
            if (isDiag) {
                int c0 = s0 + f*8 + 2*qc, c1 = c0 + 1;
                if (c0 > rA) sf[f][0] = -1e30f;
                if (c1 > rA) sf[f][1] = -1e30f;
                if (c0 > rB) sf[f][2] = -1e30f;
                if (c1 > rB) sf[f][3] = -1e30f;
            }
            tmA = fmaxf(tmA, fmaxf(sf[f][0], sf[f][1]));
            tmB = fmaxf(tmB, fmaxf(sf[f][2], sf[f][3]));
        }
        tmA = fmaxf(tmA, __shfl_xor_sync(~0u, tmA, 1));
        tmA = fmaxf(tmA, __shfl_xor_sync(~0u, tmA, 2));
        tmB = fmaxf(tmB, __shfl_xor_sync(~0u, tmB, 1));
        tmB = fmaxf(tmB, __shfl_xor_sync(~0u, tmB, 2));

        float mAn = fmaxf(mA, tmA), mBn = fmaxf(mB, tmB);
        float fA = __expf(mA - mAn), fB = __expf(mB - mBn);
        mA = mAn; mB = mBn;

        // ---- P = exp(S-m) -> dead K buffer (fp16), fp32 row sums ----
        __half* Kph = (__half*)((char*)s3 + ((it & 1)) * ATILE_B);
        float sA = 0.f, sB = 0.f;
        #pragma unroll
        for (int f = 0; f < 8; f++) {
            float p0 = __expf(sf[f][0] - mA);
            float p1 = __expf(sf[f][1] - mA);
            float p2 = __expf(sf[f][2] - mB);
            float p3 = __expf(sf[f][3] - mB);
            sA += p0 + p1; sB += p2 + p3;
            *(__half2*)&Kph[(wr0 + g    )*72 + f*8 + 2*qc] = __floats2half2_rn(p0, p1);
            *(__half2*)&Kph[(wr0 + g + 8)*72 + f*8 + 2*qc] = __floats2half2_rn(p2, p3);
        }
        sA += __shfl_xor_sync(~0u, sA, 1); sA += __shfl_xor_sync(~0u, sA, 2);
        sB += __shfl_xor_sync(~0u, sB, 1); sB += __shfl_xor_sync(~0u, sB, 2);
        lA = lA * fA + sA;
        lB = lB * fB + sB;

        // ---- rescale accumulator ----
        #pragma unroll
        for (int f = 0; f < 8; f++) {
            acc[f][0] *= fA; acc[f][1] *= fA; acc[f][2] *= fB; acc[f][3] *= fB;
        }
        __syncwarp();

        // ---- P fragments ----
        uint32_t pf[4][4];
        #pragma unroll
        for (int kk = 0; kk < 4; kk++)
            ldsm_x4(pf[kk], Kb + wr0 * AROWB + a_off + kk * 32);

        // ---- O += P V ----
        #pragma unroll
        for (int kk = 0; kk < 4; kk++) {
            #pragma unroll
            for (int f2 = 0; f2 < 4; f2++) {
                uint32_t r[4];
                ldsm_x4(r, Vb + f2 * 16 * AROWB + b_off + kk * 32);
                uint32_t b0[2] = {r[0], r[1]}, b1[2] = {r[2], r[3]};
                mma_f16(acc[2*f2],     pf[kk], b0);
                mma_f16(acc[2*f2 + 1], pf[kk], b1);
            }
        }

        if (it == nMem - 1) {
            #pragma unroll
            for (int f = 0; f < 8; f++) {
                acc[f][0] *= gA; acc[f][1] *= gA;
                acc[f][2] *= gB; acc[f][3] *= gB;
            }
        }
        __syncthreads();   // P/V(it) free before next FILL overwrites
    }
    #undef FILL_KV
    #undef KBUF
    #undef VBUF
    #undef QBUF
    #undef S0OF

    float invA = 1.f / lA, invB = 1.f / lB;
    #pragma unroll
    for (int f = 0; f < 8; f++) {
        int col = h*HD_ + f*8 + 2*qc;
        float2 o0 = make_float2(acc[f][0] * invA, acc[f][1] * invA);
        float2 o1 = make_float2(acc[f][2] * invB, acc[f][3] * invB);
        *(float2*)&outp[(size_t)(b*T_ + rA) * C_ + col] = o0;
        *(float2*)&outp[(size_t)(b*T_ + rB) * C_ + col] = o1;
    }
}

// ---------------- canon conv (float4 in, fp16 out) --------------------------
__global__ __launch_bounds__(256)
void conv_kernel(const float4* __restrict__ y4, const float* __restrict__ cw,
                 const float4* __restrict__ cb4, uint2* __restrict__ z) {
    const int C4 = C_/4;
    int idx = blockIdx.x * 256 + threadIdx.x;
    if (idx >= B_*T_*C4) return;
    int c4 = idx & (C4 - 1);
    int t  = (idx / C4) % T_;
    int b  = idx / (C4 * T_);

    const float4* cwr = (const float4*)cw;
    float4 w0 = cwr[c4*4 + 0];
    float4 w1 = cwr[c4*4 + 1];
    float4 w2 = cwr[c4*4 + 2];
    float4 w3 = cwr[c4*4 + 3];
    float wa[4][4] = {{w0.x,w0.y,w0.z,w0.w}, {w1.x,w1.y,w1.z,w1.w},
                      {w2.x,w2.y,w2.z,w2.w}, {w3.x,w3.y,w3.z,w3.w}};

    float4 acc = y4[idx];
    float4 cbv = cb4[c4];
    acc.x += cbv.x; acc.y += cbv.y; acc.z += cbv.z; acc.w += cbv.w;

    #pragma unroll
    for (int j = 0; j < KC_; j++) {
        int tt = t - (KC_ - 1) + j;
        if (tt >= 0) {
            float4 yv = y4[((size_t)(b*T_ + tt)) * C4 + c4];
            acc.x += yv.x * wa[0][j];
            acc.y += yv.y * wa[1][j];
            acc.z += yv.z * wa[2][j];
            acc.w += yv.w * wa[3][j];
        }
    }
    z[idx] = make_uint2(h2u(__floats2half2_rn(acc.x, acc.y)),
                        h2u(__floats2half2_rn(acc.z, acc.w)));
}

// ---------------- orchestration -------------------------------------------
extern "C" void kernel_launch(void* const* d_in, const int* in_sizes, int n_in,
                              void* d_out, int out_size) {
    const float* x   = (const float*)d_in[0];
    const float* fwd = (const float*)d_in[1];
    const float* rev = (const float*)d_in[2];
    const float* Wq  = (const float*)d_in[3];
    const float* Wk  = (const float*)d_in[4];
    const float* Wv  = (const float*)d_in[5];
    const float* Wo  = (const float*)d_in[6];
    const float* gw  = (const float*)d_in[7];
    const float* gb  = (const float*)d_in[8];
    const float* cw  = (const float*)d_in[9];
    const float* cb  = (const float*)d_in[10];
    float* out = (float*)d_out;

    __half *xc, *wtf, *z16, *qb, *kb, *vt;
    float *gt, *at;
    cudaGetSymbolAddress((void**)&xc,  g_xcat);
    cudaGetSymbolAddress((void**)&wtf, g_wtf);
    cudaGetSymbolAddress((void**)&z16, g_z16);
    cudaGetSymbolAddress((void**)&qb,  g_q16);
    cudaGetSymbolAddress((void**)&kb,  g_k16);
    cudaGetSymbolAddress((void**)&vt,  g_vt16);
    cudaGetSymbolAddress((void**)&gt,  g_gate);
    cudaGetSymbolAddress((void**)&at,  g_attn);

    cudaFuncSetAttribute(gemm_f16,
                         cudaFuncAttributeMaxDynamicSharedMemorySize, GEMM_SMEM);
    cudaFuncSetAttribute(attn_f16,
                         cudaFuncAttributeMaxDynamicSharedMemorySize, ATT_SMEM);
    cudaFuncSetAttribute(gate_kernel,
                         cudaFuncAttributeMaxDynamicSharedMemorySize, GATE_SMEM);

    // 1. pre-convert inputs to fp16
    {
        int n4 = B_*S_*(C_/4);
        pack_kernel<<<(n4 + 255)/256, 256>>>((const float4*)x, (const float4*)fwd,
                                             (const float4*)rev, (uint2*)xc);
    }
    wcvt_kernel<<<(4*C_*C_/4 + 255)/256, 256>>>((const float4*)Wq, (const float4*)Wk,
                                                (const float4*)Wv, (const float4*)Wo,
                                                (uint2*)wtf);

    // 2. fused QKV projection (fp16 tensor cores; v written transposed)
    gemm_f16<<<dim3(3*C_/128, (B_*S_)/128), 256, GEMM_SMEM>>>(
        xc, wtf, nullptr, qb, kb, vt, 3*C_, C_, 1);

    // 3. gate
    gate_kernel<<<(B_*T_)/GR, 256, GATE_SMEM>>>(qb, gw, gb, gt);
    // 4. attention
    attn_f16<<<dim3(T_/64, B_*H_), 128, ATT_SMEM>>>(qb, kb, vt, gt, at);
    // 5. canon conv (writes fp16)
    conv_kernel<<<(B_*T_*(C_/4) + 255)/256, 256>>>((const float4*)at, cw,
                                                   (const float4*)cb, (uint2*)z16);
    // 6. output projection into d_out (fp32 out)
    gemm_f16<<<dim3(C_/128, (B_*T_)/128), 256, GEMM_SMEM>>>(
        z16, wtf + 3*C_*C_, out, nullptr, nullptr, nullptr, C_, C_, 0);
}

// round 13
// speedup vs baseline: 2.1740x; 1.0528x over previous
#include <cuda_runtime.h>
#include <cuda_fp16.h>
#include <math.h>
#include <stdint.h>

#define B_ 2
#define T_ 2048
#define C_ 1024
#define H_ 16
#define HD_ 64
#define M_ 256
#define S_ (T_ + 2*M_)   /* 2560 */
#define KC_ 4

// ---------------- scratch (static device globals; no runtime alloc) -------
__device__ __half g_xcat[B_*S_*C_];   // concat(x,fwd,rev) fp16
__device__ __half g_wtf [4*C_*C_];    // Wq|Wk|Wv|Wo fp16
__device__ __half g_q16 [B_*T_*C_];   // q fp16
__device__ __half g_k16 [B_*S_*C_];   // k fp16
__device__ __half g_vt16[B_*C_*S_];   // V^T fp16: [b][c][s]
__device__ float  g_gate[B_*T_*H_];
__device__ __half g_attn16[B_*T_*C_]; // attention output fp16
__device__ __half g_z16 [B_*T_*C_];   // conv output fp16

// ================= helpers =================================================
__device__ __forceinline__ uint32_t h2u(__half2 h) {
    return *reinterpret_cast<uint32_t*>(&h);
}
__device__ __forceinline__ void mma_f16(float* d, const uint32_t* a,
                                        const uint32_t* b) {
    asm volatile(
        "mma.sync.aligned.m16n8k16.row.col.f32.f16.f16.f32 "
        "{%0,%1,%2,%3}, {%4,%5,%6,%7}, {%8,%9}, {%0,%1,%2,%3};"
        : "+f"(d[0]), "+f"(d[1]), "+f"(d[2]), "+f"(d[3])
        : "r"(a[0]), "r"(a[1]), "r"(a[2]), "r"(a[3]),
          "r"(b[0]), "r"(b[1]));
}
__device__ __forceinline__ void ldsm_x4(uint32_t* r, uint32_t addr) {
    asm volatile("ldmatrix.sync.aligned.m8n8.x4.shared.b16 {%0,%1,%2,%3}, [%4];"
        : "=r"(r[0]), "=r"(r[1]), "=r"(r[2]), "=r"(r[3]) : "r"(addr));
}
__device__ __forceinline__ void cp16(uint32_t dst, const void* src) {
    asm volatile("cp.async.cg.shared.global [%0], [%1], 16;" :: "r"(dst), "l"(src));
}

// ---------------- pack: xcat = concat(x, fwd, rev) -> fp16 ----------------
__global__ void pack_kernel(const float4* __restrict__ x,
                            const float4* __restrict__ fwd,
                            const float4* __restrict__ rev,
                            uint2* __restrict__ xc) {
    const int C4 = C_/4;
    int idx = blockIdx.x * 256 + threadIdx.x;
    if (idx >= B_*S_*C4) return;
    int c4 = idx % C4;
    int r  = (idx / C4) % S_;
    int b  = idx / (C4 * S_);
    float4 val;
    if (r < T_)            val = x  [(b*T_ + r)          * C4 + c4];
    else if (r < T_ + M_)  val = fwd[(b*M_ + (r - T_))   * C4 + c4];
    else                   val = rev[(b*M_ + (r - T_-M_))* C4 + c4];
    xc[idx] = make_uint2(h2u(__floats2half2_rn(val.x, val.y)),
                         h2u(__floats2half2_rn(val.z, val.w)));
}

// ---------------- weight cvt -> fp16 ----------------------------------------
__global__ void wcvt_kernel(const float4* __restrict__ w0, const float4* __restrict__ w1,
                            const float4* __restrict__ w2, const float4* __restrict__ w3,
                            uint2* __restrict__ dst) {
    const int n4 = C_*C_/4;
    int idx = blockIdx.x * 256 + threadIdx.x;
    if (idx >= 4*n4) return;
    int m = idx / n4, r = idx % n4;
    const float4* s = (m == 0) ? w0 : (m == 1) ? w1 : (m == 2) ? w2 : w3;
    float4 v = s[r];
    dst[idx] = make_uint2(h2u(__floats2half2_rn(v.x, v.y)),
                          h2u(__floats2half2_rn(v.z, v.w)));
}

// ================= FP16 GEMM: cp.async 3-stage + ldmatrix ==================
#define GBK 32
#define GROWB 80
#define GOPB (128 * GROWB)
#define GSTAGEB (2 * GOPB)
#define GEMM_SMEM (3 * GSTAGEB)          // 61440 B

__global__ __launch_bounds__(256)
void gemm_f16(const __half* __restrict__ A, const __half* __restrict__ Bm,
              float* __restrict__ Cm, __half* __restrict__ qp,
              __half* __restrict__ kp, __half* __restrict__ vp,
              int Nr, int Kr, int mode) {
    if (mode == 1 && blockIdx.x < 8 && (blockIdx.y % 20) >= 16) return;

    extern __shared__ uint32_t smg[];
    const uint32_t sbase = (uint32_t)__cvta_generic_to_shared(smg);

    const int tid  = threadIdx.x;
    const int lane = tid & 31, warp = tid >> 5;
    const int g = lane >> 2, qc = lane & 3;
    const int wm0 = (warp >> 2) * 64;
    const int wn0 = (warp & 3) * 32;
    const int m0 = blockIdx.y * 128, n0 = blockIdx.x * 128;
    const int nk = Kr / GBK;

    const int a_off = (lane & 15) * GROWB + (lane >> 4) * 16;
    const int b_off = (((lane >> 4) & 1) * 8 + (lane & 7)) * GROWB
                      + ((lane >> 3) & 1) * 16;

    float acc[4][4][4] = {};

    #define PREFETCH(KT)                                                       \
    do {                                                                       \
        int kt_ = (KT);                                                        \
        if (kt_ < nk) {                                                        \
            uint32_t da = sbase + (kt_ % 3) * GSTAGEB;                         \
            uint32_t db = da + GOPB;                                           \
            const __half* Ag_ = A  + (size_t)m0 * Kr + kt_ * GBK;              \
            const __half* Bg_ = Bm + (size_t)n0 * Kr + kt_ * GBK;              \
            _Pragma("unroll")                                                  \
            for (int j = 0; j < 2; j++) {                                      \
                int u = tid + j * 256;                                         \
                int row = u >> 2, q16 = u & 3;                                 \
                cp16(da + row * GROWB + q16 * 16, Ag_ + (size_t)row * Kr + q16 * 8); \
                cp16(db + row * GROWB + q16 * 16, Bg_ + (size_t)row * Kr + q16 * 8); \
            }                                                                  \
        }                                                                      \
        asm volatile("cp.async.commit_group;");                                \
    } while (0)

    PREFETCH(0);
    PREFETCH(1);

    for (int kt = 0; kt < nk; kt++) {
        asm volatile("cp.async.wait_group 1;");
        __syncthreads();
        PREFETCH(kt + 2);

        const uint32_t aAddr = sbase + (kt % 3) * GSTAGEB + wm0 * GROWB + a_off;
        const uint32_t bAddr = sbase + (kt % 3) * GSTAGEB + GOPB + wn0 * GROWB + b_off;

        #pragma unroll
        for (int kp_ = 0; kp_ < 2; kp_++) {
            uint32_t bf[4][2];
            {
                uint32_t r[4];
                ldsm_x4(r, bAddr + kp_ * 32);
                bf[0][0] = r[0]; bf[0][1] = r[1]; bf[1][0] = r[2]; bf[1][1] = r[3];
            }
            {
                uint32_t r[4];
                ldsm_x4(r, bAddr + 16 * GROWB + kp_ * 32);
                bf[2][0] = r[0]; bf[2][1] = r[1]; bf[3][0] = r[2]; bf[3][1] = r[3];
            }
            uint32_t af[4][4];
            #pragma unroll
            for (int mt = 0; mt < 4; mt++)
                ldsm_x4(af[mt], aAddr + mt * 16 * GROWB + kp_ * 32);
            #pragma unroll
            for (int mt = 0; mt < 4; mt++)
                #pragma unroll
                for (int nt = 0; nt < 4; nt++)
                    mma_f16(acc[mt][nt], af[mt], bf[nt]);
        }
    }
    #undef PREFETCH

    if (mode == 0) {
        #pragma unroll
        for (int mt = 0; mt < 4; mt++) {
            #pragma unroll
            for (int nt = 0; nt < 4; nt++) {
                int row = m0 + wm0 + mt*16 + g;
                int col = n0 + wn0 + nt*8 + qc*2;
                float2 lo = make_float2(acc[mt][nt][0], acc[mt][nt][1]);
                float2 hi = make_float2(acc[mt][nt][2], acc[mt][nt][3]);
                *(float2*)(Cm + (size_t)row     * Nr + col) = lo;
                *(float2*)(Cm + (size_t)(row+8) * Nr + col) = hi;
            }
        }
    } else {
        #pragma unroll
        for (int mt = 0; mt < 4; mt++) {
            #pragma unroll
            for (int nt = 0; nt < 4; nt++) {
                int row = m0 + wm0 + mt*16 + g;
                int col = n0 + wn0 + nt*8 + qc*2;
                int which = col >> 10, lc = col & 1023;
                int bb = row / S_, rr = row % S_;
                __half2 lo = __floats2half2_rn(acc[mt][nt][0], acc[mt][nt][1]);
                __half2 hi = __floats2half2_rn(acc[mt][nt][2], acc[mt][nt][3]);
                if (which == 0) {
                    if (rr < T_) {
                        __half* dst = qp + ((size_t)(bb*T_ + rr)) * C_ + lc;
                        *(__half2*)(dst)        = lo;
                        *(__half2*)(dst + 8*C_) = hi;
                    }
                } else if (which == 1) {
                    __half* dst = kp + (size_t)row * C_ + lc;
                    *(__half2*)(dst)        = lo;
                    *(__half2*)(dst + 8*C_) = hi;
                } else {
                    __half* b0 = vp + ((size_t)(bb*C_ + lc)) * S_ + rr;
                    b0[0]      = __low2half(lo);
                    b0[S_]     = __high2half(lo);
                    b0[8]      = __low2half(hi);
                    b0[S_ + 8] = __high2half(hi);
                }
            }
        }
    }
}

// ---------------- gate: reads fp16 q --------------------------------------
#define GR 16
#define GATE_SMEM (GR * 256 * (int)sizeof(uint2))   // 32 KB

__global__ __launch_bounds__(256)
void gate_kernel(const __half* __restrict__ q, const float* __restrict__ gw,
                 const float* __restrict__ gb, float* __restrict__ gate) {
    extern __shared__ uint2 qs2[];
    const int bt0 = blockIdx.x * GR;
    const int tid = threadIdx.x;
    const int warp = tid >> 5, lane = tid & 31;

    const uint2* qsrc = (const uint2*)(q + (size_t)bt0 * C_);
    #pragma unroll
    for (int i = 0; i < GR; i++)
        qs2[i * 256 + tid] = qsrc[i * 256 + tid];
    __syncthreads();

    const int h0 = warp * 2, h1 = h0 + 1;
    const float4* g0p = (const float4*)(gw + h0 * C_);
    const float4* g1p = (const float4*)(gw + h1 * C_);

    float s0[GR] = {}, s1[GR] = {};
    #pragma unroll
    for (int i = 0; i < 8; i++) {
        float4 g0 = g0p[lane + i*32];
        float4 g1 = g1p[lane + i*32];
        #pragma unroll
        for (int r = 0; r < GR; r++) {
            uint2 qv = qs2[r * 256 + lane + i*32];
            float2 f01 = __half22float2(*reinterpret_cast<__half2*>(&qv.x));
            float2 f23 = __half22float2(*reinterpret_cast<__half2*>(&qv.y));
            s0[r] += f01.x*g0.x + f01.y*g0.y + f23.x*g0.z + f23.y*g0.w;
            s1[r] += f01.x*g1.x + f01.y*g1.y + f23.x*g1.z + f23.y*g1.w;
        }
    }
    float b0 = gb[h0], b1 = gb[h1];
    #pragma unroll
    for (int r = 0; r < GR; r++) {
        float v0 = s0[r], v1 = s1[r];
        #pragma unroll
        for (int o = 16; o; o >>= 1) {
            v0 += __shfl_xor_sync(~0u, v0, o);
            v1 += __shfl_xor_sync(~0u, v1, o);
        }
        if (lane == 0) {
            gate[(size_t)(bt0 + r) * H_ + h0] = 1.f / (1.f + __expf(-(v0 + b0)));
            gate[(size_t)(bt0 + r) * H_ + h1] = 1.f / (1.f + __expf(-(v1 + b1)));
        }
    }
}

// ================= fp16 attention v2: 1 sync/tile, dedicated P buffer ======
// Buffers: K0|K1|V0|V1|Q|P (each 64 rows x 144 B). 55296 B -> 3 CTA/SM.
// FILL(it+1) issued AFTER the top-of-loop barrier (which proves all warps
// finished PV(it-1)), so the parity buffer overwrite is safe with no end sync.
#define AROWB 144
#define ATILE_B (64 * AROWB)             // 9216 B
#define ATT_SMEM (6 * ATILE_B)           // 55296 B

__global__ __launch_bounds__(128, 3)
void attn_f16(const __half* __restrict__ q, const __half* __restrict__ k,
              const __half* __restrict__ vT, const float* __restrict__ gate,
              __half* __restrict__ outp) {
    extern __shared__ uint32_t s3[];
    const uint32_t sbase = (uint32_t)__cvta_generic_to_shared(s3);

    const int tid  = threadIdx.x;
    const int lane = tid & 31, warp = tid >> 5;
    const int g = lane >> 2, qc = lane & 3;
    const int wr0 = warp * 16;
    const int b  = blockIdx.y >> 4;
    const int h  = blockIdx.y & 15;
    const int t0 = (gridDim.x - 1 - blockIdx.x) * 64;

    const int a_off = (lane & 15) * AROWB + (lane >> 4) * 16;
    const int b_off = (((lane >> 4) & 1) * 8 + (lane & 7)) * AROWB
                      + ((lane >> 3) & 1) * 16;

    const int nMem   = (2*M_)/64;
    const int nChunk = t0/64 + 1;
    const int nTiles = nMem + nChunk;

    #define KBUF(IT) (sbase + (((IT) & 1)     ) * ATILE_B)
    #define VBUF(IT) (sbase + (2 + ((IT) & 1) ) * ATILE_B)
    #define QBUF     (sbase + 4 * ATILE_B)
    #define PBUF     (sbase + 5 * ATILE_B)
    #define S0OF(IT) (((IT) < nMem) ? (T_ + (IT)*64) : ((IT) - nMem)*64)

    // ---- stage Q ----
    {
        const __half* src_ = q + ((size_t)(b*T_ + t0)) * C_ + h*HD_;
        #pragma unroll
        for (int j = 0; j < 4; j++) {
            int u = tid + j * 128;
            int row = u >> 3, cw = u & 7;
            cp16(QBUF + row * AROWB + cw * 16, src_ + (size_t)row * C_ + cw * 8);
        }
        asm volatile("cp.async.commit_group;");
    }

    #define FILL_KV(IT)                                                       \
    do {                                                                      \
        int it_ = (IT);                                                       \
        if (it_ < nTiles) {                                                   \
            int s0_ = S0OF(it_);                                              \
            uint32_t kb_ = KBUF(it_);                                         \
            uint32_t vb_ = VBUF(it_);                                         \
            const __half* ks_ = k  + ((size_t)(b*S_ + s0_)) * C_ + h*HD_;     \
            const __half* vs_ = vT + ((size_t)(b*C_ + h*HD_)) * S_ + s0_;     \
            _Pragma("unroll")                                                 \
            for (int j = 0; j < 4; j++) {                                     \
                int u = tid + j * 128;                                        \
                int row = u >> 3, cw = u & 7;                                 \
                cp16(kb_ + row * AROWB + cw * 16, ks_ + (size_t)row * C_ + cw * 8); \
                cp16(vb_ + row * AROWB + cw * 16, vs_ + (size_t)row * S_ + cw * 8); \
            }                                                                 \
        }                                                                     \
        asm volatile("cp.async.commit_group;");                               \
    } while (0)

    FILL_KV(0);
    asm volatile("cp.async.wait_group 1;");   // Q staged
    __syncthreads();

    // ---- Q fragments (scale 1/8 folded) ----
    uint32_t qf[4][4];
    const __half2 sc8 = __half2half2(__float2half(0.125f));
    #pragma unroll
    for (int kk = 0; kk < 4; kk++) {
        ldsm_x4(qf[kk], QBUF + wr0 * AROWB + a_off + kk * 32);
        #pragma unroll
        for (int e = 0; e < 4; e++) {
            __half2 hm = __hmul2(*reinterpret_cast<__half2*>(&qf[kk][e]), sc8);
            qf[kk][e] = h2u(hm);
        }
    }

    const int rA = t0 + wr0 + g, rB = rA + 8;
    const float gA = gate[(size_t)(b*T_ + rA) * H_ + h];
    const float gB = gate[(size_t)(b*T_ + rB) * H_ + h];

    float acc[8][4] = {};
    float mA = -1e30f, mB = -1e30f, lA = 0.f, lB = 0.f;

    for (int it = 0; it < nTiles; it++) {
        const int  s0     = S0OF(it);
        const bool isDiag = (it == nTiles - 1);
        const uint32_t Kb = KBUF(it);
        const uint32_t Vb = VBUF(it);

        asm volatile("cp.async.wait_group 0;");   // FILL(it) complete
        __syncthreads();                          // visibility + PV(it-1) done
        FILL_KV(it + 1);                          // safe: overwrites it-1 bufs

        // ---- S = Q K^T ----
        float sf[8][4] = {};
        #pragma unroll
        for (int kk = 0; kk < 4; kk++) {
            #pragma unroll
            for (int f2 = 0; f2 < 4; f2++) {
                uint32_t r[4];
                ldsm_x4(r, Kb + f2 * 16 * AROWB + b_off + kk * 32);
                uint32_t b0[2] = {r[0], r[1]}, b1[2] = {r[2], r[3]};
                mma_f16(sf[2*f2],     qf[kk], b0);
                mma_f16(sf[2*f2 + 1], qf[kk], b1);
            }
        }

        // ---- mask + row max ----
        float tmA = -1e30f, tmB = -1e30f;
        #pragma unroll
        for (int f = 0; f < 8; f++) {
            if (isDiag) {
                int c0 = s0 + f*8 + 2*qc, c1 = c0 + 1;
                if (c0 > rA) sf[f][0] = -1e30f;
                if (c1 > rA) sf[f][1] = -1e30f;
                if (c0 > rB) sf[f][2] = -1e30f;
                if (c1 > rB) sf[f][3] = -1e30f;
            }
            tmA = fmaxf(tmA, fmaxf(sf[f][0], sf[f][1]));
            tmB = fmaxf(tmB, fmaxf(sf[f][2], sf[f][3]));
        }
        tmA = fmaxf(tmA, __shfl_xor_sync(~0u, tmA, 1));
        tmA = fmaxf(tmA, __shfl_xor_sync(~0u, tmA, 2));
        tmB = fmaxf(tmB, __shfl_xor_sync(~0u, tmB, 1));
        tmB = fmaxf(tmB, __shfl_xor_sync(~0u, tmB, 2));

        float mAn = fmaxf(mA, tmA), mBn = fmaxf(mB, tmB);
        float fA = __expf(mA - mAn), fB = __expf(mB - mBn);
        mA = mAn; mB = mBn;

        // ---- P = exp(S-m) -> P buffer (own warp rows), fp32 row sums ----
        __half* Ph = (__half*)((char*)s3 + 5 * ATILE_B);
        float sA = 0.f, sB = 0.f;
        #pragma unroll
        for (int f = 0; f < 8; f++) {
            float p0 = __expf(sf[f][0] - mA);
            float p1 = __expf(sf[f][1] - mA);
            float p2 = __expf(sf[f][2] - mB);
            float p3 = __expf(sf[f][3] - mB);
            sA += p0 + p1; sB += p2 + p3;
            *(__half2*)&Ph[(wr0 + g    )*72 + f*8 + 2*qc] = __floats2half2_rn(p0, p1);
            *(__half2*)&Ph[(wr0 + g + 8)*72 + f*8 + 2*qc] = __floats2half2_rn(p2, p3);
        }
        sA += __shfl_xor_sync(~0u, sA, 1); sA += __shfl_xor_sync(~0u, sA, 2);
        sB += __shfl_xor_sync(~0u, sB, 1); sB += __shfl_xor_sync(~0u, sB, 2);
        lA = lA * fA + sA;
        lB = lB * fB + sB;

        // ---- rescale accumulator ----
        #pragma unroll
        for (int f = 0; f < 8; f++) {
            acc[f][0] *= fA; acc[f][1] *= fA; acc[f][2] *= fB; acc[f][3] *= fB;
        }
        __syncwarp();

        // ---- P fragments (own rows: no cross-warp hazard) ----
        uint32_t pf[4][4];
        #pragma unroll
        for (int kk = 0; kk < 4; kk++)
            ldsm_x4(pf[kk], PBUF + wr0 * AROWB + a_off + kk * 32);

        // ---- O += P V ----
        #pragma unroll
        for (int kk = 0; kk < 4; kk++) {
            #pragma unroll
            for (int f2 = 0; f2 < 4; f2++) {
                uint32_t r[4];
                ldsm_x4(r, Vb + f2 * 16 * AROWB + b_off + kk * 32);
                uint32_t b0[2] = {r[0], r[1]}, b1[2] = {r[2], r[3]};
                mma_f16(acc[2*f2],     pf[kk], b0);
                mma_f16(acc[2*f2 + 1], pf[kk], b1);
            }
        }

        if (it == nMem - 1) {
            #pragma unroll
            for (int f = 0; f < 8; f++) {
                acc[f][0] *= gA; acc[f][1] *= gA;
                acc[f][2] *= gB; acc[f][3] *= gB;
            }
        }
    }
    #undef FILL_KV
    #undef KBUF
    #undef VBUF
    #undef QBUF
    #undef PBUF
    #undef S0OF

    // ---- epilogue: fp16 output ----
    float invA = 1.f / lA, invB = 1.f / lB;
    #pragma unroll
    for (int f = 0; f < 8; f++) {
        int col = h*HD_ + f*8 + 2*qc;
        __half2 o0 = __floats2half2_rn(acc[f][0] * invA, acc[f][1] * invA);
        __half2 o1 = __floats2half2_rn(acc[f][2] * invB, acc[f][3] * invB);
        *(__half2*)&outp[(size_t)(b*T_ + rA) * C_ + col] = o0;
        *(__half2*)&outp[(size_t)(b*T_ + rB) * C_ + col] = o1;
    }
}

// ---------------- canon conv (fp16 in, fp16 out) ----------------------------
__global__ __launch_bounds__(256)
void conv_kernel(const __half* __restrict__ y, const float* __restrict__ cw,
                 const float4* __restrict__ cb4, uint2* __restrict__ z) {
    const int C4 = C_/4;
    int idx = blockIdx.x * 256 + threadIdx.x;
    if (idx >= B_*T_*C4) return;
    int c4 = idx & (C4 - 1);
    int t  = (idx / C4) % T_;
    int b  = idx / (C4 * T_);

    const float4* cwr = (const float4*)cw;
    float4 w0 = cwr[c4*4 + 0];
    float4 w1 = cwr[c4*4 + 1];
    float4 w2 = cwr[c4*4 + 2];
    float4 w3 = cwr[c4*4 + 3];
    float wa[4][4] = {{w0.x,w0.y,w0.z,w0.w}, {w1.x,w1.y,w1.z,w1.w},
                      {w2.x,w2.y,w2.z,w2.w}, {w3.x,w3.y,w3.z,w3.w}};

    const uint2* y2 = (const uint2*)y;
    uint2 yc = y2[idx];
    float2 a01 = __half22float2(*reinterpret_cast<__half2*>(&yc.x));
    float2 a23 = __half22float2(*reinterpret_cast<__half2*>(&yc.y));
    float4 cbv = cb4[c4];
    float ax = a01.x + cbv.x, ay = a01.y + cbv.y;
    float az = a23.x + cbv.z, aw = a23.y + cbv.w;

    #pragma unroll
    for (int j = 0; j < KC_; j++) {
        int tt = t - (KC_ - 1) + j;
        if (tt >= 0) {
            uint2 yv = y2[((size_t)(b*T_ + tt)) * C4 + c4];
            float2 f01 = __half22float2(*reinterpret_cast<__half2*>(&yv.x));
            float2 f23 = __half22float2(*reinterpret_cast<__half2*>(&yv.y));
            ax += f01.x * wa[0][j];
            ay += f01.y * wa[1][j];
            az += f23.x * wa[2][j];
            aw += f23.y * wa[3][j];
        }
    }
    z[idx] = make_uint2(h2u(__floats2half2_rn(ax, ay)),
                        h2u(__floats2half2_rn(az, aw)));
}

// ---------------- orchestration -------------------------------------------
extern "C" void kernel_launch(void* const* d_in, const int* in_sizes, int n_in,
                              void* d_out, int out_size) {
    const float* x   = (const float*)d_in[0];
    const float* fwd = (const float*)d_in[1];
    const float* rev = (const float*)d_in[2];
    const float* Wq  = (const float*)d_in[3];
    const float* Wk  = (const float*)d_in[4];
    const float* Wv  = (const float*)d_in[5];
    const float* Wo  = (const float*)d_in[6];
    const float* gw  = (const float*)d_in[7];
    const float* gb  = (const float*)d_in[8];
    const float* cw  = (const float*)d_in[9];
    const float* cb  = (const float*)d_in[10];
    float* out = (float*)d_out;

    __half *xc, *wtf, *z16, *qb, *kb, *vt, *at;
    float *gt;
    cudaGetSymbolAddress((void**)&xc,  g_xcat);
    cudaGetSymbolAddress((void**)&wtf, g_wtf);
    cudaGetSymbolAddress((void**)&z16, g_z16);
    cudaGetSymbolAddress((void**)&qb,  g_q16);
    cudaGetSymbolAddress((void**)&kb,  g_k16);
    cudaGetSymbolAddress((void**)&vt,  g_vt16);
    cudaGetSymbolAddress((void**)&gt,  g_gate);
    cudaGetSymbolAddress((void**)&at,  g_attn16);

    cudaFuncSetAttribute(gemm_f16,
                         cudaFuncAttributeMaxDynamicSharedMemorySize, GEMM_SMEM);
    cudaFuncSetAttribute(attn_f16,
                         cudaFuncAttributeMaxDynamicSharedMemorySize, ATT_SMEM);
    cudaFuncSetAttribute(gate_kernel,
                         cudaFuncAttributeMaxDynamicSharedMemorySize, GATE_SMEM);

    // 1. pre-convert inputs to fp16
    {
        int n4 = B_*S_*(C_/4);
        pack_kernel<<<(n4 + 255)/256, 256>>>((const float4*)x, (const float4*)fwd,
                                             (const float4*)rev, (uint2*)xc);
    }
    wcvt_kernel<<<(4*C_*C_/4 + 255)/256, 256>>>((const float4*)Wq, (const float4*)Wk,
                                                (const float4*)Wv, (const float4*)Wo,
                                                (uint2*)wtf);

    // 2. fused QKV projection (fp16 tensor cores; v written transposed)
    gemm_f16<<<dim3(3*C_/128, (B_*S_)/128), 256, GEMM_SMEM>>>(
        xc, wtf, nullptr, qb, kb, vt, 3*C_, C_, 1);

    // 3. gate
    gate_kernel<<<(B_*T_)/GR, 256, GATE_SMEM>>>(qb, gw, gb, gt);
    // 4. attention (fp16 out)
    attn_f16<<<dim3(T_/64, B_*H_), 128, ATT_SMEM>>>(qb, kb, vt, gt, at);
    // 5. canon conv (fp16 in/out)
    conv_kernel<<<(B_*T_*(C_/4) + 255)/256, 256>>>(at, cw,
                                                   (const float4*)cb, (uint2*)z16);
    // 6. output projection into d_out (fp32 out)
    gemm_f16<<<dim3(C_/128, (B_*T_)/128), 256, GEMM_SMEM>>>(
        z16, wtf + 3*C_*C_, out, nullptr, nullptr, nullptr, C_, C_, 0);
}

// round 14
// speedup vs baseline: 2.2416x; 1.0311x over previous
#include <cuda_runtime.h>
#include <cuda_fp16.h>
#include <math.h>
#include <stdint.h>

#define B_ 2
#define T_ 2048
#define C_ 1024
#define H_ 16
#define HD_ 64
#define M_ 256
#define S_ (T_ + 2*M_)   /* 2560 */
#define KC_ 4

// ---------------- scratch (static device globals; no runtime alloc) -------
__device__ __half g_xcat[B_*S_*C_];   // concat(x,fwd,rev) fp16
__device__ __half g_wtf [4*C_*C_];    // Wq|Wk|Wv|Wo fp16
__device__ __half g_q16 [B_*T_*C_];   // q fp16
__device__ __half g_k16 [B_*S_*C_];   // k fp16
__device__ __half g_vt16[B_*C_*S_];   // V^T fp16: [b][c][s]
__device__ float  g_gate[B_*T_*H_];
__device__ __half g_attn16[B_*T_*C_]; // attention output fp16
__device__ __half g_z16 [B_*T_*C_];   // conv output fp16

// ================= helpers =================================================
__device__ __forceinline__ uint32_t h2u(__half2 h) {
    return *reinterpret_cast<uint32_t*>(&h);
}
__device__ __forceinline__ void mma_f16(float* d, const uint32_t* a,
                                        const uint32_t* b) {
    asm volatile(
        "mma.sync.aligned.m16n8k16.row.col.f32.f16.f16.f32 "
        "{%0,%1,%2,%3}, {%4,%5,%6,%7}, {%8,%9}, {%0,%1,%2,%3};"
        : "+f"(d[0]), "+f"(d[1]), "+f"(d[2]), "+f"(d[3])
        : "r"(a[0]), "r"(a[1]), "r"(a[2]), "r"(a[3]),
          "r"(b[0]), "r"(b[1]));
}
__device__ __forceinline__ void ldsm_x4(uint32_t* r, uint32_t addr) {
    asm volatile("ldmatrix.sync.aligned.m8n8.x4.shared.b16 {%0,%1,%2,%3}, [%4];"
        : "=r"(r[0]), "=r"(r[1]), "=r"(r[2]), "=r"(r[3]) : "r"(addr));
}
__device__ __forceinline__ void cp16(uint32_t dst, const void* src) {
    asm volatile("cp.async.cg.shared.global [%0], [%1], 16;" :: "r"(dst), "l"(src));
}

// ---------------- prep: pack xcat + convert weights (fused) ----------------
__global__ void prep_kernel(const float4* __restrict__ x,
                            const float4* __restrict__ fwd,
                            const float4* __restrict__ rev,
                            const float4* __restrict__ w0, const float4* __restrict__ w1,
                            const float4* __restrict__ w2, const float4* __restrict__ w3,
                            uint2* __restrict__ xc, uint2* __restrict__ wdst) {
    const int C4 = C_/4;
    const int NX = B_*S_*C4;
    const int NW = C_*C_/4;
    int idx = blockIdx.x * 256 + threadIdx.x;
    if (idx < NX) {
        int c4 = idx % C4;
        int r  = (idx / C4) % S_;
        int b  = idx / (C4 * S_);
        float4 val;
        if (r < T_)            val = x  [(b*T_ + r)          * C4 + c4];
        else if (r < T_ + M_)  val = fwd[(b*M_ + (r - T_))   * C4 + c4];
        else                   val = rev[(b*M_ + (r - T_-M_))* C4 + c4];
        xc[idx] = make_uint2(h2u(__floats2half2_rn(val.x, val.y)),
                             h2u(__floats2half2_rn(val.z, val.w)));
    } else {
        int widx = idx - NX;
        if (widx >= 4*NW) return;
        int m = widx / NW, r = widx % NW;
        const float4* s = (m == 0) ? w0 : (m == 1) ? w1 : (m == 2) ? w2 : w3;
        float4 v = s[r];
        wdst[widx] = make_uint2(h2u(__floats2half2_rn(v.x, v.y)),
                                h2u(__floats2half2_rn(v.z, v.w)));
    }
}

// ================= FP16 GEMM: BK=64, cp.async 3-stage + ldmatrix ===========
#define GBK 64
#define GROWB 144
#define GOPB (128 * GROWB)               // 18432 B per operand per stage
#define GSTAGEB (2 * GOPB)
#define GEMM_SMEM (3 * GSTAGEB)          // 110592 B -> 2 CTA/SM

__global__ __launch_bounds__(256)
void gemm_f16(const __half* __restrict__ A, const __half* __restrict__ Bm,
              float* __restrict__ Cm, __half* __restrict__ qp,
              __half* __restrict__ kp, __half* __restrict__ vp,
              int Nr, int Kr, int mode) {
    if (mode == 1 && blockIdx.x < 8 && (blockIdx.y % 20) >= 16) return;

    extern __shared__ uint32_t smg[];
    const uint32_t sbase = (uint32_t)__cvta_generic_to_shared(smg);

    const int tid  = threadIdx.x;
    const int lane = tid & 31, warp = tid >> 5;
    const int g = lane >> 2, qc = lane & 3;
    const int wm0 = (warp >> 2) * 64;
    const int wn0 = (warp & 3) * 32;
    const int m0 = blockIdx.y * 128, n0 = blockIdx.x * 128;
    const int nk = Kr / GBK;

    const int a_off = (lane & 15) * GROWB + (lane >> 4) * 16;
    const int b_off = (((lane >> 4) & 1) * 8 + (lane & 7)) * GROWB
                      + ((lane >> 3) & 1) * 16;

    float acc[4][4][4] = {};

    #define PREFETCH(KT)                                                       \
    do {                                                                       \
        int kt_ = (KT);                                                        \
        if (kt_ < nk) {                                                        \
            uint32_t da = sbase + (kt_ % 3) * GSTAGEB;                         \
            uint32_t db = da + GOPB;                                           \
            const __half* Ag_ = A  + (size_t)m0 * Kr + kt_ * GBK;              \
            const __half* Bg_ = Bm + (size_t)n0 * Kr + kt_ * GBK;              \
            _Pragma("unroll")                                                  \
            for (int j = 0; j < 4; j++) {                                      \
                int u = tid + j * 256;                                         \
                int row = u >> 3, q16 = u & 7;                                 \
                cp16(da + row * GROWB + q16 * 16, Ag_ + (size_t)row * Kr + q16 * 8); \
                cp16(db + row * GROWB + q16 * 16, Bg_ + (size_t)row * Kr + q16 * 8); \
            }                                                                  \
        }                                                                      \
        asm volatile("cp.async.commit_group;");                                \
    } while (0)

    PREFETCH(0);
    PREFETCH(1);

    for (int kt = 0; kt < nk; kt++) {
        asm volatile("cp.async.wait_group 1;");
        __syncthreads();
        PREFETCH(kt + 2);

        const uint32_t aAddr = sbase + (kt % 3) * GSTAGEB + wm0 * GROWB + a_off;
        const uint32_t bAddr = sbase + (kt % 3) * GSTAGEB + GOPB + wn0 * GROWB + b_off;

        #pragma unroll
        for (int kp_ = 0; kp_ < 4; kp_++) {
            uint32_t bf[4][2];
            {
                uint32_t r[4];
                ldsm_x4(r, bAddr + kp_ * 32);
                bf[0][0] = r[0]; bf[0][1] = r[1]; bf[1][0] = r[2]; bf[1][1] = r[3];
            }
            {
                uint32_t r[4];
                ldsm_x4(r, bAddr + 16 * GROWB + kp_ * 32);
                bf[2][0] = r[0]; bf[2][1] = r[1]; bf[3][0] = r[2]; bf[3][1] = r[3];
            }
            uint32_t af[4][4];
            #pragma unroll
            for (int mt = 0; mt < 4; mt++)
                ldsm_x4(af[mt], aAddr + mt * 16 * GROWB + kp_ * 32);
            #pragma unroll
            for (int mt = 0; mt < 4; mt++)
                #pragma unroll
                for (int nt = 0; nt < 4; nt++)
                    mma_f16(acc[mt][nt], af[mt], bf[nt]);
        }
    }
    #undef PREFETCH

    if (mode == 0) {
        #pragma unroll
        for (int mt = 0; mt < 4; mt++) {
            #pragma unroll
            for (int nt = 0; nt < 4; nt++) {
                int row = m0 + wm0 + mt*16 + g;
                int col = n0 + wn0 + nt*8 + qc*2;
                float2 lo = make_float2(acc[mt][nt][0], acc[mt][nt][1]);
                float2 hi = make_float2(acc[mt][nt][2], acc[mt][nt][3]);
                *(float2*)(Cm + (size_t)row     * Nr + col) = lo;
                *(float2*)(Cm + (size_t)(row+8) * Nr + col) = hi;
            }
        }
    } else {
        #pragma unroll
        for (int mt = 0; mt < 4; mt++) {
            #pragma unroll
            for (int nt = 0; nt < 4; nt++) {
                int row = m0 + wm0 + mt*16 + g;
                int col = n0 + wn0 + nt*8 + qc*2;
                int which = col >> 10, lc = col & 1023;
                int bb = row / S_, rr = row % S_;
                __half2 lo = __floats2half2_rn(acc[mt][nt][0], acc[mt][nt][1]);
                __half2 hi = __floats2half2_rn(acc[mt][nt][2], acc[mt][nt][3]);
                if (which == 0) {
                    if (rr < T_) {
                        __half* dst = qp + ((size_t)(bb*T_ + rr)) * C_ + lc;
                        *(__half2*)(dst)        = lo;
                        *(__half2*)(dst + 8*C_) = hi;
                    }
                } else if (which == 1) {
                    __half* dst = kp + (size_t)row * C_ + lc;
                    *(__half2*)(dst)        = lo;
                    *(__half2*)(dst + 8*C_) = hi;
                } else {
                    __half* b0 = vp + ((size_t)(bb*C_ + lc)) * S_ + rr;
                    b0[0]      = __low2half(lo);
                    b0[S_]     = __high2half(lo);
                    b0[8]      = __low2half(hi);
                    b0[S_ + 8] = __high2half(hi);
                }
            }
        }
    }
}

// ---------------- gate: GR=8 (512 CTAs), reads fp16 q ----------------------
#define GR 8
#define GATE_SMEM (GR * 256 * (int)sizeof(uint2))   // 16 KB

__global__ __launch_bounds__(256)
void gate_kernel(const __half* __restrict__ q, const float* __restrict__ gw,
                 const float* __restrict__ gb, float* __restrict__ gate) {
    extern __shared__ uint2 qs2[];
    const int bt0 = blockIdx.x * GR;
    const int tid = threadIdx.x;
    const int warp = tid >> 5, lane = tid & 31;

    const uint2* qsrc = (const uint2*)(q + (size_t)bt0 * C_);
    #pragma unroll
    for (int i = 0; i < GR; i++)
        qs2[i * 256 + tid] = qsrc[i * 256 + tid];
    __syncthreads();

    const int h0 = warp * 2, h1 = h0 + 1;
    const float4* g0p = (const float4*)(gw + h0 * C_);
    const float4* g1p = (const float4*)(gw + h1 * C_);

    float s0[GR] = {}, s1[GR] = {};
    #pragma unroll
    for (int i = 0; i < 8; i++) {
        float4 g0 = g0p[lane + i*32];
        float4 g1 = g1p[lane + i*32];
        #pragma unroll
        for (int r = 0; r < GR; r++) {
            uint2 qv = qs2[r * 256 + lane + i*32];
            float2 f01 = __half22float2(*reinterpret_cast<__half2*>(&qv.x));
            float2 f23 = __half22float2(*reinterpret_cast<__half2*>(&qv.y));
            s0[r] += f01.x*g0.x + f01.y*g0.y + f23.x*g0.z + f23.y*g0.w;
            s1[r] += f01.x*g1.x + f01.y*g1.y + f23.x*g1.z + f23.y*g1.w;
        }
    }
    float b0 = gb[h0], b1 = gb[h1];
    #pragma unroll
    for (int r = 0; r < GR; r++) {
        float v0 = s0[r], v1 = s1[r];
        #pragma unroll
        for (int o = 16; o; o >>= 1) {
            v0 += __shfl_xor_sync(~0u, v0, o);
            v1 += __shfl_xor_sync(~0u, v1, o);
        }
        if (lane == 0) {
            gate[(size_t)(bt0 + r) * H_ + h0] = 1.f / (1.f + __expf(-(v0 + b0)));
            gate[(size_t)(bt0 + r) * H_ + h1] = 1.f / (1.f + __expf(-(v1 + b1)));
        }
    }
}

// ================= fp16 attention (unchanged from R13) =====================
#define AROWB 144
#define ATILE_B (64 * AROWB)
#define ATT_SMEM (6 * ATILE_B)           // 55296 B -> 3 CTA/SM

__global__ __launch_bounds__(128, 3)
void attn_f16(const __half* __restrict__ q, const __half* __restrict__ k,
              const __half* __restrict__ vT, const float* __restrict__ gate,
              __half* __restrict__ outp) {
    extern __shared__ uint32_t s3[];
    const uint32_t sbase = (uint32_t)__cvta_generic_to_shared(s3);

    const int tid  = threadIdx.x;
    const int lane = tid & 31, warp = tid >> 5;
    const int g = lane >> 2, qc = lane & 3;
    const int wr0 = warp * 16;
    const int b  = blockIdx.y >> 4;
    const int h  = blockIdx.y & 15;
    const int t0 = (gridDim.x - 1 - blockIdx.x) * 64;

    const int a_off = (lane & 15) * AROWB + (lane >> 4) * 16;
    const int b_off = (((lane >> 4) & 1) * 8 + (lane & 7)) * AROWB
                      + ((lane >> 3) & 1) * 16;

    const int nMem   = (2*M_)/64;
    const int nChunk = t0/64 + 1;
    const int nTiles = nMem + nChunk;

    #define KBUF(IT) (sbase + (((IT) & 1)     ) * ATILE_B)
    #define VBUF(IT) (sbase + (2 + ((IT) & 1) ) * ATILE_B)
    #define QBUF     (sbase + 4 * ATILE_B)
    #define PBUF     (sbase + 5 * ATILE_B)
    #define S0OF(IT) (((IT) < nMem) ? (T_ + (IT)*64) : ((IT) - nMem)*64)

    {
        const __half* src_ = q + ((size_t)(b*T_ + t0)) * C_ + h*HD_;
        #pragma unroll
        for (int j = 0; j < 4; j++) {
            int u = tid + j * 128;
            int row = u >> 3, cw = u & 7;
            cp16(QBUF + row * AROWB + cw * 16, src_ + (size_t)row * C_ + cw * 8);
        }
        asm volatile("cp.async.commit_group;");
    }

    #define FILL_KV(IT)                                                       \
    do {                                                                      \
        int it_ = (IT);                                                       \
        if (it_ < nTiles) {                                                   \
            int s0_ = S0OF(it_);                                              \
            uint32_t kb_ = KBUF(it_);                                         \
            uint32_t vb_ = VBUF(it_);                                         \
            const __half* ks_ = k  + ((size_t)(b*S_ + s0_)) * C_ + h*HD_;     \
            const __half* vs_ = vT + ((size_t)(b*C_ + h*HD_)) * S_ + s0_;     \
            _Pragma("unroll")                                                 \
            for (int j = 0; j < 4; j++) {                                     \
                int u = tid + j * 128;                                        \
                int row = u >> 3, cw = u & 7;                                 \
                cp16(kb_ + row * AROWB + cw * 16, ks_ + (size_t)row * C_ + cw * 8); \
                cp16(vb_ + row * AROWB + cw * 16, vs_ + (size_t)row * S_ + cw * 8); \
            }                                                                 \
        }                                                                     \
        asm volatile("cp.async.commit_group;");                               \
    } while (0)

    FILL_KV(0);
    asm volatile("cp.async.wait_group 1;");
    __syncthreads();

    uint32_t qf[4][4];
    const __half2 sc8 = __half2half2(__float2half(0.125f));
    #pragma unroll
    for (int kk = 0; kk < 4; kk++) {
        ldsm_x4(qf[kk], QBUF + wr0 * AROWB + a_off + kk * 32);
        #pragma unroll
        for (int e = 0; e < 4; e++) {
            __half2 hm = __hmul2(*reinterpret_cast<__half2*>(&qf[kk][e]), sc8);
            qf[kk][e] = h2u(hm);
        }
    }

    const int rA = t0 + wr0 + g, rB = rA + 8;
    const float gA = gate[(size_t)(b*T_ + rA) * H_ + h];
    const float gB = gate[(size_t)(b*T_ + rB) * H_ + h];

    float acc[8][4] = {};
    float mA = -1e30f, mB = -1e30f, lA = 0.f, lB = 0.f;

    for (int it = 0; it < nTiles; it++) {
        const int  s0     = S0OF(it);
        const bool isDiag = (it == nTiles - 1);
        const uint32_t Kb = KBUF(it);
        const uint32_t Vb = VBUF(it);

        asm volatile("cp.async.wait_group 0;");
        __syncthreads();
        FILL_KV(it + 1);

        float sf[8][4] = {};
        #pragma unroll
        for (int kk = 0; kk < 4; kk++) {
            #pragma unroll
            for (int f2 = 0; f2 < 4; f2++) {
                uint32_t r[4];
                ldsm_x4(r, Kb + f2 * 16 * AROWB + b_off + kk * 32);
                uint32_t b0[2] = {r[0], r[1]}, b1[2] = {r[2], r[3]};
                mma_f16(sf[2*f2],     qf[kk], b0);
                mma_f16(sf[2*f2 + 1], qf[kk], b1);
            }
        }

        float tmA = -1e30f, tmB = -1e30f;
        #pragma unroll
        for (int f = 0; f < 8; f++) {
            if (isDiag) {
                int c0 = s0 + f*8 + 2*qc, c1 = c0 + 1;
                if (c0 > rA) sf[f][0] = -1e30f;
                if (c1 > rA) sf[f][1] = -1e30f;
                if (c0 > rB) sf[f][2] = -1e30f;
                if (c1 > rB) sf[f][3] = -1e30f;
            }
            tmA = fmaxf(tmA, fmaxf(sf[f][0], sf[f][1]));
            tmB = fmaxf(tmB, fmaxf(sf[f][2], sf[f][3]));
        }
        tmA = fmaxf(tmA, __shfl_xor_sync(~0u, tmA, 1));
        tmA = fmaxf(tmA, __shfl_xor_sync(~0u, tmA, 2));
        tmB = fmaxf(tmB, __shfl_xor_sync(~0u, tmB, 1));
        tmB = fmaxf(tmB, __shfl_xor_sync(~0u, tmB, 2));

        float mAn = fmaxf(mA, tmA), mBn = fmaxf(mB, tmB);
        float fA = __expf(mA - mAn), fB = __expf(mB - mBn);
        mA = mAn; mB = mBn;

        __half* Ph = (__half*)((char*)s3 + 5 * ATILE_B);
        float sA = 0.f, sB = 0.f;
        #pragma unroll
        for (int f = 0; f < 8; f++) {
            float p0 = __expf(sf[f][0] - mA);
            float p1 = __expf(sf[f][1] - mA);
            float p2 = __expf(sf[f][2] - mB);
            float p3 = __expf(sf[f][3] - mB);
            sA += p0 + p1; sB += p2 + p3;
            *(__half2*)&Ph[(wr0 + g    )*72 + f*8 + 2*qc] = __floats2half2_rn(p0, p1);
            *(__half2*)&Ph[(wr0 + g + 8)*72 + f*8 + 2*qc] = __floats2half2_rn(p2, p3);
        }
        sA += __shfl_xor_sync(~0u, sA, 1); sA += __shfl_xor_sync(~0u, sA, 2);
        sB += __shfl_xor_sync(~0u, sB, 1); sB += __shfl_xor_sync(~0u, sB, 2);
        lA = lA * fA + sA;
        lB = lB * fB + sB;

        #pragma unroll
        for (int f = 0; f < 8; f++) {
            acc[f][0] *= fA; acc[f][1] *= fA; acc[f][2] *= fB; acc[f][3] *= fB;
        }
        __syncwarp();

        uint32_t pf[4][4];
        #pragma unroll
        for (int kk = 0; kk < 4; kk++)
            ldsm_x4(pf[kk], PBUF + wr0 * AROWB + a_off + kk * 32);

        #pragma unroll
        for (int kk = 0; kk < 4; kk++) {
            #pragma unroll
            for (int f2 = 0; f2 < 4; f2++) {
                uint32_t r[4];
                ldsm_x4(r, Vb + f2 * 16 * AROWB + b_off + kk * 32);
                uint32_t b0[2] = {r[0], r[1]}, b1[2] = {r[2], r[3]};
                mma_f16(acc[2*f2],     pf[kk], b0);
                mma_f16(acc[2*f2 + 1], pf[kk], b1);
            }
        }

        if (it == nMem - 1) {
            #pragma unroll
            for (int f = 0; f < 8; f++) {
                acc[f][0] *= gA; acc[f][1] *= gA;
                acc[f][2] *= gB; acc[f][3] *= gB;
            }
        }
    }
    #undef FILL_KV
    #undef KBUF
    #undef VBUF
    #undef QBUF
    #undef PBUF
    #undef S0OF

    float invA = 1.f / lA, invB = 1.f / lB;
    #pragma unroll
    for (int f = 0; f < 8; f++) {
        int col = h*HD_ + f*8 + 2*qc;
        __half2 o0 = __floats2half2_rn(acc[f][0] * invA, acc[f][1] * invA);
        __half2 o1 = __floats2half2_rn(acc[f][2] * invB, acc[f][3] * invB);
        *(__half2*)&outp[(size_t)(b*T_ + rA) * C_ + col] = o0;
        *(__half2*)&outp[(size_t)(b*T_ + rB) * C_ + col] = o1;
    }
}

// ---------------- canon conv (fp16 in, fp16 out) ----------------------------
__global__ __launch_bounds__(256)
void conv_kernel(const __half* __restrict__ y, const float* __restrict__ cw,
                 const float4* __restrict__ cb4, uint2* __restrict__ z) {
    const int C4 = C_/4;
    int idx = blockIdx.x * 256 + threadIdx.x;
    if (idx >= B_*T_*C4) return;
    int c4 = idx & (C4 - 1);
    int t  = (idx / C4) % T_;
    int b  = idx / (C4 * T_);

    const float4* cwr = (const float4*)cw;
    float4 w0 = cwr[c4*4 + 0];
    float4 w1 = cwr[c4*4 + 1];
    float4 w2 = cwr[c4*4 + 2];
    float4 w3 = cwr[c4*4 + 3];
    float wa[4][4] = {{w0.x,w0.y,w0.z,w0.w}, {w1.x,w1.y,w1.z,w1.w},
                      {w2.x,w2.y,w2.z,w2.w}, {w3.x,w3.y,w3.z,w3.w}};

    const uint2* y2 = (const uint2*)y;
    uint2 yc = y2[idx];
    float2 a01 = __half22float2(*reinterpret_cast<__half2*>(&yc.x));
    float2 a23 = __half22float2(*reinterpret_cast<__half2*>(&yc.y));
    float4 cbv = cb4[c4];
    float ax = a01.x + cbv.x, ay = a01.y + cbv.y;
    float az = a23.x + cbv.z, aw = a23.y + cbv.w;

    #pragma unroll
    for (int j = 0; j < KC_; j++) {
        int tt = t - (KC_ - 1) + j;
        if (tt >= 0) {
            uint2 yv = y2[((size_t)(b*T_ + tt)) * C4 + c4];
            float2 f01 = __half22float2(*reinterpret_cast<__half2*>(&yv.x));
            float2 f23 = __half22float2(*reinterpret_cast<__half2*>(&yv.y));
            ax += f01.x * wa[0][j];
            ay += f01.y * wa[1][j];
            az += f23.x * wa[2][j];
            aw += f23.y * wa[3][j];
        }
    }
    z[idx] = make_uint2(h2u(__floats2half2_rn(ax, ay)),
                        h2u(__floats2half2_rn(az, aw)));
}

// ---------------- orchestration -------------------------------------------
extern "C" void kernel_launch(void* const* d_in, const int* in_sizes, int n_in,
                              void* d_out, int out_size) {
    const float* x   = (const float*)d_in[0];
    const float* fwd = (const float*)d_in[1];
    const float* rev = (const float*)d_in[2];
    const float* Wq  = (const float*)d_in[3];
    const float* Wk  = (const float*)d_in[4];
    const float* Wv  = (const float*)d_in[5];
    const float* Wo  = (const float*)d_in[6];
    const float* gw  = (const float*)d_in[7];
    const float* gb  = (const float*)d_in[8];
    const float* cw  = (const float*)d_in[9];
    const float* cb  = (const float*)d_in[10];
    float* out = (float*)d_out;

    __half *xc, *wtf, *z16, *qb, *kb, *vt, *at;
    float *gt;
    cudaGetSymbolAddress((void**)&xc,  g_xcat);
    cudaGetSymbolAddress((void**)&wtf, g_wtf);
    cudaGetSymbolAddress((void**)&z16, g_z16);
    cudaGetSymbolAddress((void**)&qb,  g_q16);
    cudaGetSymbolAddress((void**)&kb,  g_k16);
    cudaGetSymbolAddress((void**)&vt,  g_vt16);
    cudaGetSymbolAddress((void**)&gt,  g_gate);
    cudaGetSymbolAddress((void**)&at,  g_attn16);

    cudaFuncSetAttribute(gemm_f16,
                         cudaFuncAttributeMaxDynamicSharedMemorySize, GEMM_SMEM);
    cudaFuncSetAttribute(attn_f16,
                         cudaFuncAttributeMaxDynamicSharedMemorySize, ATT_SMEM);
    cudaFuncSetAttribute(gate_kernel,
                         cudaFuncAttributeMaxDynamicSharedMemorySize, GATE_SMEM);

    // 1. fused pre-convert (xcat pack + all weights)
    {
        int ntot = B_*S_*(C_/4) + 4*C_*C_/4;
        prep_kernel<<<(ntot + 255)/256, 256>>>(
            (const float4*)x, (const float4*)fwd, (const float4*)rev,
            (const float4*)Wq, (const float4*)Wk, (const float4*)Wv,
            (const float4*)Wo, (uint2*)xc, (uint2*)wtf);
    }

    // 2. fused QKV projection (fp16 tensor cores; v written transposed)
    gemm_f16<<<dim3(3*C_/128, (B_*S_)/128), 256, GEMM_SMEM>>>(
        xc, wtf, nullptr, qb, kb, vt, 3*C_, C_, 1);

    // 3. gate
    gate_kernel<<<(B_*T_)/GR, 256, GATE_SMEM>>>(qb, gw, gb, gt);
    // 4. attention (fp16 out)
    attn_f16<<<dim3(T_/64, B_*H_), 128, ATT_SMEM>>>(qb, kb, vt, gt, at);
    // 5. canon conv (fp16 in/out)
    conv_kernel<<<(B_*T_*(C_/4) + 255)/256, 256>>>(at, cw,
                                                   (const float4*)cb, (uint2*)z16);
    // 6. output projection into d_out (fp32 out)
    gemm_f16<<<dim3(C_/128, (B_*T_)/128), 256, GEMM_SMEM>>>(
        z16, wtf + 3*C_*C_, out, nullptr, nullptr, nullptr, C_, C_, 0);
}

// round 15
// speedup vs baseline: 2.3956x; 1.0687x over previous
#include <cuda_runtime.h>
#include <cuda_fp16.h>
#include <math.h>
#include <stdint.h>

#define B_ 2
#define T_ 2048
#define C_ 1024
#define H_ 16
#define HD_ 64
#define M_ 256
#define S_ (T_ + 2*M_)   /* 2560 */
#define KC_ 4

// ---------------- scratch (static device globals; no runtime alloc) -------
__device__ __half g_xcat[B_*S_*C_];   // concat(x,fwd,rev) fp16
__device__ __half g_wtf [4*C_*C_];    // Wq|Wk|Wv|Wo fp16
__device__ __half g_q16 [B_*T_*C_];   // q fp16
__device__ __half g_k16 [B_*S_*C_];   // k fp16
__device__ __half g_vt16[B_*C_*S_];   // V^T fp16: [b][c][s]
__device__ float  g_gate[B_*T_*H_];
__device__ __half g_attn16[B_*T_*C_]; // attention output fp16
__device__ __half g_z16 [B_*T_*C_];   // conv output fp16
__device__ int    g_work;             // persistent-attention work counter

#define NITEMS ((T_/64) * B_ * H_)    // 1024 work items

// ================= helpers =================================================
__device__ __forceinline__ uint32_t h2u(__half2 h) {
    return *reinterpret_cast<uint32_t*>(&h);
}
__device__ __forceinline__ void mma_f16(float* d, const uint32_t* a,
                                        const uint32_t* b) {
    asm volatile(
        "mma.sync.aligned.m16n8k16.row.col.f32.f16.f16.f32 "
        "{%0,%1,%2,%3}, {%4,%5,%6,%7}, {%8,%9}, {%0,%1,%2,%3};"
        : "+f"(d[0]), "+f"(d[1]), "+f"(d[2]), "+f"(d[3])
        : "r"(a[0]), "r"(a[1]), "r"(a[2]), "r"(a[3]),
          "r"(b[0]), "r"(b[1]));
}
__device__ __forceinline__ void ldsm_x4(uint32_t* r, uint32_t addr) {
    asm volatile("ldmatrix.sync.aligned.m8n8.x4.shared.b16 {%0,%1,%2,%3}, [%4];"
        : "=r"(r[0]), "=r"(r[1]), "=r"(r[2]), "=r"(r[3]) : "r"(addr));
}
__device__ __forceinline__ void cp16(uint32_t dst, const void* src) {
    asm volatile("cp.async.cg.shared.global [%0], [%1], 16;" :: "r"(dst), "l"(src));
}

// ---------------- prep: pack xcat + convert weights + reset queue ----------
__global__ void prep_kernel(const float4* __restrict__ x,
                            const float4* __restrict__ fwd,
                            const float4* __restrict__ rev,
                            const float4* __restrict__ w0, const float4* __restrict__ w1,
                            const float4* __restrict__ w2, const float4* __restrict__ w3,
                            uint2* __restrict__ xc, uint2* __restrict__ wdst) {
    if (blockIdx.x == 0 && threadIdx.x == 0) g_work = 0;
    const int C4 = C_/4;
    const int NX = B_*S_*C4;
    const int NW = C_*C_/4;
    int idx = blockIdx.x * 256 + threadIdx.x;
    if (idx < NX) {
        int c4 = idx % C4;
        int r  = (idx / C4) % S_;
        int b  = idx / (C4 * S_);
        float4 val;
        if (r < T_)            val = x  [(b*T_ + r)          * C4 + c4];
        else if (r < T_ + M_)  val = fwd[(b*M_ + (r - T_))   * C4 + c4];
        else                   val = rev[(b*M_ + (r - T_-M_))* C4 + c4];
        xc[idx] = make_uint2(h2u(__floats2half2_rn(val.x, val.y)),
                             h2u(__floats2half2_rn(val.z, val.w)));
    } else {
        int widx = idx - NX;
        if (widx >= 4*NW) return;
        int m = widx / NW, r = widx % NW;
        const float4* s = (m == 0) ? w0 : (m == 1) ? w1 : (m == 2) ? w2 : w3;
        float4 v = s[r];
        wdst[widx] = make_uint2(h2u(__floats2half2_rn(v.x, v.y)),
                                h2u(__floats2half2_rn(v.z, v.w)));
    }
}

// ================= FP16 GEMM: BK=64, cp.async 3-stage + ldmatrix ===========
#define GBK 64
#define GROWB 144
#define GOPB (128 * GROWB)
#define GSTAGEB (2 * GOPB)
#define GEMM_SMEM (3 * GSTAGEB)          // 110592 B -> 2 CTA/SM

__global__ __launch_bounds__(256)
void gemm_f16(const __half* __restrict__ A, const __half* __restrict__ Bm,
              float* __restrict__ Cm, __half* __restrict__ qp,
              __half* __restrict__ kp, __half* __restrict__ vp,
              int Nr, int Kr, int mode) {
    if (mode == 1 && blockIdx.x < 8 && (blockIdx.y % 20) >= 16) return;

    extern __shared__ uint32_t smg[];
    const uint32_t sbase = (uint32_t)__cvta_generic_to_shared(smg);

    const int tid  = threadIdx.x;
    const int lane = tid & 31, warp = tid >> 5;
    const int g = lane >> 2, qc = lane & 3;
    const int wm0 = (warp >> 2) * 64;
    const int wn0 = (warp & 3) * 32;
    const int m0 = blockIdx.y * 128, n0 = blockIdx.x * 128;
    const int nk = Kr / GBK;

    const int a_off = (lane & 15) * GROWB + (lane >> 4) * 16;
    const int b_off = (((lane >> 4) & 1) * 8 + (lane & 7)) * GROWB
                      + ((lane >> 3) & 1) * 16;

    float acc[4][4][4] = {};

    #define PREFETCH(KT)                                                       \
    do {                                                                       \
        int kt_ = (KT);                                                        \
        if (kt_ < nk) {                                                        \
            uint32_t da = sbase + (kt_ % 3) * GSTAGEB;                         \
            uint32_t db = da + GOPB;                                           \
            const __half* Ag_ = A  + (size_t)m0 * Kr + kt_ * GBK;              \
            const __half* Bg_ = Bm + (size_t)n0 * Kr + kt_ * GBK;              \
            _Pragma("unroll")                                                  \
            for (int j = 0; j < 4; j++) {                                      \
                int u = tid + j * 256;                                         \
                int row = u >> 3, q16 = u & 7;                                 \
                cp16(da + row * GROWB + q16 * 16, Ag_ + (size_t)row * Kr + q16 * 8); \
                cp16(db + row * GROWB + q16 * 16, Bg_ + (size_t)row * Kr + q16 * 8); \
            }                                                                  \
        }                                                                      \
        asm volatile("cp.async.commit_group;");                                \
    } while (0)

    PREFETCH(0);
    PREFETCH(1);

    for (int kt = 0; kt < nk; kt++) {
        asm volatile("cp.async.wait_group 1;");
        __syncthreads();
        PREFETCH(kt + 2);

        const uint32_t aAddr = sbase + (kt % 3) * GSTAGEB + wm0 * GROWB + a_off;
        const uint32_t bAddr = sbase + (kt % 3) * GSTAGEB + GOPB + wn0 * GROWB + b_off;

        #pragma unroll
        for (int kp_ = 0; kp_ < 4; kp_++) {
            uint32_t bf[4][2];
            {
                uint32_t r[4];
                ldsm_x4(r, bAddr + kp_ * 32);
                bf[0][0] = r[0]; bf[0][1] = r[1]; bf[1][0] = r[2]; bf[1][1] = r[3];
            }
            {
                uint32_t r[4];
                ldsm_x4(r, bAddr + 16 * GROWB + kp_ * 32);
                bf[2][0] = r[0]; bf[2][1] = r[1]; bf[3][0] = r[2]; bf[3][1] = r[3];
            }
            uint32_t af[4][4];
            #pragma unroll
            for (int mt = 0; mt < 4; mt++)
                ldsm_x4(af[mt], aAddr + mt * 16 * GROWB + kp_ * 32);
            #pragma unroll
            for (int mt = 0; mt < 4; mt++)
                #pragma unroll
                for (int nt = 0; nt < 4; nt++)
                    mma_f16(acc[mt][nt], af[mt], bf[nt]);
        }
    }
    #undef PREFETCH

    if (mode == 0) {
        #pragma unroll
        for (int mt = 0; mt < 4; mt++) {
            #pragma unroll
            for (int nt = 0; nt < 4; nt++) {
                int row = m0 + wm0 + mt*16 + g;
                int col = n0 + wn0 + nt*8 + qc*2;
                float2 lo = make_float2(acc[mt][nt][0], acc[mt][nt][1]);
                float2 hi = make_float2(acc[mt][nt][2], acc[mt][nt][3]);
                *(float2*)(Cm + (size_t)row     * Nr + col) = lo;
                *(float2*)(Cm + (size_t)(row+8) * Nr + col) = hi;
            }
        }
    } else {
        #pragma unroll
        for (int mt = 0; mt < 4; mt++) {
            #pragma unroll
            for (int nt = 0; nt < 4; nt++) {
                int row = m0 + wm0 + mt*16 + g;
                int col = n0 + wn0 + nt*8 + qc*2;
                int which = col >> 10, lc = col & 1023;
                int bb = row / S_, rr = row % S_;
                __half2 lo = __floats2half2_rn(acc[mt][nt][0], acc[mt][nt][1]);
                __half2 hi = __floats2half2_rn(acc[mt][nt][2], acc[mt][nt][3]);
                if (which == 0) {
                    if (rr < T_) {
                        __half* dst = qp + ((size_t)(bb*T_ + rr)) * C_ + lc;
                        *(__half2*)(dst)        = lo;
                        *(__half2*)(dst + 8*C_) = hi;
                    }
                } else if (which == 1) {
                    __half* dst = kp + (size_t)row * C_ + lc;
                    *(__half2*)(dst)        = lo;
                    *(__half2*)(dst + 8*C_) = hi;
                } else {
                    __half* b0 = vp + ((size_t)(bb*C_ + lc)) * S_ + rr;
                    b0[0]      = __low2half(lo);
                    b0[S_]     = __high2half(lo);
                    b0[8]      = __low2half(hi);
                    b0[S_ + 8] = __high2half(hi);
                }
            }
        }
    }
}

// ---------------- gate: GR=8 (512 CTAs), reads fp16 q ----------------------
#define GR 8
#define GATE_SMEM (GR * 256 * (int)sizeof(uint2))   // 16 KB

__global__ __launch_bounds__(256)
void gate_kernel(const __half* __restrict__ q, const float* __restrict__ gw,
                 const float* __restrict__ gb, float* __restrict__ gate) {
    extern __shared__ uint2 qs2[];
    const int bt0 = blockIdx.x * GR;
    const int tid = threadIdx.x;
    const int warp = tid >> 5, lane = tid & 31;

    const uint2* qsrc = (const uint2*)(q + (size_t)bt0 * C_);
    #pragma unroll
    for (int i = 0; i < GR; i++)
        qs2[i * 256 + tid] = qsrc[i * 256 + tid];
    __syncthreads();

    const int h0 = warp * 2, h1 = h0 + 1;
    const float4* g0p = (const float4*)(gw + h0 * C_);
    const float4* g1p = (const float4*)(gw + h1 * C_);

    float s0[GR] = {}, s1[GR] = {};
    #pragma unroll
    for (int i = 0; i < 8; i++) {
        float4 g0 = g0p[lane + i*32];
        float4 g1 = g1p[lane + i*32];
        #pragma unroll
        for (int r = 0; r < GR; r++) {
            uint2 qv = qs2[r * 256 + lane + i*32];
            float2 f01 = __half22float2(*reinterpret_cast<__half2*>(&qv.x));
            float2 f23 = __half22float2(*reinterpret_cast<__half2*>(&qv.y));
            s0[r] += f01.x*g0.x + f01.y*g0.y + f23.x*g0.z + f23.y*g0.w;
            s1[r] += f01.x*g1.x + f01.y*g1.y + f23.x*g1.z + f23.y*g1.w;
        }
    }
    float b0 = gb[h0], b1 = gb[h1];
    #pragma unroll
    for (int r = 0; r < GR; r++) {
        float v0 = s0[r], v1 = s1[r];
        #pragma unroll
        for (int o = 16; o; o >>= 1) {
            v0 += __shfl_xor_sync(~0u, v0, o);
            v1 += __shfl_xor_sync(~0u, v1, o);
        }
        if (lane == 0) {
            gate[(size_t)(bt0 + r) * H_ + h0] = 1.f / (1.f + __expf(-(v0 + b0)));
            gate[(size_t)(bt0 + r) * H_ + h1] = 1.f / (1.f + __expf(-(v1 + b1)));
        }
    }
}

// ================= fp16 attention: persistent, LPT queue ===================
#define AROWB 144
#define ATILE_B (64 * AROWB)
#define ATT_SMEM (6 * ATILE_B)           // 55296 B -> 3 CTA/SM

__global__ __launch_bounds__(128, 3)
void attn_f16(const __half* __restrict__ q, const __half* __restrict__ k,
              const __half* __restrict__ vT, const float* __restrict__ gate,
              __half* __restrict__ outp) {
    extern __shared__ uint32_t s3[];
    __shared__ int s_item;
    const uint32_t sbase = (uint32_t)__cvta_generic_to_shared(s3);

    const int tid  = threadIdx.x;
    const int lane = tid & 31, warp = tid >> 5;
    const int g = lane >> 2, qc = lane & 3;
    const int wr0 = warp * 16;

    const int a_off = (lane & 15) * AROWB + (lane >> 4) * 16;
    const int b_off = (((lane >> 4) & 1) * 8 + (lane & 7)) * AROWB
                      + ((lane >> 3) & 1) * 16;
    const int nMem = (2*M_)/64;

    #define KBUF(IT) (sbase + (((IT) & 1)     ) * ATILE_B)
    #define VBUF(IT) (sbase + (2 + ((IT) & 1) ) * ATILE_B)
    #define QBUF     (sbase + 4 * ATILE_B)
    #define PBUF     (sbase + 5 * ATILE_B)

    for (;;) {
        if (tid == 0) s_item = atomicAdd(&g_work, 1);
        __syncthreads();           // broadcast + prior item's smem reads done
        const int w = s_item;
        if (w >= NITEMS) return;

        // heavy-first decode: largest t0 first
        const int xi = w >> 5;                 // 0..31
        const int yi = w & 31;                 // (b,h)
        const int t0 = (31 - xi) * 64;
        const int b  = yi >> 4;
        const int h  = yi & 15;

        const int nChunk = t0/64 + 1;
        const int nTiles = nMem + nChunk;
        #define S0OF(IT) (((IT) < nMem) ? (T_ + (IT)*64) : ((IT) - nMem)*64)

        // ---- stage Q ----
        {
            const __half* src_ = q + ((size_t)(b*T_ + t0)) * C_ + h*HD_;
            #pragma unroll
            for (int j = 0; j < 4; j++) {
                int u = tid + j * 128;
                int row = u >> 3, cw = u & 7;
                cp16(QBUF + row * AROWB + cw * 16, src_ + (size_t)row * C_ + cw * 8);
            }
            asm volatile("cp.async.commit_group;");
        }

        #define FILL_KV(IT)                                                       \
        do {                                                                      \
            int it_ = (IT);                                                       \
            if (it_ < nTiles) {                                                   \
                int s0_ = S0OF(it_);                                              \
                uint32_t kb_ = KBUF(it_);                                         \
                uint32_t vb_ = VBUF(it_);                                         \
                const __half* ks_ = k  + ((size_t)(b*S_ + s0_)) * C_ + h*HD_;     \
                const __half* vs_ = vT + ((size_t)(b*C_ + h*HD_)) * S_ + s0_;     \
                _Pragma("unroll")                                                 \
                for (int j = 0; j < 4; j++) {                                     \
                    int u = tid + j * 128;                                        \
                    int row = u >> 3, cw = u & 7;                                 \
                    cp16(kb_ + row * AROWB + cw * 16, ks_ + (size_t)row * C_ + cw * 8); \
                    cp16(vb_ + row * AROWB + cw * 16, vs_ + (size_t)row * S_ + cw * 8); \
                }                                                                 \
            }                                                                     \
            asm volatile("cp.async.commit_group;");                               \
        } while (0)

        FILL_KV(0);
        asm volatile("cp.async.wait_group 1;");   // Q staged (leftovers drained)
        __syncthreads();

        // ---- Q fragments (scale 1/8 folded) ----
        uint32_t qf[4][4];
        const __half2 sc8 = __half2half2(__float2half(0.125f));
        #pragma unroll
        for (int kk = 0; kk < 4; kk++) {
            ldsm_x4(qf[kk], QBUF + wr0 * AROWB + a_off + kk * 32);
            #pragma unroll
            for (int e = 0; e < 4; e++) {
                __half2 hm = __hmul2(*reinterpret_cast<__half2*>(&qf[kk][e]), sc8);
                qf[kk][e] = h2u(hm);
            }
        }

        const int rA = t0 + wr0 + g, rB = rA + 8;
        const float gA = gate[(size_t)(b*T_ + rA) * H_ + h];
        const float gB = gate[(size_t)(b*T_ + rB) * H_ + h];

        float acc[8][4] = {};
        float mA = -1e30f, mB = -1e30f, lA = 0.f, lB = 0.f;

        for (int it = 0; it < nTiles; it++) {
            const int  s0     = S0OF(it);
            const bool isDiag = (it == nTiles - 1);
            const uint32_t Kb = KBUF(it);
            const uint32_t Vb = VBUF(it);

            asm volatile("cp.async.wait_group 0;");
            __syncthreads();
            FILL_KV(it + 1);

            float sf[8][4] = {};
            #pragma unroll
            for (int kk = 0; kk < 4; kk++) {
                #pragma unroll
                for (int f2 = 0; f2 < 4; f2++) {
                    uint32_t r[4];
                    ldsm_x4(r, Kb + f2 * 16 * AROWB + b_off + kk * 32);
                    uint32_t b0[2] = {r[0], r[1]}, b1[2] = {r[2], r[3]};
                    mma_f16(sf[2*f2],     qf[kk], b0);
                    mma_f16(sf[2*f2 + 1], qf[kk], b1);
                }
            }

            float tmA = -1e30f, tmB = -1e30f;
            #pragma unroll
            for (int f = 0; f < 8; f++) {
                if (isDiag) {
                    int c0 = s0 + f*8 + 2*qc, c1 = c0 + 1;
                    if (c0 > rA) sf[f][0] = -1e30f;
                    if (c1 > rA) sf[f][1] = -1e30f;
                    if (c0 > rB) sf[f][2] = -1e30f;
                    if (c1 > rB) sf[f][3] = -1e30f;
                }
                tmA = fmaxf(tmA, fmaxf(sf[f][0], sf[f][1]));
                tmB = fmaxf(tmB, fmaxf(sf[f][2], sf[f][3]));
            }
            tmA = fmaxf(tmA, __shfl_xor_sync(~0u, tmA, 1));
            tmA = fmaxf(tmA, __shfl_xor_sync(~0u, tmA, 2));
            tmB = fmaxf(tmB, __shfl_xor_sync(~0u, tmB, 1));
            tmB = fmaxf(tmB, __shfl_xor_sync(~0u, tmB, 2));

            float mAn = fmaxf(mA, tmA), mBn = fmaxf(mB, tmB);
            float fA = __expf(mA - mAn), fB = __expf(mB - mBn);
            mA = mAn; mB = mBn;

            __half* Ph = (__half*)((char*)s3 + 5 * ATILE_B);
            float sA = 0.f, sB = 0.f;
            #pragma unroll
            for (int f = 0; f < 8; f++) {
                float p0 = __expf(sf[f][0] - mA);
                float p1 = __expf(sf[f][1] - mA);
                float p2 = __expf(sf[f][2] - mB);
                float p3 = __expf(sf[f][3] - mB);
                sA += p0 + p1; sB += p2 + p3;
                *(__half2*)&Ph[(wr0 + g    )*72 + f*8 + 2*qc] = __floats2half2_rn(p0, p1);
                *(__half2*)&Ph[(wr0 + g + 8)*72 + f*8 + 2*qc] = __floats2half2_rn(p2, p3);
            }
            sA += __shfl_xor_sync(~0u, sA, 1); sA += __shfl_xor_sync(~0u, sA, 2);
            sB += __shfl_xor_sync(~0u, sB, 1); sB += __shfl_xor_sync(~0u, sB, 2);
            lA = lA * fA + sA;
            lB = lB * fB + sB;

            #pragma unroll
            for (int f = 0; f < 8; f++) {
                acc[f][0] *= fA; acc[f][1] *= fA; acc[f][2] *= fB; acc[f][3] *= fB;
            }
            __syncwarp();

            uint32_t pf[4][4];
            #pragma unroll
            for (int kk = 0; kk < 4; kk++)
                ldsm_x4(pf[kk], PBUF + wr0 * AROWB + a_off + kk * 32);

            #pragma unroll
            for (int kk = 0; kk < 4; kk++) {
                #pragma unroll
                for (int f2 = 0; f2 < 4; f2++) {
                    uint32_t r[4];
                    ldsm_x4(r, Vb + f2 * 16 * AROWB + b_off + kk * 32);
                    uint32_t b0[2] = {r[0], r[1]}, b1[2] = {r[2], r[3]};
                    mma_f16(acc[2*f2],     pf[kk], b0);
                    mma_f16(acc[2*f2 + 1], pf[kk], b1);
                }
            }

            if (it == nMem - 1) {
                #pragma unroll
                for (int f = 0; f < 8; f++) {
                    acc[f][0] *= gA; acc[f][1] *= gA;
                    acc[f][2] *= gB; acc[f][3] *= gB;
                }
            }
        }
        #undef FILL_KV
        #undef S0OF

        float invA = 1.f / lA, invB = 1.f / lB;
        #pragma unroll
        for (int f = 0; f < 8; f++) {
            int col = h*HD_ + f*8 + 2*qc;
            __half2 o0 = __floats2half2_rn(acc[f][0] * invA, acc[f][1] * invA);
            __half2 o1 = __floats2half2_rn(acc[f][2] * invB, acc[f][3] * invB);
            *(__half2*)&outp[(size_t)(b*T_ + rA) * C_ + col] = o0;
            *(__half2*)&outp[(size_t)(b*T_ + rB) * C_ + col] = o1;
        }
    }
    #undef KBUF
    #undef VBUF
    #undef QBUF
    #undef PBUF
}

// ---------------- canon conv (fp16 in, fp16 out) ----------------------------
__global__ __launch_bounds__(256)
void conv_kernel(const __half* __restrict__ y, const float* __restrict__ cw,
                 const float4* __restrict__ cb4, uint2* __restrict__ z) {
    const int C4 = C_/4;
    int idx = blockIdx.x * 256 + threadIdx.x;
    if (idx >= B_*T_*C4) return;
    int c4 = idx & (C4 - 1);
    int t  = (idx / C4) % T_;
    int b  = idx / (C4 * T_);

    const float4* cwr = (const float4*)cw;
    float4 w0 = cwr[c4*4 + 0];
    float4 w1 = cwr[c4*4 + 1];
    float4 w2 = cwr[c4*4 + 2];
    float4 w3 = cwr[c4*4 + 3];
    float wa[4][4] = {{w0.x,w0.y,w0.z,w0.w}, {w1.x,w1.y,w1.z,w1.w},
                      {w2.x,w2.y,w2.z,w2.w}, {w3.x,w3.y,w3.z,w3.w}};

    const uint2* y2 = (const uint2*)y;
    uint2 yc = y2[idx];
    float2 a01 = __half22float2(*reinterpret_cast<__half2*>(&yc.x));
    float2 a23 = __half22float2(*reinterpret_cast<__half2*>(&yc.y));
    float4 cbv = cb4[c4];
    float ax = a01.x + cbv.x, ay = a01.y + cbv.y;
    float az = a23.x + cbv.z, aw = a23.y + cbv.w;

    #pragma unroll
    for (int j = 0; j < KC_; j++) {
        int tt = t - (KC_ - 1) + j;
        if (tt >= 0) {
            uint2 yv = y2[((size_t)(b*T_ + tt)) * C4 + c4];
            float2 f01 = __half22float2(*reinterpret_cast<__half2*>(&yv.x));
            float2 f23 = __half22float2(*reinterpret_cast<__half2*>(&yv.y));
            ax += f01.x * wa[0][j];
            ay += f01.y * wa[1][j];
            az += f23.x * wa[2][j];
            aw += f23.y * wa[3][j];
        }
    }
    z[idx] = make_uint2(h2u(__floats2half2_rn(ax, ay)),
                        h2u(__floats2half2_rn(az, aw)));
}

// ---------------- orchestration -------------------------------------------
extern "C" void kernel_launch(void* const* d_in, const int* in_sizes, int n_in,
                              void* d_out, int out_size) {
    const float* x   = (const float*)d_in[0];
    const float* fwd = (const float*)d_in[1];
    const float* rev = (const float*)d_in[2];
    const float* Wq  = (const float*)d_in[3];
    const float* Wk  = (const float*)d_in[4];
    const float* Wv  = (const float*)d_in[5];
    const float* Wo  = (const float*)d_in[6];
    const float* gw  = (const float*)d_in[7];
    const float* gb  = (const float*)d_in[8];
    const float* cw  = (const float*)d_in[9];
    const float* cb  = (const float*)d_in[10];
    float* out = (float*)d_out;

    __half *xc, *wtf, *z16, *qb, *kb, *vt, *at;
    float *gt;
    cudaGetSymbolAddress((void**)&xc,  g_xcat);
    cudaGetSymbolAddress((void**)&wtf, g_wtf);
    cudaGetSymbolAddress((void**)&z16, g_z16);
    cudaGetSymbolAddress((void**)&qb,  g_q16);
    cudaGetSymbolAddress((void**)&kb,  g_k16);
    cudaGetSymbolAddress((void**)&vt,  g_vt16);
    cudaGetSymbolAddress((void**)&gt,  g_gate);
    cudaGetSymbolAddress((void**)&at,  g_attn16);

    cudaFuncSetAttribute(gemm_f16,
                         cudaFuncAttributeMaxDynamicSharedMemorySize, GEMM_SMEM);
    cudaFuncSetAttribute(attn_f16,
                         cudaFuncAttributeMaxDynamicSharedMemorySize, ATT_SMEM);
    cudaFuncSetAttribute(gate_kernel,
                         cudaFuncAttributeMaxDynamicSharedMemorySize, GATE_SMEM);

    // 1. fused pre-convert (xcat pack + weights + queue reset)
    {
        int ntot = B_*S_*(C_/4) + 4*C_*C_/4;
        prep_kernel<<<(ntot + 255)/256, 256>>>(
            (const float4*)x, (const float4*)fwd, (const float4*)rev,
            (const float4*)Wq, (const float4*)Wk, (const float4*)Wv,
            (const float4*)Wo, (uint2*)xc, (uint2*)wtf);
    }

    // 2. fused QKV projection (fp16 tensor cores; v written transposed)
    gemm_f16<<<dim3(3*C_/128, (B_*S_)/128), 256, GEMM_SMEM>>>(
        xc, wtf, nullptr, qb, kb, vt, 3*C_, C_, 1);

    // 3. gate
    gate_kernel<<<(B_*T_)/GR, 256, GATE_SMEM>>>(qb, gw, gb, gt);
    // 4. attention (persistent, 3 CTA/SM x 148 SMs)
    attn_f16<<<148*3, 128, ATT_SMEM>>>(qb, kb, vt, gt, at);
    // 5. canon conv (fp16 in/out)
    conv_kernel<<<(B_*T_*(C_/4) + 255)/256, 256>>>(at, cw,
                                                   (const float4*)cb, (uint2*)z16);
    // 6. output projection into d_out (fp32 out)
    gemm_f16<<<dim3(C_/128, (B_*T_)/128), 256, GEMM_SMEM>>>(
        z16, wtf + 3*C_*C_, out, nullptr, nullptr, nullptr, C_, C_, 0);
}

// round 16
// speedup vs baseline: 2.3962x; 1.0002x over previous
#include <cuda_runtime.h>
#include <cuda_fp16.h>
#include <math.h>
#include <stdint.h>

#define B_ 2
#define T_ 2048
#define C_ 1024
#define H_ 16
#define HD_ 64
#define M_ 256
#define S_ (T_ + 2*M_)   /* 2560 */
#define KC_ 4

// ---------------- scratch (static device globals; no runtime alloc) -------
__device__ __half g_xcat[B_*S_*C_];   // concat(x,fwd,rev) fp16
__device__ __half g_wtf [4*C_*C_];    // Wq|Wk|Wv|Wo fp16
__device__ __half g_q16 [B_*T_*C_];   // q fp16
__device__ __half g_k16 [B_*S_*C_];   // k fp16
__device__ __half g_vt16[B_*C_*S_];   // V^T fp16: [b][c][s]
__device__ float  g_gate[B_*T_*H_];
__device__ __half g_attn16[B_*T_*C_]; // attention output fp16
__device__ __half g_z16 [B_*T_*C_];   // conv output fp16
__device__ int    g_work;             // persistent-attention work counter

#define NITEMS ((T_/64) * B_ * H_)    // 1024 work items

// ================= helpers =================================================
__device__ __forceinline__ uint32_t h2u(__half2 h) {
    return *reinterpret_cast<uint32_t*>(&h);
}
__device__ __forceinline__ void mma_f16(float* d, const uint32_t* a,
                                        const uint32_t* b) {
    asm volatile(
        "mma.sync.aligned.m16n8k16.row.col.f32.f16.f16.f32 "
        "{%0,%1,%2,%3}, {%4,%5,%6,%7}, {%8,%9}, {%0,%1,%2,%3};"
        : "+f"(d[0]), "+f"(d[1]), "+f"(d[2]), "+f"(d[3])
        : "r"(a[0]), "r"(a[1]), "r"(a[2]), "r"(a[3]),
          "r"(b[0]), "r"(b[1]));
}
__device__ __forceinline__ void ldsm_x4(uint32_t* r, uint32_t addr) {
    asm volatile("ldmatrix.sync.aligned.m8n8.x4.shared.b16 {%0,%1,%2,%3}, [%4];"
        : "=r"(r[0]), "=r"(r[1]), "=r"(r[2]), "=r"(r[3]) : "r"(addr));
}
__device__ __forceinline__ void cp16(uint32_t dst, const void* src) {
    asm volatile("cp.async.cg.shared.global [%0], [%1], 16;" :: "r"(dst), "l"(src));
}

// ---------------- prep: pack xcat + convert weights + reset queue ----------
__global__ void prep_kernel(const float4* __restrict__ x,
                            const float4* __restrict__ fwd,
                            const float4* __restrict__ rev,
                            const float4* __restrict__ w0, const float4* __restrict__ w1,
                            const float4* __restrict__ w2, const float4* __restrict__ w3,
                            uint2* __restrict__ xc, uint2* __restrict__ wdst) {
    if (blockIdx.x == 0 && threadIdx.x == 0) g_work = 0;
    const int C4 = C_/4;
    const int NX = B_*S_*C4;
    const int NW = C_*C_/4;
    int idx = blockIdx.x * 256 + threadIdx.x;
    if (idx < NX) {
        int c4 = idx % C4;
        int r  = (idx / C4) % S_;
        int b  = idx / (C4 * S_);
        float4 val;
        if (r < T_)            val = x  [(b*T_ + r)          * C4 + c4];
        else if (r < T_ + M_)  val = fwd[(b*M_ + (r - T_))   * C4 + c4];
        else                   val = rev[(b*M_ + (r - T_-M_))* C4 + c4];
        xc[idx] = make_uint2(h2u(__floats2half2_rn(val.x, val.y)),
                             h2u(__floats2half2_rn(val.z, val.w)));
    } else {
        int widx = idx - NX;
        if (widx >= 4*NW) return;
        int m = widx / NW, r = widx % NW;
        const float4* s = (m == 0) ? w0 : (m == 1) ? w1 : (m == 2) ? w2 : w3;
        float4 v = s[r];
        wdst[widx] = make_uint2(h2u(__floats2half2_rn(v.x, v.y)),
                                h2u(__floats2half2_rn(v.z, v.w)));
    }
}

// ================= FP16 GEMM: BK=64, cp.async 3-stage + ldmatrix ===========
// mode 1 V-columns: tile transposed through smem, coalesced store to vt.
#define GBK 64
#define GROWB 144
#define GOPB (128 * GROWB)
#define GSTAGEB (2 * GOPB)
#define GEMM_SMEM (3 * GSTAGEB)          // 110592 B -> 2 CTA/SM

__global__ __launch_bounds__(256)
void gemm_f16(const __half* __restrict__ A, const __half* __restrict__ Bm,
              float* __restrict__ Cm, __half* __restrict__ qp,
              __half* __restrict__ kp, __half* __restrict__ vp,
              int Nr, int Kr, int mode) {
    if (mode == 1 && blockIdx.x < 8 && (blockIdx.y % 20) >= 16) return;

    extern __shared__ uint32_t smg[];
    const uint32_t sbase = (uint32_t)__cvta_generic_to_shared(smg);

    const int tid  = threadIdx.x;
    const int lane = tid & 31, warp = tid >> 5;
    const int g = lane >> 2, qc = lane & 3;
    const int wm0 = (warp >> 2) * 64;
    const int wn0 = (warp & 3) * 32;
    const int m0 = blockIdx.y * 128, n0 = blockIdx.x * 128;
    const int nk = Kr / GBK;

    const int a_off = (lane & 15) * GROWB + (lane >> 4) * 16;
    const int b_off = (((lane >> 4) & 1) * 8 + (lane & 7)) * GROWB
                      + ((lane >> 3) & 1) * 16;

    float acc[4][4][4] = {};

    #define PREFETCH(KT)                                                       \
    do {                                                                       \
        int kt_ = (KT);                                                        \
        if (kt_ < nk) {                                                        \
            uint32_t da = sbase + (kt_ % 3) * GSTAGEB;                         \
            uint32_t db = da + GOPB;                                           \
            const __half* Ag_ = A  + (size_t)m0 * Kr + kt_ * GBK;              \
            const __half* Bg_ = Bm + (size_t)n0 * Kr + kt_ * GBK;              \
            _Pragma("unroll")                                                  \
            for (int j = 0; j < 4; j++) {                                      \
                int u = tid + j * 256;                                         \
                int row = u >> 3, q16 = u & 7;                                 \
                cp16(da + row * GROWB + q16 * 16, Ag_ + (size_t)row * Kr + q16 * 8); \
                cp16(db + row * GROWB + q16 * 16, Bg_ + (size_t)row * Kr + q16 * 8); \
            }                                                                  \
        }                                                                      \
        asm volatile("cp.async.commit_group;");                                \
    } while (0)

    PREFETCH(0);
    PREFETCH(1);

    for (int kt = 0; kt < nk; kt++) {
        asm volatile("cp.async.wait_group 1;");
        __syncthreads();
        PREFETCH(kt + 2);

        const uint32_t aAddr = sbase + (kt % 3) * GSTAGEB + wm0 * GROWB + a_off;
        const uint32_t bAddr = sbase + (kt % 3) * GSTAGEB + GOPB + wn0 * GROWB + b_off;

        #pragma unroll
        for (int kp_ = 0; kp_ < 4; kp_++) {
            uint32_t bf[4][2];
            {
                uint32_t r[4];
                ldsm_x4(r, bAddr + kp_ * 32);
                bf[0][0] = r[0]; bf[0][1] = r[1]; bf[1][0] = r[2]; bf[1][1] = r[3];
            }
            {
                uint32_t r[4];
                ldsm_x4(r, bAddr + 16 * GROWB + kp_ * 32);
                bf[2][0] = r[0]; bf[2][1] = r[1]; bf[3][0] = r[2]; bf[3][1] = r[3];
            }
            uint32_t af[4][4];
            #pragma unroll
            for (int mt = 0; mt < 4; mt++)
                ldsm_x4(af[mt], aAddr + mt * 16 * GROWB + kp_ * 32);
            #pragma unroll
            for (int mt = 0; mt < 4; mt++)
                #pragma unroll
                for (int nt = 0; nt < 4; nt++)
                    mma_f16(acc[mt][nt], af[mt], bf[nt]);
        }
    }
    #undef PREFETCH

    if (mode == 0) {
        #pragma unroll
        for (int mt = 0; mt < 4; mt++) {
            #pragma unroll
            for (int nt = 0; nt < 4; nt++) {
                int row = m0 + wm0 + mt*16 + g;
                int col = n0 + wn0 + nt*8 + qc*2;
                float2 lo = make_float2(acc[mt][nt][0], acc[mt][nt][1]);
                float2 hi = make_float2(acc[mt][nt][2], acc[mt][nt][3]);
                *(float2*)(Cm + (size_t)row     * Nr + col) = lo;
                *(float2*)(Cm + (size_t)(row+8) * Nr + col) = hi;
            }
        }
    } else if (blockIdx.x < 16) {
        // q / k columns: direct fp16 stores (coalesced 4B)
        #pragma unroll
        for (int mt = 0; mt < 4; mt++) {
            #pragma unroll
            for (int nt = 0; nt < 4; nt++) {
                int row = m0 + wm0 + mt*16 + g;
                int col = n0 + wn0 + nt*8 + qc*2;
                int which = col >> 10, lc = col & 1023;
                int bb = row / S_, rr = row % S_;
                __half2 lo = __floats2half2_rn(acc[mt][nt][0], acc[mt][nt][1]);
                __half2 hi = __floats2half2_rn(acc[mt][nt][2], acc[mt][nt][3]);
                if (which == 0) {
                    if (rr < T_) {
                        __half* dst = qp + ((size_t)(bb*T_ + rr)) * C_ + lc;
                        *(__half2*)(dst)        = lo;
                        *(__half2*)(dst + 8*C_) = hi;
                    }
                } else {
                    __half* dst = kp + (size_t)row * C_ + lc;
                    *(__half2*)(dst)        = lo;
                    *(__half2*)(dst + 8*C_) = hi;
                }
            }
        }
    } else {
        // V columns: transpose tile via smem, then coalesced rows into vt.
        asm volatile("cp.async.wait_group 0;");
        __syncthreads();                       // all MMA reads of smem done
        __half* tsm = (__half*)smg;            // [128 cols][136 pad] halves
        #pragma unroll
        for (int mt = 0; mt < 4; mt++) {
            #pragma unroll
            for (int nt = 0; nt < 4; nt++) {
                int cl = wn0 + nt*8 + qc*2;    // tile-local col (V channel)
                int rl = wm0 + mt*16 + g;      // tile-local row (seq pos)
                __half2 lo = __floats2half2_rn(acc[mt][nt][0], acc[mt][nt][1]);
                __half2 hi = __floats2half2_rn(acc[mt][nt][2], acc[mt][nt][3]);
                tsm[(cl    ) * 136 + rl    ] = __low2half(lo);
                tsm[(cl + 1) * 136 + rl    ] = __high2half(lo);
                tsm[(cl    ) * 136 + rl + 8] = __low2half(hi);
                tsm[(cl + 1) * 136 + rl + 8] = __high2half(hi);
            }
        }
        __syncthreads();
        const int bb  = m0 / S_;               // whole tile in one batch
        const int rr0 = m0 % S_;
        const int lc0 = n0 & 1023;
        const int vtrow = tid & 127, seg = tid >> 7;   // 2 segs x 64 halves
        __half* dst = vp + ((size_t)(bb*C_ + lc0 + vtrow)) * S_ + rr0 + seg*64;
        const __half* src = tsm + vtrow * 136 + seg * 64;
        #pragma unroll
        for (int i = 0; i < 8; i++)
            *(uint4*)(dst + i*8) = *(const uint4*)(src + i*8);
    }
}

// ---------------- gate: GR=8 (512 CTAs), reads fp16 q ----------------------
#define GR 8
#define GATE_SMEM (GR * 256 * (int)sizeof(uint2))   // 16 KB

__global__ __launch_bounds__(256)
void gate_kernel(const __half* __restrict__ q, const float* __restrict__ gw,
                 const float* __restrict__ gb, float* __restrict__ gate) {
    extern __shared__ uint2 qs2[];
    const int bt0 = blockIdx.x * GR;
    const int tid = threadIdx.x;
    const int warp = tid >> 5, lane = tid & 31;

    const uint2* qsrc = (const uint2*)(q + (size_t)bt0 * C_);
    #pragma unroll
    for (int i = 0; i < GR; i++)
        qs2[i * 256 + tid] = qsrc[i * 256 + tid];
    __syncthreads();

    const int h0 = warp * 2, h1 = h0 + 1;
    const float4* g0p = (const float4*)(gw + h0 * C_);
    const float4* g1p = (const float4*)(gw + h1 * C_);

    float s0[GR] = {}, s1[GR] = {};
    #pragma unroll
    for (int i = 0; i < 8; i++) {
        float4 g0 = g0p[lane + i*32];
        float4 g1 = g1p[lane + i*32];
        #pragma unroll
        for (int r = 0; r < GR; r++) {
            uint2 qv = qs2[r * 256 + lane + i*32];
            float2 f01 = __half22float2(*reinterpret_cast<__half2*>(&qv.x));
            float2 f23 = __half22float2(*reinterpret_cast<__half2*>(&qv.y));
            s0[r] += f01.x*g0.x + f01.y*g0.y + f23.x*g0.z + f23.y*g0.w;
            s1[r] += f01.x*g1.x + f01.y*g1.y + f23.x*g1.z + f23.y*g1.w;
        }
    }
    float b0 = gb[h0], b1 = gb[h1];
    #pragma unroll
    for (int r = 0; r < GR; r++) {
        float v0 = s0[r], v1 = s1[r];
        #pragma unroll
        for (int o = 16; o; o >>= 1) {
            v0 += __shfl_xor_sync(~0u, v0, o);
            v1 += __shfl_xor_sync(~0u, v1, o);
        }
        if (lane == 0) {
            gate[(size_t)(bt0 + r) * H_ + h0] = 1.f / (1.f + __expf(-(v0 + b0)));
            gate[(size_t)(bt0 + r) * H_ + h1] = 1.f / (1.f + __expf(-(v1 + b1)));
        }
    }
}

// ================= fp16 attention: persistent, LPT queue ===================
#define AROWB 144
#define ATILE_B (64 * AROWB)
#define ATT_SMEM (6 * ATILE_B)           // 55296 B -> 3 CTA/SM

__global__ __launch_bounds__(128, 3)
void attn_f16(const __half* __restrict__ q, const __half* __restrict__ k,
              const __half* __restrict__ vT, const float* __restrict__ gate,
              __half* __restrict__ outp) {
    extern __shared__ uint32_t s3[];
    __shared__ int s_item;
    const uint32_t sbase = (uint32_t)__cvta_generic_to_shared(s3);

    const int tid  = threadIdx.x;
    const int lane = tid & 31, warp = tid >> 5;
    const int g = lane >> 2, qc = lane & 3;
    const int wr0 = warp * 16;

    const int a_off = (lane & 15) * AROWB + (lane >> 4) * 16;
    const int b_off = (((lane >> 4) & 1) * 8 + (lane & 7)) * AROWB
                      + ((lane >> 3) & 1) * 16;
    const int nMem = (2*M_)/64;

    #define KBUF(IT) (sbase + (((IT) & 1)     ) * ATILE_B)
    #define VBUF(IT) (sbase + (2 + ((IT) & 1) ) * ATILE_B)
    #define QBUF     (sbase + 4 * ATILE_B)
    #define PBUF     (sbase + 5 * ATILE_B)

    for (;;) {
        if (tid == 0) s_item = atomicAdd(&g_work, 1);
        __syncthreads();
        const int w = s_item;
        if (w >= NITEMS) return;

        const int xi = w >> 5;
        const int yi = w & 31;
        const int t0 = (31 - xi) * 64;
        const int b  = yi >> 4;
        const int h  = yi & 15;

        const int nChunk = t0/64 + 1;
        const int nTiles = nMem + nChunk;
        #define S0OF(IT) (((IT) < nMem) ? (T_ + (IT)*64) : ((IT) - nMem)*64)

        {
            const __half* src_ = q + ((size_t)(b*T_ + t0)) * C_ + h*HD_;
            #pragma unroll
            for (int j = 0; j < 4; j++) {
                int u = tid + j * 128;
                int row = u >> 3, cw = u & 7;
                cp16(QBUF + row * AROWB + cw * 16, src_ + (size_t)row * C_ + cw * 8);
            }
            asm volatile("cp.async.commit_group;");
        }

        #define FILL_KV(IT)                                                       \
        do {                                                                      \
            int it_ = (IT);                                                       \
            if (it_ < nTiles) {                                                   \
                int s0_ = S0OF(it_);                                              \
                uint32_t kb_ = KBUF(it_);                                         \
                uint32_t vb_ = VBUF(it_);                                         \
                const __half* ks_ = k  + ((size_t)(b*S_ + s0_)) * C_ + h*HD_;     \
                const __half* vs_ = vT + ((size_t)(b*C_ + h*HD_)) * S_ + s0_;     \
                _Pragma("unroll")                                                 \
                for (int j = 0; j < 4; j++) {                                     \
                    int u = tid + j * 128;                                        \
                    int row = u >> 3, cw = u & 7;                                 \
                    cp16(kb_ + row * AROWB + cw * 16, ks_ + (size_t)row * C_ + cw * 8); \
                    cp16(vb_ + row * AROWB + cw * 16, vs_ + (size_t)row * S_ + cw * 8); \
                }                                                                 \
            }                                                                     \
            asm volatile("cp.async.commit_group;");                               \
        } while (0)

        FILL_KV(0);
        asm volatile("cp.async.wait_group 1;");
        __syncthreads();

        uint32_t qf[4][4];
        const __half2 sc8 = __half2half2(__float2half(0.125f));
        #pragma unroll
        for (int kk = 0; kk < 4; kk++) {
            ldsm_x4(qf[kk], QBUF + wr0 * AROWB + a_off + kk * 32);
            #pragma unroll
            for (int e = 0; e < 4; e++) {
                __half2 hm = __hmul2(*reinterpret_cast<__half2*>(&qf[kk][e]), sc8);
                qf[kk][e] = h2u(hm);
            }
        }

        const int rA = t0 + wr0 + g, rB = rA + 8;
        const float gA = gate[(size_t)(b*T_ + rA) * H_ + h];
        const float gB = gate[(size_t)(b*T_ + rB) * H_ + h];

        float acc[8][4] = {};
        float mA = -1e30f, mB = -1e30f, lA = 0.f, lB = 0.f;

        for (int it = 0; it < nTiles; it++) {
            const int  s0     = S0OF(it);
            const bool isDiag = (it == nTiles - 1);
            const uint32_t Kb = KBUF(it);
            const uint32_t Vb = VBUF(it);

            asm volatile("cp.async.wait_group 0;");
            __syncthreads();
            FILL_KV(it + 1);

            float sf[8][4] = {};
            #pragma unroll
            for (int kk = 0; kk < 4; kk++) {
                #pragma unroll
                for (int f2 = 0; f2 < 4; f2++) {
                    uint32_t r[4];
                    ldsm_x4(r, Kb + f2 * 16 * AROWB + b_off + kk * 32);
                    uint32_t b0[2] = {r[0], r[1]}, b1[2] = {r[2], r[3]};
                    mma_f16(sf[2*f2],     qf[kk], b0);
                    mma_f16(sf[2*f2 + 1], qf[kk], b1);
                }
            }

            float tmA = -1e30f, tmB = -1e30f;
            #pragma unroll
            for (int f = 0; f < 8; f++) {
                if (isDiag) {
                    int c0 = s0 + f*8 + 2*qc, c1 = c0 + 1;
                    if (c0 > rA) sf[f][0] = -1e30f;
                    if (c1 > rA) sf[f][1] = -1e30f;
                    if (c0 > rB) sf[f][2] = -1e30f;
                    if (c1 > rB) sf[f][3] = -1e30f;
                }
                tmA = fmaxf(tmA, fmaxf(sf[f][0], sf[f][1]));
                tmB = fmaxf(tmB, fmaxf(sf[f][2], sf[f][3]));
            }
            tmA = fmaxf(tmA, __shfl_xor_sync(~0u, tmA, 1));
            tmA = fmaxf(tmA, __shfl_xor_sync(~0u, tmA, 2));
            tmB = fmaxf(tmB, __shfl_xor_sync(~0u, tmB, 1));
            tmB = fmaxf(tmB, __shfl_xor_sync(~0u, tmB, 2));

            float mAn = fmaxf(mA, tmA), mBn = fmaxf(mB, tmB);
            float fA = __expf(mA - mAn), fB = __expf(mB - mBn);
            mA = mAn; mB = mBn;

            __half* Ph = (__half*)((char*)s3 + 5 * ATILE_B);
            float sA = 0.f, sB = 0.f;
            #pragma unroll
            for (int f = 0; f < 8; f++) {
                float p0 = __expf(sf[f][0] - mA);
                float p1 = __expf(sf[f][1] - mA);
                float p2 = __expf(sf[f][2] - mB);
                float p3 = __expf(sf[f][3] - mB);
                sA += p0 + p1; sB += p2 + p3;
                *(__half2*)&Ph[(wr0 + g    )*72 + f*8 + 2*qc] = __floats2half2_rn(p0, p1);
                *(__half2*)&Ph[(wr0 + g + 8)*72 + f*8 + 2*qc] = __floats2half2_rn(p2, p3);
            }
            sA += __shfl_xor_sync(~0u, sA, 1); sA += __shfl_xor_sync(~0u, sA, 2);
            sB += __shfl_xor_sync(~0u, sB, 1); sB += __shfl_xor_sync(~0u, sB, 2);
            lA = lA * fA + sA;
            lB = lB * fB + sB;

            #pragma unroll
            for (int f = 0; f < 8; f++) {
                acc[f][0] *= fA; acc[f][1] *= fA; acc[f][2] *= fB; acc[f][3] *= fB;
            }
            __syncwarp();

            uint32_t pf[4][4];
            #pragma unroll
            for (int kk = 0; kk < 4; kk++)
                ldsm_x4(pf[kk], PBUF + wr0 * AROWB + a_off + kk * 32);

            #pragma unroll
            for (int kk = 0; kk < 4; kk++) {
                #pragma unroll
                for (int f2 = 0; f2 < 4; f2++) {
                    uint32_t r[4];
                    ldsm_x4(r, Vb + f2 * 16 * AROWB + b_off + kk * 32);
                    uint32_t b0[2] = {r[0], r[1]}, b1[2] = {r[2], r[3]};
                    mma_f16(acc[2*f2],     pf[kk], b0);
                    mma_f16(acc[2*f2 + 1], pf[kk], b1);
                }
            }

            if (it == nMem - 1) {
                #pragma unroll
                for (int f = 0; f < 8; f++) {
                    acc[f][0] *= gA; acc[f][1] *= gA;
                    acc[f][2] *= gB; acc[f][3] *= gB;
                }
            }
        }
        #undef FILL_KV
        #undef S0OF

        float invA = 1.f / lA, invB = 1.f / lB;
        #pragma unroll
        for (int f = 0; f < 8; f++) {
            int col = h*HD_ + f*8 + 2*qc;
            __half2 o0 = __floats2half2_rn(acc[f][0] * invA, acc[f][1] * invA);
            __half2 o1 = __floats2half2_rn(acc[f][2] * invB, acc[f][3] * invB);
            *(__half2*)&outp[(size_t)(b*T_ + rA) * C_ + col] = o0;
            *(__half2*)&outp[(size_t)(b*T_ + rB) * C_ + col] = o1;
        }
    }
    #undef KBUF
    #undef VBUF
    #undef QBUF
    #undef PBUF
}

// ---------------- canon conv (fp16 in, fp16 out) ----------------------------
__global__ __launch_bounds__(256)
void conv_kernel(const __half* __restrict__ y, const float* __restrict__ cw,
                 const float4* __restrict__ cb4, uint2* __restrict__ z) {
    const int C4 = C_/4;
    int idx = blockIdx.x * 256 + threadIdx.x;
    if (idx >= B_*T_*C4) return;
    int c4 = idx & (C4 - 1);
    int t  = (idx / C4) % T_;
    int b  = idx / (C4 * T_);

    const float4* cwr = (const float4*)cw;
    float4 w0 = cwr[c4*4 + 0];
    float4 w1 = cwr[c4*4 + 1];
    float4 w2 = cwr[c4*4 + 2];
    float4 w3 = cwr[c4*4 + 3];
    float wa[4][4] = {{w0.x,w0.y,w0.z,w0.w}, {w1.x,w1.y,w1.z,w1.w},
                      {w2.x,w2.y,w2.z,w2.w}, {w3.x,w3.y,w3.z,w3.w}};

    const uint2* y2 = (const uint2*)y;
    uint2 yc = y2[idx];
    float2 a01 = __half22float2(*reinterpret_cast<__half2*>(&yc.x));
    float2 a23 = __half22float2(*reinterpret_cast<__half2*>(&yc.y));
    float4 cbv = cb4[c4];
    float ax = a01.x + cbv.x, ay = a01.y + cbv.y;
    float az = a23.x + cbv.z, aw = a23.y + cbv.w;

    #pragma unroll
    for (int j = 0; j < KC_; j++) {
        int tt = t - (KC_ - 1) + j;
        if (tt >= 0) {
            uint2 yv = y2[((size_t)(b*T_ + tt)) * C4 + c4];
            float2 f01 = __half22float2(*reinterpret_cast<__half2*>(&yv.x));
            float2 f23 = __half22float2(*reinterpret_cast<__half2*>(&yv.y));
            ax += f01.x * wa[0][j];
            ay += f01.y * wa[1][j];
            az += f23.x * wa[2][j];
            aw += f23.y * wa[3][j];
        }
    }
    z[idx] = make_uint2(h2u(__floats2half2_rn(ax, ay)),
                        h2u(__floats2half2_rn(az, aw)));
}

// ---------------- orchestration -------------------------------------------
extern "C" void kernel_launch(void* const* d_in, const int* in_sizes, int n_in,
                              void* d_out, int out_size) {
    const float* x   = (const float*)d_in[0];
    const float* fwd = (const float*)d_in[1];
    const float* rev = (const float*)d_in[2];
    const float* Wq  = (const float*)d_in[3];
    const float* Wk  = (const float*)d_in[4];
    const float* Wv  = (const float*)d_in[5];
    const float* Wo  = (const float*)d_in[6];
    const float* gw  = (const float*)d_in[7];
    const float* gb  = (const float*)d_in[8];
    const float* cw  = (const float*)d_in[9];
    const float* cb  = (const float*)d_in[10];
    float* out = (float*)d_out;

    __half *xc, *wtf, *z16, *qb, *kb, *vt, *at;
    float *gt;
    cudaGetSymbolAddress((void**)&xc,  g_xcat);
    cudaGetSymbolAddress((void**)&wtf, g_wtf);
    cudaGetSymbolAddress((void**)&z16, g_z16);
    cudaGetSymbolAddress((void**)&qb,  g_q16);
    cudaGetSymbolAddress((void**)&kb,  g_k16);
    cudaGetSymbolAddress((void**)&vt,  g_vt16);
    cudaGetSymbolAddress((void**)&gt,  g_gate);
    cudaGetSymbolAddress((void**)&at,  g_attn16);

    cudaFuncSetAttribute(gemm_f16,
                         cudaFuncAttributeMaxDynamicSharedMemorySize, GEMM_SMEM);
    cudaFuncSetAttribute(attn_f16,
                         cudaFuncAttributeMaxDynamicSharedMemorySize, ATT_SMEM);
    cudaFuncSetAttribute(gate_kernel,
                         cudaFuncAttributeMaxDynamicSharedMemorySize, GATE_SMEM);

    // 1. fused pre-convert (xcat pack + weights + queue reset)
    {
        int ntot = B_*S_*(C_/4) + 4*C_*C_/4;
        prep_kernel<<<(ntot + 255)/256, 256>>>(
            (const float4*)x, (const float4*)fwd, (const float4*)rev,
            (const float4*)Wq, (const float4*)Wk, (const float4*)Wv,
            (const float4*)Wo, (uint2*)xc, (uint2*)wtf);
    }

    // 2. fused QKV projection (fp16 tensor cores; v transposed via smem)
    gemm_f16<<<dim3(3*C_/128, (B_*S_)/128), 256, GEMM_SMEM>>>(
        xc, wtf, nullptr, qb, kb, vt, 3*C_, C_, 1);

    // 3. gate
    gate_kernel<<<(B_*T_)/GR, 256, GATE_SMEM>>>(qb, gw, gb, gt);
    // 4. attention (persistent, 3 CTA/SM x 148 SMs)
    attn_f16<<<148*3, 128, ATT_SMEM>>>(qb, kb, vt, gt, at);
    // 5. canon conv (fp16 in/out)
    conv_kernel<<<(B_*T_*(C_/4) + 255)/256, 256>>>(at, cw,
                                                   (const float4*)cb, (uint2*)z16);
    // 6. output projection into d_out (fp32 out)
    gemm_f16<<<dim3(C_/128, (B_*T_)/128), 256, GEMM_SMEM>>>(
        z16, wtf + 3*C_*C_, out, nullptr, nullptr, nullptr, C_, C_, 0);
}

// round 17
// speedup vs baseline: 2.4737x; 1.0323x over previous
#include <cuda_runtime.h>
#include <cuda_fp16.h>
#include <math.h>
#include <stdint.h>

#define B_ 2
#define T_ 2048
#define C_ 1024
#define H_ 16
#define HD_ 64
#define M_ 256
#define S_ (T_ + 2*M_)   /* 2560 */
#define KC_ 4

// ---------------- scratch (static device globals; no runtime alloc) -------
__device__ __half g_xcat[B_*S_*C_];   // concat(x,fwd,rev) fp16
__device__ __half g_wtf [4*C_*C_];    // Wq|Wk|Wv|Wo fp16
__device__ __half g_q16 [B_*T_*C_];   // q fp16
__device__ __half g_k16 [B_*S_*C_];   // k fp16
__device__ __half g_vt16[B_*C_*S_];   // V^T fp16: [b][c][s]
__device__ float  g_gate[B_*T_*H_];
__device__ __half g_attn16[B_*T_*C_]; // attention output fp16
__device__ __half g_z16 [B_*T_*C_];   // conv output fp16
__device__ int    g_work;             // persistent-attention work counter

#define NITEMS ((T_/64) * B_ * H_)    // 1024 work items

// ================= helpers =================================================
__device__ __forceinline__ uint32_t h2u(__half2 h) {
    return *reinterpret_cast<uint32_t*>(&h);
}
__device__ __forceinline__ void mma_f16(float* d, const uint32_t* a,
                                        const uint32_t* b) {
    asm volatile(
        "mma.sync.aligned.m16n8k16.row.col.f32.f16.f16.f32 "
        "{%0,%1,%2,%3}, {%4,%5,%6,%7}, {%8,%9}, {%0,%1,%2,%3};"
        : "+f"(d[0]), "+f"(d[1]), "+f"(d[2]), "+f"(d[3])
        : "r"(a[0]), "r"(a[1]), "r"(a[2]), "r"(a[3]),
          "r"(b[0]), "r"(b[1]));
}
__device__ __forceinline__ void ldsm_x4(uint32_t* r, uint32_t addr) {
    asm volatile("ldmatrix.sync.aligned.m8n8.x4.shared.b16 {%0,%1,%2,%3}, [%4];"
        : "=r"(r[0]), "=r"(r[1]), "=r"(r[2]), "=r"(r[3]) : "r"(addr));
}
__device__ __forceinline__ void cp16(uint32_t dst, const void* src) {
    asm volatile("cp.async.cg.shared.global [%0], [%1], 16;" :: "r"(dst), "l"(src));
}

// ---------------- prep: pack xcat + convert weights + reset queue ----------
__global__ void prep_kernel(const float4* __restrict__ x,
                            const float4* __restrict__ fwd,
                            const float4* __restrict__ rev,
                            const float4* __restrict__ w0, const float4* __restrict__ w1,
                            const float4* __restrict__ w2, const float4* __restrict__ w3,
                            uint2* __restrict__ xc, uint2* __restrict__ wdst) {
    if (blockIdx.x == 0 && threadIdx.x == 0) g_work = 0;
    const int C4 = C_/4;
    const int NX = B_*S_*C4;
    const int NW = C_*C_/4;
    int idx = blockIdx.x * 256 + threadIdx.x;
    if (idx < NX) {
        int c4 = idx % C4;
        int r  = (idx / C4) % S_;
        int b  = idx / (C4 * S_);
        float4 val;
        if (r < T_)            val = x  [(b*T_ + r)          * C4 + c4];
        else if (r < T_ + M_)  val = fwd[(b*M_ + (r - T_))   * C4 + c4];
        else                   val = rev[(b*M_ + (r - T_-M_))* C4 + c4];
        xc[idx] = make_uint2(h2u(__floats2half2_rn(val.x, val.y)),
                             h2u(__floats2half2_rn(val.z, val.w)));
    } else {
        int widx = idx - NX;
        if (widx >= 4*NW) return;
        int m = widx / NW, r = widx % NW;
        const float4* s = (m == 0) ? w0 : (m == 1) ? w1 : (m == 2) ? w2 : w3;
        float4 v = s[r];
        wdst[widx] = make_uint2(h2u(__floats2half2_rn(v.x, v.y)),
                                h2u(__floats2half2_rn(v.z, v.w)));
    }
}

// ================= FP16 GEMM: BK=64, cp.async 3-stage + ldmatrix ===========
#define GBK 64
#define GROWB 144
#define GOPB (128 * GROWB)
#define GSTAGEB (2 * GOPB)
#define GEMM_SMEM (3 * GSTAGEB)          // 110592 B -> 2 CTA/SM

__global__ __launch_bounds__(256)
void gemm_f16(const __half* __restrict__ A, const __half* __restrict__ Bm,
              float* __restrict__ Cm, __half* __restrict__ qp,
              __half* __restrict__ kp, __half* __restrict__ vp,
              int Nr, int Kr, int mode) {
    if (mode == 1 && blockIdx.x < 8 && (blockIdx.y % 20) >= 16) return;

    extern __shared__ uint32_t smg[];
    const uint32_t sbase = (uint32_t)__cvta_generic_to_shared(smg);

    const int tid  = threadIdx.x;
    const int lane = tid & 31, warp = tid >> 5;
    const int g = lane >> 2, qc = lane & 3;
    const int wm0 = (warp >> 2) * 64;
    const int wn0 = (warp & 3) * 32;
    const int m0 = blockIdx.y * 128, n0 = blockIdx.x * 128;
    const int nk = Kr / GBK;

    const int a_off = (lane & 15) * GROWB + (lane >> 4) * 16;
    const int b_off = (((lane >> 4) & 1) * 8 + (lane & 7)) * GROWB
                      + ((lane >> 3) & 1) * 16;

    float acc[4][4][4] = {};

    #define PREFETCH(KT)                                                       \
    do {                                                                       \
        int kt_ = (KT);                                                        \
        if (kt_ < nk) {                                                        \
            uint32_t da = sbase + (kt_ % 3) * GSTAGEB;                         \
            uint32_t db = da + GOPB;                                           \
            const __half* Ag_ = A  + (size_t)m0 * Kr + kt_ * GBK;              \
            const __half* Bg_ = Bm + (size_t)n0 * Kr + kt_ * GBK;              \
            _Pragma("unroll")                                                  \
            for (int j = 0; j < 4; j++) {                                      \
                int u = tid + j * 256;                                         \
                int row = u >> 3, q16 = u & 7;                                 \
                cp16(da + row * GROWB + q16 * 16, Ag_ + (size_t)row * Kr + q16 * 8); \
                cp16(db + row * GROWB + q16 * 16, Bg_ + (size_t)row * Kr + q16 * 8); \
            }                                                                  \
        }                                                                      \
        asm volatile("cp.async.commit_group;");                                \
    } while (0)

    PREFETCH(0);
    PREFETCH(1);

    for (int kt = 0; kt < nk; kt++) {
        asm volatile("cp.async.wait_group 1;");
        __syncthreads();
        PREFETCH(kt + 2);

        const uint32_t aAddr = sbase + (kt % 3) * GSTAGEB + wm0 * GROWB + a_off;
        const uint32_t bAddr = sbase + (kt % 3) * GSTAGEB + GOPB + wn0 * GROWB + b_off;

        #pragma unroll
        for (int kp_ = 0; kp_ < 4; kp_++) {
            uint32_t bf[4][2];
            {
                uint32_t r[4];
                ldsm_x4(r, bAddr + kp_ * 32);
                bf[0][0] = r[0]; bf[0][1] = r[1]; bf[1][0] = r[2]; bf[1][1] = r[3];
            }
            {
                uint32_t r[4];
                ldsm_x4(r, bAddr + 16 * GROWB + kp_ * 32);
                bf[2][0] = r[0]; bf[2][1] = r[1]; bf[3][0] = r[2]; bf[3][1] = r[3];
            }
            uint32_t af[4][4];
            #pragma unroll
            for (int mt = 0; mt < 4; mt++)
                ldsm_x4(af[mt], aAddr + mt * 16 * GROWB + kp_ * 32);
            #pragma unroll
            for (int mt = 0; mt < 4; mt++)
                #pragma unroll
                for (int nt = 0; nt < 4; nt++)
                    mma_f16(acc[mt][nt], af[mt], bf[nt]);
        }
    }
    #undef PREFETCH

    if (mode == 0) {
        #pragma unroll
        for (int mt = 0; mt < 4; mt++) {
            #pragma unroll
            for (int nt = 0; nt < 4; nt++) {
                int row = m0 + wm0 + mt*16 + g;
                int col = n0 + wn0 + nt*8 + qc*2;
                float2 lo = make_float2(acc[mt][nt][0], acc[mt][nt][1]);
                float2 hi = make_float2(acc[mt][nt][2], acc[mt][nt][3]);
                *(float2*)(Cm + (size_t)row     * Nr + col) = lo;
                *(float2*)(Cm + (size_t)(row+8) * Nr + col) = hi;
            }
        }
    } else if (blockIdx.x < 16) {
        #pragma unroll
        for (int mt = 0; mt < 4; mt++) {
            #pragma unroll
            for (int nt = 0; nt < 4; nt++) {
                int row = m0 + wm0 + mt*16 + g;
                int col = n0 + wn0 + nt*8 + qc*2;
                int which = col >> 10, lc = col & 1023;
                int bb = row / S_, rr = row % S_;
                __half2 lo = __floats2half2_rn(acc[mt][nt][0], acc[mt][nt][1]);
                __half2 hi = __floats2half2_rn(acc[mt][nt][2], acc[mt][nt][3]);
                if (which == 0) {
                    if (rr < T_) {
                        __half* dst = qp + ((size_t)(bb*T_ + rr)) * C_ + lc;
                        *(__half2*)(dst)        = lo;
                        *(__half2*)(dst + 8*C_) = hi;
                    }
                } else {
                    __half* dst = kp + (size_t)row * C_ + lc;
                    *(__half2*)(dst)        = lo;
                    *(__half2*)(dst + 8*C_) = hi;
                }
            }
        }
    } else {
        // V columns: transpose tile via smem, then coalesced rows into vt.
        asm volatile("cp.async.wait_group 0;");
        __syncthreads();
        __half* tsm = (__half*)smg;            // [128 cols][136 pad] halves
        #pragma unroll
        for (int mt = 0; mt < 4; mt++) {
            #pragma unroll
            for (int nt = 0; nt < 4; nt++) {
                int cl = wn0 + nt*8 + qc*2;
                int rl = wm0 + mt*16 + g;
                __half2 lo = __floats2half2_rn(acc[mt][nt][0], acc[mt][nt][1]);
                __half2 hi = __floats2half2_rn(acc[mt][nt][2], acc[mt][nt][3]);
                tsm[(cl    ) * 136 + rl    ] = __low2half(lo);
                tsm[(cl + 1) * 136 + rl    ] = __high2half(lo);
                tsm[(cl    ) * 136 + rl + 8] = __low2half(hi);
                tsm[(cl + 1) * 136 + rl + 8] = __high2half(hi);
            }
        }
        __syncthreads();
        const int bb  = m0 / S_;
        const int rr0 = m0 % S_;
        const int lc0 = n0 & 1023;
        const int vtrow = tid & 127, seg = tid >> 7;
        __half* dst = vp + ((size_t)(bb*C_ + lc0 + vtrow)) * S_ + rr0 + seg*64;
        const __half* src = tsm + vtrow * 136 + seg * 64;
        #pragma unroll
        for (int i = 0; i < 8; i++)
            *(uint4*)(dst + i*8) = *(const uint4*)(src + i*8);
    }
}

// ---------------- gate: GR=8 (512 CTAs), reads fp16 q ----------------------
#define GR 8
#define GATE_SMEM (GR * 256 * (int)sizeof(uint2))   // 16 KB

__global__ __launch_bounds__(256)
void gate_kernel(const __half* __restrict__ q, const float* __restrict__ gw,
                 const float* __restrict__ gb, float* __restrict__ gate) {
    extern __shared__ uint2 qs2[];
    const int bt0 = blockIdx.x * GR;
    const int tid = threadIdx.x;
    const int warp = tid >> 5, lane = tid & 31;

    const uint2* qsrc = (const uint2*)(q + (size_t)bt0 * C_);
    #pragma unroll
    for (int i = 0; i < GR; i++)
        qs2[i * 256 + tid] = qsrc[i * 256 + tid];
    __syncthreads();

    const int h0 = warp * 2, h1 = h0 + 1;
    const float4* g0p = (const float4*)(gw + h0 * C_);
    const float4* g1p = (const float4*)(gw + h1 * C_);

    float s0[GR] = {}, s1[GR] = {};
    #pragma unroll
    for (int i = 0; i < 8; i++) {
        float4 g0 = g0p[lane + i*32];
        float4 g1 = g1p[lane + i*32];
        #pragma unroll
        for (int r = 0; r < GR; r++) {
            uint2 qv = qs2[r * 256 + lane + i*32];
            float2 f01 = __half22float2(*reinterpret_cast<__half2*>(&qv.x));
            float2 f23 = __half22float2(*reinterpret_cast<__half2*>(&qv.y));
            s0[r] += f01.x*g0.x + f01.y*g0.y + f23.x*g0.z + f23.y*g0.w;
            s1[r] += f01.x*g1.x + f01.y*g1.y + f23.x*g1.z + f23.y*g1.w;
        }
    }
    float b0 = gb[h0], b1 = gb[h1];
    #pragma unroll
    for (int r = 0; r < GR; r++) {
        float v0 = s0[r], v1 = s1[r];
        #pragma unroll
        for (int o = 16; o; o >>= 1) {
            v0 += __shfl_xor_sync(~0u, v0, o);
            v1 += __shfl_xor_sync(~0u, v1, o);
        }
        if (lane == 0) {
            gate[(size_t)(bt0 + r) * H_ + h0] = 1.f / (1.f + __expf(-(v0 + b0)));
            gate[(size_t)(bt0 + r) * H_ + h1] = 1.f / (1.f + __expf(-(v1 + b1)));
        }
    }
}

// ================= fp16 attention: persistent, P stays in registers ========
// Accumulator layout == A-fragment layout (half2-packed), so P fragments are
// packed directly from sf — no smem roundtrip, no syncwarp, no ldsm for P.
// Buffers: K0|K1|V0|V1|Q (5 tiles, 46080 B).
#define AROWB 144
#define ATILE_B (64 * AROWB)
#define ATT_SMEM (5 * ATILE_B)           // 46080 B

__global__ __launch_bounds__(128, 3)
void attn_f16(const __half* __restrict__ q, const __half* __restrict__ k,
              const __half* __restrict__ vT, const float* __restrict__ gate,
              __half* __restrict__ outp) {
    extern __shared__ uint32_t s3[];
    __shared__ int s_item;
    const uint32_t sbase = (uint32_t)__cvta_generic_to_shared(s3);

    const int tid  = threadIdx.x;
    const int lane = tid & 31, warp = tid >> 5;
    const int g = lane >> 2, qc = lane & 3;
    const int wr0 = warp * 16;

    const int a_off = (lane & 15) * AROWB + (lane >> 4) * 16;
    const int b_off = (((lane >> 4) & 1) * 8 + (lane & 7)) * AROWB
                      + ((lane >> 3) & 1) * 16;
    const int nMem = (2*M_)/64;

    #define KBUF(IT) (sbase + (((IT) & 1)     ) * ATILE_B)
    #define VBUF(IT) (sbase + (2 + ((IT) & 1) ) * ATILE_B)
    #define QBUF     (sbase + 4 * ATILE_B)

    for (;;) {
        if (tid == 0) s_item = atomicAdd(&g_work, 1);
        __syncthreads();
        const int w = s_item;
        if (w >= NITEMS) return;

        const int xi = w >> 5;
        const int yi = w & 31;
        const int t0 = (31 - xi) * 64;
        const int b  = yi >> 4;
        const int h  = yi & 15;

        const int nChunk = t0/64 + 1;
        const int nTiles = nMem + nChunk;
        #define S0OF(IT) (((IT) < nMem) ? (T_ + (IT)*64) : ((IT) - nMem)*64)

        {
            const __half* src_ = q + ((size_t)(b*T_ + t0)) * C_ + h*HD_;
            #pragma unroll
            for (int j = 0; j < 4; j++) {
                int u = tid + j * 128;
                int row = u >> 3, cw = u & 7;
                cp16(QBUF + row * AROWB + cw * 16, src_ + (size_t)row * C_ + cw * 8);
            }
            asm volatile("cp.async.commit_group;");
        }

        #define FILL_KV(IT)                                                       \
        do {                                                                      \
            int it_ = (IT);                                                       \
            if (it_ < nTiles) {                                                   \
                int s0_ = S0OF(it_);                                              \
                uint32_t kb_ = KBUF(it_);                                         \
                uint32_t vb_ = VBUF(it_);                                         \
                const __half* ks_ = k  + ((size_t)(b*S_ + s0_)) * C_ + h*HD_;     \
                const __half* vs_ = vT + ((size_t)(b*C_ + h*HD_)) * S_ + s0_;     \
                _Pragma("unroll")                                                 \
                for (int j = 0; j < 4; j++) {                                     \
                    int u = tid + j * 128;                                        \
                    int row = u >> 3, cw = u & 7;                                 \
                    cp16(kb_ + row * AROWB + cw * 16, ks_ + (size_t)row * C_ + cw * 8); \
                    cp16(vb_ + row * AROWB + cw * 16, vs_ + (size_t)row * S_ + cw * 8); \
                }                                                                 \
            }                                                                     \
            asm volatile("cp.async.commit_group;");                               \
        } while (0)

        FILL_KV(0);
        asm volatile("cp.async.wait_group 1;");
        __syncthreads();

        uint32_t qf[4][4];
        const __half2 sc8 = __half2half2(__float2half(0.125f));
        #pragma unroll
        for (int kk = 0; kk < 4; kk++) {
            ldsm_x4(qf[kk], QBUF + wr0 * AROWB + a_off + kk * 32);
            #pragma unroll
            for (int e = 0; e < 4; e++) {
                __half2 hm = __hmul2(*reinterpret_cast<__half2*>(&qf[kk][e]), sc8);
                qf[kk][e] = h2u(hm);
            }
        }

        const int rA = t0 + wr0 + g, rB = rA + 8;
        const float gA = gate[(size_t)(b*T_ + rA) * H_ + h];
        const float gB = gate[(size_t)(b*T_ + rB) * H_ + h];

        float acc[8][4] = {};
        float mA = -1e30f, mB = -1e30f, lA = 0.f, lB = 0.f;

        for (int it = 0; it < nTiles; it++) {
            const int  s0     = S0OF(it);
            const bool isDiag = (it == nTiles - 1);
            const uint32_t Kb = KBUF(it);
            const uint32_t Vb = VBUF(it);

            asm volatile("cp.async.wait_group 0;");
            __syncthreads();
            FILL_KV(it + 1);

            // ---- S = Q K^T ----
            float sf[8][4] = {};
            #pragma unroll
            for (int kk = 0; kk < 4; kk++) {
                #pragma unroll
                for (int f2 = 0; f2 < 4; f2++) {
                    uint32_t r[4];
                    ldsm_x4(r, Kb + f2 * 16 * AROWB + b_off + kk * 32);
                    uint32_t b0[2] = {r[0], r[1]}, b1[2] = {r[2], r[3]};
                    mma_f16(sf[2*f2],     qf[kk], b0);
                    mma_f16(sf[2*f2 + 1], qf[kk], b1);
                }
            }

            // ---- mask + row max ----
            float tmA = -1e30f, tmB = -1e30f;
            #pragma unroll
            for (int f = 0; f < 8; f++) {
                if (isDiag) {
                    int c0 = s0 + f*8 + 2*qc, c1 = c0 + 1;
                    if (c0 > rA) sf[f][0] = -1e30f;
                    if (c1 > rA) sf[f][1] = -1e30f;
                    if (c0 > rB) sf[f][2] = -1e30f;
                    if (c1 > rB) sf[f][3] = -1e30f;
                }
                tmA = fmaxf(tmA, fmaxf(sf[f][0], sf[f][1]));
                tmB = fmaxf(tmB, fmaxf(sf[f][2], sf[f][3]));
            }
            tmA = fmaxf(tmA, __shfl_xor_sync(~0u, tmA, 1));
            tmA = fmaxf(tmA, __shfl_xor_sync(~0u, tmA, 2));
            tmB = fmaxf(tmB, __shfl_xor_sync(~0u, tmB, 1));
            tmB = fmaxf(tmB, __shfl_xor_sync(~0u, tmB, 2));

            float mAn = fmaxf(mA, tmA), mBn = fmaxf(mB, tmB);
            float fA = __expf(mA - mAn), fB = __expf(mB - mBn);
            mA = mAn; mB = mBn;

            // ---- P = exp(S-m): pack A-fragments directly in registers ----
            uint32_t pf[4][4];
            float sA = 0.f, sB = 0.f;
            #pragma unroll
            for (int kk = 0; kk < 4; kk++) {
                float p00 = __expf(sf[2*kk  ][0] - mA);
                float p01 = __expf(sf[2*kk  ][1] - mA);
                float p02 = __expf(sf[2*kk  ][2] - mB);
                float p03 = __expf(sf[2*kk  ][3] - mB);
                float p10 = __expf(sf[2*kk+1][0] - mA);
                float p11 = __expf(sf[2*kk+1][1] - mA);
                float p12 = __expf(sf[2*kk+1][2] - mB);
                float p13 = __expf(sf[2*kk+1][3] - mB);
                sA += p00 + p01 + p10 + p11;
                sB += p02 + p03 + p12 + p13;
                pf[kk][0] = h2u(__floats2half2_rn(p00, p01));
                pf[kk][1] = h2u(__floats2half2_rn(p02, p03));
                pf[kk][2] = h2u(__floats2half2_rn(p10, p11));
                pf[kk][3] = h2u(__floats2half2_rn(p12, p13));
            }
            sA += __shfl_xor_sync(~0u, sA, 1); sA += __shfl_xor_sync(~0u, sA, 2);
            sB += __shfl_xor_sync(~0u, sB, 1); sB += __shfl_xor_sync(~0u, sB, 2);
            lA = lA * fA + sA;
            lB = lB * fB + sB;

            // ---- rescale accumulator ----
            #pragma unroll
            for (int f = 0; f < 8; f++) {
                acc[f][0] *= fA; acc[f][1] *= fA; acc[f][2] *= fB; acc[f][3] *= fB;
            }

            // ---- O += P V ----
            #pragma unroll
            for (int kk = 0; kk < 4; kk++) {
                #pragma unroll
                for (int f2 = 0; f2 < 4; f2++) {
                    uint32_t r[4];
                    ldsm_x4(r, Vb + f2 * 16 * AROWB + b_off + kk * 32);
                    uint32_t b0[2] = {r[0], r[1]}, b1[2] = {r[2], r[3]};
                    mma_f16(acc[2*f2],     pf[kk], b0);
                    mma_f16(acc[2*f2 + 1], pf[kk], b1);
                }
            }

            if (it == nMem - 1) {
                #pragma unroll
                for (int f = 0; f < 8; f++) {
                    acc[f][0] *= gA; acc[f][1] *= gA;
                    acc[f][2] *= gB; acc[f][3] *= gB;
                }
            }
        }
        #undef FILL_KV
        #undef S0OF

        float invA = 1.f / lA, invB = 1.f / lB;
        #pragma unroll
        for (int f = 0; f < 8; f++) {
            int col = h*HD_ + f*8 + 2*qc;
            __half2 o0 = __floats2half2_rn(acc[f][0] * invA, acc[f][1] * invA);
            __half2 o1 = __floats2half2_rn(acc[f][2] * invB, acc[f][3] * invB);
            *(__half2*)&outp[(size_t)(b*T_ + rA) * C_ + col] = o0;
            *(__half2*)&outp[(size_t)(b*T_ + rB) * C_ + col] = o1;
        }
    }
    #undef KBUF
    #undef VBUF
    #undef QBUF
}

// ---------------- canon conv (fp16 in, fp16 out) ----------------------------
__global__ __launch_bounds__(256)
void conv_kernel(const __half* __restrict__ y, const float* __restrict__ cw,
                 const float4* __restrict__ cb4, uint2* __restrict__ z) {
    const int C4 = C_/4;
    int idx = blockIdx.x * 256 + threadIdx.x;
    if (idx >= B_*T_*C4) return;
    int c4 = idx & (C4 - 1);
    int t  = (idx / C4) % T_;
    int b  = idx / (C4 * T_);

    const float4* cwr = (const float4*)cw;
    float4 w0 = cwr[c4*4 + 0];
    float4 w1 = cwr[c4*4 + 1];
    float4 w2 = cwr[c4*4 + 2];
    float4 w3 = cwr[c4*4 + 3];
    float wa[4][4] = {{w0.x,w0.y,w0.z,w0.w}, {w1.x,w1.y,w1.z,w1.w},
                      {w2.x,w2.y,w2.z,w2.w}, {w3.x,w3.y,w3.z,w3.w}};

    const uint2* y2 = (const uint2*)y;
    uint2 yc = y2[idx];
    float2 a01 = __half22float2(*reinterpret_cast<__half2*>(&yc.x));
    float2 a23 = __half22float2(*reinterpret_cast<__half2*>(&yc.y));
    float4 cbv = cb4[c4];
    float ax = a01.x + cbv.x, ay = a01.y + cbv.y;
    float az = a23.x + cbv.z, aw = a23.y + cbv.w;

    #pragma unroll
    for (int j = 0; j < KC_; j++) {
        int tt = t - (KC_ - 1) + j;
        if (tt >= 0) {
            uint2 yv = y2[((size_t)(b*T_ + tt)) * C4 + c4];
            float2 f01 = __half22float2(*reinterpret_cast<__half2*>(&yv.x));
            float2 f23 = __half22float2(*reinterpret_cast<__half2*>(&yv.y));
            ax += f01.x * wa[0][j];
            ay += f01.y * wa[1][j];
            az += f23.x * wa[2][j];
            aw += f23.y * wa[3][j];
        }
    }
    z[idx] = make_uint2(h2u(__floats2half2_rn(ax, ay)),
                        h2u(__floats2half2_rn(az, aw)));
}

// ---------------- orchestration -------------------------------------------
extern "C" void kernel_launch(void* const* d_in, const int* in_sizes, int n_in,
                              void* d_out, int out_size) {
    const float* x   = (const float*)d_in[0];
    const float* fwd = (const float*)d_in[1];
    const float* rev = (const float*)d_in[2];
    const float* Wq  = (const float*)d_in[3];
    const float* Wk  = (const float*)d_in[4];
    const float* Wv  = (const float*)d_in[5];
    const float* Wo  = (const float*)d_in[6];
    const float* gw  = (const float*)d_in[7];
    const float* gb  = (const float*)d_in[8];
    const float* cw  = (const float*)d_in[9];
    const float* cb  = (const float*)d_in[10];
    float* out = (float*)d_out;

    __half *xc, *wtf, *z16, *qb, *kb, *vt, *at;
    float *gt;
    cudaGetSymbolAddress((void**)&xc,  g_xcat);
    cudaGetSymbolAddress((void**)&wtf, g_wtf);
    cudaGetSymbolAddress((void**)&z16, g_z16);
    cudaGetSymbolAddress((void**)&qb,  g_q16);
    cudaGetSymbolAddress((void**)&kb,  g_k16);
    cudaGetSymbolAddress((void**)&vt,  g_vt16);
    cudaGetSymbolAddress((void**)&gt,  g_gate);
    cudaGetSymbolAddress((void**)&at,  g_attn16);

    cudaFuncSetAttribute(gemm_f16,
                         cudaFuncAttributeMaxDynamicSharedMemorySize, GEMM_SMEM);
    cudaFuncSetAttribute(attn_f16,
                         cudaFuncAttributeMaxDynamicSharedMemorySize, ATT_SMEM);
    cudaFuncSetAttribute(gate_kernel,
                         cudaFuncAttributeMaxDynamicSharedMemorySize, GATE_SMEM);

    // 1. fused pre-convert (xcat pack + weights + queue reset)
    {
        int ntot = B_*S_*(C_/4) + 4*C_*C_/4;
        prep_kernel<<<(ntot + 255)/256, 256>>>(
            (const float4*)x, (const float4*)fwd, (const float4*)rev,
            (const float4*)Wq, (const float4*)Wk, (const float4*)Wv,
            (const float4*)Wo, (uint2*)xc, (uint2*)wtf);
    }

    // 2. fused QKV projection (fp16 tensor cores; v transposed via smem)
    gemm_f16<<<dim3(3*C_/128, (B_*S_)/128), 256, GEMM_SMEM>>>(
        xc, wtf, nullptr, qb, kb, vt, 3*C_, C_, 1);

    // 3. gate
    gate_kernel<<<(B_*T_)/GR, 256, GATE_SMEM>>>(qb, gw, gb, gt);
    // 4. attention (persistent, P in registers)
    attn_f16<<<148*3, 128, ATT_SMEM>>>(qb, kb, vt, gt, at);
    // 5. canon conv (fp16 in/out)
    conv_kernel<<<(B_*T_*(C_/4) + 255)/256, 256>>>(at, cw,
                                                   (const float4*)cb, (uint2*)z16);
    // 6. output projection into d_out (fp32 out)
    gemm_f16<<<dim3(C_/128, (B_*T_)/128), 256, GEMM_SMEM>>>(
        z16, wtf + 3*C_*C_, out, nullptr, nullptr, nullptr, C_, C_, 0);
}